// round 4
// baseline (speedup 1.0000x reference)
#include <cuda_runtime.h>
#include <cuda_bf16.h>
#include <cstdint>

// Problem constants
#define S    2048
#define Dm   2048
#define FF   8192
#define NH   32
#define HD   64
#define L    4096   // 2*S

typedef __nv_bfloat16 bf16;

// ===================== helpers =====================
__device__ __forceinline__ uint32_t smem_u32(const void* p) {
    uint32_t a;
    asm("{ .reg .u64 t; cvta.to.shared.u64 t, %1; cvt.u32.u64 %0, t; }" : "=r"(a) : "l"(p));
    return a;
}
__device__ __forceinline__ void ldm_x4(uint32_t* r, uint32_t a) {
    asm volatile("ldmatrix.sync.aligned.m8n8.x4.shared.b16 {%0,%1,%2,%3}, [%4];"
        : "=r"(r[0]), "=r"(r[1]), "=r"(r[2]), "=r"(r[3]) : "r"(a));
}
__device__ __forceinline__ void mma_bf16(float* c, const uint32_t* a, uint32_t b0, uint32_t b1) {
    asm volatile("mma.sync.aligned.m16n8k16.row.col.f32.bf16.bf16.f32 "
        "{%0,%1,%2,%3}, {%4,%5,%6,%7}, {%8,%9}, {%0,%1,%2,%3};"
        : "+f"(c[0]), "+f"(c[1]), "+f"(c[2]), "+f"(c[3])
        : "r"(a[0]), "r"(a[1]), "r"(a[2]), "r"(a[3]), "r"(b0), "r"(b1));
}
#define CP_ASYNC16(dst, src) \
    asm volatile("cp.async.cg.shared.global [%0], [%1], 16;" :: "r"(dst), "l"(src))
#define CP_COMMIT() asm volatile("cp.async.commit_group;" ::: "memory")
#define CP_WAIT2()  asm volatile("cp.async.wait_group 2;" ::: "memory")

// ===================== scratch (device globals) =====================
__device__ bf16  g_xh [L * Dm];       // ln1 output hi
__device__ bf16  g_xl [L * Dm];       // ln1 output lo
__device__ float g_q  [S * Dm];
__device__ float g_k  [L * Dm];
__device__ float g_v  [L * Dm];
__device__ bf16  g_ah [S * Dm];       // attn out hi
__device__ bf16  g_al [S * Dm];
__device__ float g_h  [S * Dm];       // post-attn residual
__device__ bf16  g_h2h[S * Dm];
__device__ bf16  g_h2l[S * Dm];
__device__ float g_gr [S * FF];       // gate raw
__device__ float g_ur [S * FF];       // up raw
__device__ bf16  g_gh [S * FF];       // silu(gate)*up hi
__device__ bf16  g_gl [S * FF];
__device__ bf16  g_wqh[Dm * Dm]; __device__ bf16 g_wql[Dm * Dm];
__device__ bf16  g_wkh[Dm * Dm]; __device__ bf16 g_wkl[Dm * Dm];
__device__ bf16  g_wvh[Dm * Dm]; __device__ bf16 g_wvl[Dm * Dm];
__device__ bf16  g_woh[Dm * Dm]; __device__ bf16 g_wol[Dm * Dm];
__device__ bf16  g_wgh[FF * Dm]; __device__ bf16 g_wgl[FF * Dm];
__device__ bf16  g_wuh[FF * Dm]; __device__ bf16 g_wul[FF * Dm];
__device__ bf16  g_wdh[Dm * FF]; __device__ bf16 g_wdl[Dm * FF];

// ===================== bf16 hi/lo split of a tensor =====================
__global__ __launch_bounds__(256) void split_kernel(
    const float* __restrict__ X, bf16* __restrict__ H, bf16* __restrict__ Lo, int n4)
{
    int i = blockIdx.x * blockDim.x + threadIdx.x;
    if (i >= n4) return;
    float4 x = ((const float4*)X)[i];
    bf16 h0 = __float2bfloat16_rn(x.x), h1 = __float2bfloat16_rn(x.y);
    bf16 h2 = __float2bfloat16_rn(x.z), h3 = __float2bfloat16_rn(x.w);
    bf16 l0 = __float2bfloat16_rn(x.x - __bfloat162float(h0));
    bf16 l1 = __float2bfloat16_rn(x.y - __bfloat162float(h1));
    bf16 l2 = __float2bfloat16_rn(x.z - __bfloat162float(h2));
    bf16 l3 = __float2bfloat16_rn(x.w - __bfloat162float(h3));
    __nv_bfloat162 hv0 = {h0, h1}, hv1 = {h2, h3};
    __nv_bfloat162 lv0 = {l0, l1}, lv1 = {l2, l3};
    uint2 hu, lu;
    hu.x = *(uint32_t*)&hv0; hu.y = *(uint32_t*)&hv1;
    lu.x = *(uint32_t*)&lv0; lu.y = *(uint32_t*)&lv1;
    ((uint2*)H)[i]  = hu;
    ((uint2*)Lo)[i] = lu;
}

// ===================== LayerNorm with fused bf16 split =====================
__global__ __launch_bounds__(256) void ln_split_kernel(
    const float* __restrict__ X, const float* __restrict__ w,
    const float* __restrict__ b, bf16* __restrict__ OH, bf16* __restrict__ OL)
{
    int row = blockIdx.x;
    int tid = threadIdx.x;
    const float* xr = X + (size_t)row * Dm;
    float4 a = ((const float4*)xr)[tid * 2];
    float4 c = ((const float4*)xr)[tid * 2 + 1];
    float s  = a.x + a.y + a.z + a.w + c.x + c.y + c.z + c.w;
    float ss = a.x*a.x + a.y*a.y + a.z*a.z + a.w*a.w
             + c.x*c.x + c.y*c.y + c.z*c.z + c.w*c.w;
#pragma unroll
    for (int o = 16; o; o >>= 1) {
        s  += __shfl_xor_sync(0xffffffffu, s,  o);
        ss += __shfl_xor_sync(0xffffffffu, ss, o);
    }
    __shared__ float bs[8], bss[8];
    if ((tid & 31) == 0) { bs[tid >> 5] = s; bss[tid >> 5] = ss; }
    __syncthreads();
    float ts = 0.f, tss = 0.f;
#pragma unroll
    for (int i = 0; i < 8; i++) { ts += bs[i]; tss += bss[i]; }
    float mean = ts * (1.f / Dm);
    float var  = tss * (1.f / Dm) - mean * mean;
    float inv  = rsqrtf(var + 1e-5f);

    int d = tid * 8;
    float4 w0 = ((const float4*)w)[tid*2], w1 = ((const float4*)w)[tid*2+1];
    float4 b0 = ((const float4*)b)[tid*2], b1 = ((const float4*)b)[tid*2+1];
    float v8[8];
    v8[0]=(a.x-mean)*inv*w0.x+b0.x; v8[1]=(a.y-mean)*inv*w0.y+b0.y;
    v8[2]=(a.z-mean)*inv*w0.z+b0.z; v8[3]=(a.w-mean)*inv*w0.w+b0.w;
    v8[4]=(c.x-mean)*inv*w1.x+b1.x; v8[5]=(c.y-mean)*inv*w1.y+b1.y;
    v8[6]=(c.z-mean)*inv*w1.z+b1.z; v8[7]=(c.w-mean)*inv*w1.w+b1.w;
    uint16_t h8[8], l8[8];
#pragma unroll
    for (int i = 0; i < 8; i++) {
        bf16 hv = __float2bfloat16_rn(v8[i]);
        bf16 lv = __float2bfloat16_rn(v8[i] - __bfloat162float(hv));
        h8[i] = *(uint16_t*)&hv;
        l8[i] = *(uint16_t*)&lv;
    }
    *(uint4*)(OH + (size_t)row * Dm + d) = *(uint4*)h8;
    *(uint4*)(OL + (size_t)row * Dm + d) = *(uint4*)l8;
}

// ===================== bf16 mma.sync GEMM, 3-term compensated =====================
// C[M,N] = (Ahi+Alo)[M,K] @ (Bhi+Blo)[N,K]^T (+Res)
// 128x128 tile, BK=32, 3 cp.async stages, 8 warps = 4(M) x 2(N), warp tile 32x64.
#define GBK 32
#define G_ROWB 80                         // 32 bf16 (64B) + 16B pad
#define G_TILEB (128 * G_ROWB)            // 10240
#define G_STAGEB (4 * G_TILEB)            // 40960 (Ah, Al, Bh, Bl)
#define G_DSMEM (3 * G_STAGEB)            // 122880

__global__ __launch_bounds__(256, 1)
void gemm3_bf16(const bf16* __restrict__ Ahi, const bf16* __restrict__ Alo,
                const bf16* __restrict__ Bhi, const bf16* __restrict__ Blo,
                const float* __restrict__ Res, float* __restrict__ C,
                int M, int N, int K)
{
    extern __shared__ char smem[];
    uint32_t sb = smem_u32(smem);
    int tid  = threadIdx.x;
    int wid  = tid >> 5;
    int lane = tid & 31;
    int wm = wid & 3;          // 4 warps over M (32 rows each)
    int wn = wid >> 2;         // 2 warps over N (64 cols each)
    int bm = blockIdx.y * 128;
    int bn = blockIdx.x * 128;

    // cp.async load of one 32-k chunk: 4 tiles of 128 rows x 32 bf16
    auto loadChunk = [&](int stg, int k0) {
        uint32_t base = sb + stg * G_STAGEB;
#pragma unroll
        for (int h = 0; h < 2; h++) {
            int cid = tid * 2 + h;          // 0..511
            int r = cid >> 2;
            int c = cid & 3;
            uint32_t doff = r * G_ROWB + c * 16;
            size_t soff = (size_t)r * K + k0 + c * 8;
            CP_ASYNC16(base + doff,             Ahi + (size_t)bm * K + soff);
            CP_ASYNC16(base + G_TILEB + doff,   Alo + (size_t)bm * K + soff);
            CP_ASYNC16(base + 2*G_TILEB + doff, Bhi + (size_t)bn * K + soff);
            CP_ASYNC16(base + 3*G_TILEB + doff, Blo + (size_t)bn * K + soff);
        }
    };

    float acc[2][8][4];
#pragma unroll
    for (int i = 0; i < 2; i++)
#pragma unroll
        for (int j = 0; j < 8; j++)
#pragma unroll
            for (int t = 0; t < 4; t++) acc[i][j][t] = 0.f;

    // ldmatrix lane-address components
    int a_row = ((lane >> 3) & 1) * 8 + (lane & 7);   // + kbyte (lane>>4)*16
    int b_row = (lane & 7);                            // + nfrag sel ((lane>>4)&1)
    int b_kb  = ((lane >> 3) & 1) * 16;

    int NKC = K / GBK;
    loadChunk(0, 0);        CP_COMMIT();
    loadChunk(1, GBK);      CP_COMMIT();
    loadChunk(2, 2 * GBK);  CP_COMMIT();

    for (int k = 0; k < NKC; k++) {
        int stg = k % 3;
        CP_WAIT2();
        __syncthreads();
        uint32_t base = sb + stg * G_STAGEB;
#pragma unroll
        for (int kk = 0; kk < 2; kk++) {
            uint32_t Ah[2][4], Al[2][4];
#pragma unroll
            for (int mf = 0; mf < 2; mf++) {
                uint32_t addr = base + (uint32_t)((wm*32 + mf*16 + a_row) * G_ROWB)
                              + kk*32 + (lane >> 4) * 16;
                ldm_x4(Ah[mf], addr);
                ldm_x4(Al[mf], addr + G_TILEB);
            }
#pragma unroll
            for (int g = 0; g < 2; g++) {
                uint32_t Bh[4][2], Bl[4][2];
#pragma unroll
                for (int p = 0; p < 2; p++) {
                    uint32_t addr = base + 2*G_TILEB
                        + (uint32_t)((wn*64 + (g*4 + p*2 + ((lane>>4)&1))*8 + b_row) * G_ROWB)
                        + kk*32 + b_kb;
                    uint32_t r4[4];
                    ldm_x4(r4, addr);
                    Bh[p*2][0] = r4[0]; Bh[p*2][1] = r4[1];
                    Bh[p*2+1][0] = r4[2]; Bh[p*2+1][1] = r4[3];
                    ldm_x4(r4, addr + G_TILEB);
                    Bl[p*2][0] = r4[0]; Bl[p*2][1] = r4[1];
                    Bl[p*2+1][0] = r4[2]; Bl[p*2+1][1] = r4[3];
                }
#pragma unroll
                for (int mf = 0; mf < 2; mf++)
#pragma unroll
                    for (int nf = 0; nf < 4; nf++) {
                        float* c = acc[mf][g*4 + nf];
                        mma_bf16(c, Ah[mf], Bh[nf][0], Bh[nf][1]);
                        mma_bf16(c, Al[mf], Bh[nf][0], Bh[nf][1]);
                        mma_bf16(c, Ah[mf], Bl[nf][0], Bl[nf][1]);
                    }
            }
        }
        __syncthreads();
        if (k + 3 < NKC) loadChunk(stg, (k + 3) * GBK);
        CP_COMMIT();
    }

    // Epilogue: direct float2 stores (+optional residual)
    int rr = lane >> 2;
    int cp = lane & 3;
#pragma unroll
    for (int mf = 0; mf < 2; mf++) {
        int row0 = bm + wm*32 + mf*16 + rr;
#pragma unroll
        for (int nf = 0; nf < 8; nf++) {
            int col = bn + wn*64 + nf*8 + cp*2;
            float* c = acc[mf][nf];
            size_t o0 = (size_t)row0 * N + col;
            size_t o1 = (size_t)(row0 + 8) * N + col;
            float2 v0 = make_float2(c[0], c[1]);
            float2 v1 = make_float2(c[2], c[3]);
            if (Res) {
                float2 e0 = *(const float2*)(Res + o0);
                float2 e1 = *(const float2*)(Res + o1);
                v0.x += e0.x; v0.y += e0.y;
                v1.x += e1.x; v1.y += e1.y;
            }
            *(float2*)(C + o0) = v0;
            *(float2*)(C + o1) = v1;
        }
    }
}

// ---------------- partial RoPE on first 16 dims of each head ----------------
__global__ __launch_bounds__(256) void rope_kernel(float* __restrict__ X, int rows)
{
    int row = blockIdx.x;
    if (row >= rows) return;
    int r = threadIdx.x;
    int h = r >> 3, d = r & 7;
    int pos = row & (S - 1);
    float invf = __powf(10000.f, -(float)d * 0.125f);
    float ang  = (float)pos * invf;
    float sn, cs;
    sincosf(ang, &sn, &cs);
    float* p = X + (size_t)row * Dm + h * HD;
    float x1 = p[d], x2 = p[d + 8];
    p[d]     = x1 * cs - x2 * sn;
    p[d + 8] = x2 * cs + x1 * sn;
}

// ---------------- sparse attention (fp32), epilogue writes bf16 hi/lo -------
#define AM 64
#define AN 32
__global__ __launch_bounds__(256) void attn_kernel(
    const float* __restrict__ Q, const float* __restrict__ K,
    const float* __restrict__ V, bf16* __restrict__ OH, bf16* __restrict__ OL)
{
    __shared__ float qs[AM][65];
    __shared__ float ks[AN][65];
    __shared__ float vs[AN][65];
    __shared__ float ps[AM][33];
    __shared__ float red[AM][8];

    int qb = blockIdx.x;
    int h  = blockIdx.y;
    int tid = threadIdx.x;
    int m  = tid >> 2;
    int q4 = tid & 3;
    int i  = qb * AM + m;

    {
        const float* qrow = Q + (size_t)i * Dm + h * HD + q4 * 16;
#pragma unroll
        for (int t = 0; t < 4; t++) {
            float4 v4 = *(const float4*)(qrow + t * 4);
            qs[m][q4*16 + t*4 + 0] = v4.x;
            qs[m][q4*16 + t*4 + 1] = v4.y;
            qs[m][q4*16 + t*4 + 2] = v4.z;
            qs[m][q4*16 + t*4 + 3] = v4.w;
        }
    }

    float mi = -1e30f, li = 0.f;
    float acc[16];
#pragma unroll
    for (int t = 0; t < 16; t++) acc[t] = 0.f;

    int kbmax = 2 * qb + 1;
    for (int kb = 0; kb <= kbmax; kb++) {
        __syncthreads();
        {
            int lr = tid >> 3;
            int lcc = (tid & 7) * 8;
            const float* kp = K + (size_t)(kb * AN + lr) * Dm + h * HD + lcc;
            const float* vp = V + (size_t)(kb * AN + lr) * Dm + h * HD + lcc;
            float4 a = *(const float4*)kp, b = *(const float4*)(kp + 4);
            ks[lr][lcc+0]=a.x; ks[lr][lcc+1]=a.y; ks[lr][lcc+2]=a.z; ks[lr][lcc+3]=a.w;
            ks[lr][lcc+4]=b.x; ks[lr][lcc+5]=b.y; ks[lr][lcc+6]=b.z; ks[lr][lcc+7]=b.w;
            float4 c = *(const float4*)vp, d = *(const float4*)(vp + 4);
            vs[lr][lcc+0]=c.x; vs[lr][lcc+1]=c.y; vs[lr][lcc+2]=c.z; vs[lr][lcc+3]=c.w;
            vs[lr][lcc+4]=d.x; vs[lr][lcc+5]=d.y; vs[lr][lcc+6]=d.z; vs[lr][lcc+7]=d.w;
        }
        __syncthreads();

        float sc[8];
#pragma unroll
        for (int n = 0; n < 8; n++) sc[n] = 0.f;
#pragma unroll
        for (int d = 0; d < HD; d++) {
            float qd = qs[m][d];
#pragma unroll
            for (int n = 0; n < 8; n++)
                sc[n] += qd * ks[q4*8 + n][d];
        }
        float lmax = -1e30f;
#pragma unroll
        for (int n = 0; n < 8; n++) {
            int j = kb * AN + q4 * 8 + n;
            float sv = sc[n] * 0.125f;
            if (j >= i) sv = -1e30f;
            sc[n] = sv;
            lmax = fmaxf(lmax, sv);
        }
        red[m][q4] = lmax;
        __syncthreads();
        float rmax = fmaxf(fmaxf(red[m][0], red[m][1]), fmaxf(red[m][2], red[m][3]));
        float newm = fmaxf(mi, rmax);
        float scale = __expf(mi - newm);
        float lsum = 0.f;
#pragma unroll
        for (int n = 0; n < 8; n++) {
            float p = (sc[n] <= -1e29f) ? 0.f : __expf(sc[n] - newm);
            ps[m][q4*8 + n] = p;
            lsum += p;
        }
        red[m][4 + q4] = lsum;
        __syncthreads();
        float rsum = red[m][4] + red[m][5] + red[m][6] + red[m][7];
        mi = newm;
        li = li * scale + rsum;
#pragma unroll
        for (int t = 0; t < 16; t++) acc[t] *= scale;
        for (int n = 0; n < AN; n++) {
            float p = ps[m][n];
#pragma unroll
            for (int t = 0; t < 16; t++)
                acc[t] += p * vs[n][q4*16 + t];
        }
    }

    {
        const float* krow = K + (size_t)(S + i) * Dm + h * HD + q4 * 16;
        float part = 0.f;
#pragma unroll
        for (int t = 0; t < 16; t++) part += qs[m][q4*16 + t] * krow[t];
        __syncthreads();
        red[m][q4] = part;
        __syncthreads();
        float sself = 0.125f * (red[m][0] + red[m][1] + red[m][2] + red[m][3]);
        float newm = fmaxf(mi, sself);
        float scale = __expf(mi - newm);
        float p = __expf(sself - newm);
        li = li * scale + p;
        float inv = 1.f / li;
        const float* vrow = V + (size_t)(S + i) * Dm + h * HD + q4 * 16;
        uint16_t h16[16], l16[16];
#pragma unroll
        for (int t = 0; t < 16; t++) {
            float val = (acc[t] * scale + p * vrow[t]) * inv;
            bf16 hv = __float2bfloat16_rn(val);
            bf16 lv = __float2bfloat16_rn(val - __bfloat162float(hv));
            h16[t] = *(uint16_t*)&hv;
            l16[t] = *(uint16_t*)&lv;
        }
        bf16* orh = OH + (size_t)i * Dm + h * HD + q4 * 16;
        bf16* orl = OL + (size_t)i * Dm + h * HD + q4 * 16;
        *(uint4*)(orh)     = *(uint4*)(h16);
        *(uint4*)(orh + 8) = *(uint4*)(h16 + 8);
        *(uint4*)(orl)     = *(uint4*)(l16);
        *(uint4*)(orl + 8) = *(uint4*)(l16 + 8);
    }
}

// ---------------- SiLU(gate) * up with fused bf16 split ----------------
__global__ __launch_bounds__(256) void silu_split_kernel(
    const float* __restrict__ G, const float* __restrict__ U,
    bf16* __restrict__ OH, bf16* __restrict__ OL, int n4)
{
    int idx = blockIdx.x * blockDim.x + threadIdx.x;
    if (idx >= n4) return;
    float4 g = ((const float4*)G)[idx];
    float4 u = ((const float4*)U)[idx];
    float v[4];
    v[0] = g.x / (1.f + __expf(-g.x)) * u.x;
    v[1] = g.y / (1.f + __expf(-g.y)) * u.y;
    v[2] = g.z / (1.f + __expf(-g.z)) * u.z;
    v[3] = g.w / (1.f + __expf(-g.w)) * u.w;
    uint16_t h4[4], l4[4];
#pragma unroll
    for (int i = 0; i < 4; i++) {
        bf16 hv = __float2bfloat16_rn(v[i]);
        bf16 lv = __float2bfloat16_rn(v[i] - __bfloat162float(hv));
        h4[i] = *(uint16_t*)&hv;
        l4[i] = *(uint16_t*)&lv;
    }
    ((uint2*)OH)[idx] = *(uint2*)h4;
    ((uint2*)OL)[idx] = *(uint2*)l4;
}

// ===================== launch =====================
extern "C" void kernel_launch(void* const* d_in, const int* in_sizes, int n_in,
                              void* d_out, int out_size)
{
    const float* hidden = (const float*)d_in[0];
    const float* memory = (const float*)d_in[1];
    const float* ln1w = (const float*)d_in[4];
    const float* ln1b = (const float*)d_in[5];
    const float* ln2w = (const float*)d_in[6];
    const float* ln2b = (const float*)d_in[7];
    const float* Wq = (const float*)d_in[8];
    const float* Wk = (const float*)d_in[9];
    const float* Wv = (const float*)d_in[10];
    const float* Wo = (const float*)d_in[11];
    const float* Wg = (const float*)d_in[12];
    const float* Wu = (const float*)d_in[13];
    const float* Wd = (const float*)d_in[14];
    float* out = (float*)d_out;

    void* p;
    cudaGetSymbolAddress(&p, g_xh);  bf16* xh  = (bf16*)p;
    cudaGetSymbolAddress(&p, g_xl);  bf16* xl  = (bf16*)p;
    cudaGetSymbolAddress(&p, g_q);   float* q   = (float*)p;
    cudaGetSymbolAddress(&p, g_k);   float* k   = (float*)p;
    cudaGetSymbolAddress(&p, g_v);   float* v   = (float*)p;
    cudaGetSymbolAddress(&p, g_ah);  bf16* ah  = (bf16*)p;
    cudaGetSymbolAddress(&p, g_al);  bf16* al  = (bf16*)p;
    cudaGetSymbolAddress(&p, g_h);   float* hbuf= (float*)p;
    cudaGetSymbolAddress(&p, g_h2h); bf16* h2h = (bf16*)p;
    cudaGetSymbolAddress(&p, g_h2l); bf16* h2l = (bf16*)p;
    cudaGetSymbolAddress(&p, g_gr);  float* gr  = (float*)p;
    cudaGetSymbolAddress(&p, g_ur);  float* ur  = (float*)p;
    cudaGetSymbolAddress(&p, g_gh);  bf16* gh  = (bf16*)p;
    cudaGetSymbolAddress(&p, g_gl);  bf16* gl  = (bf16*)p;
    cudaGetSymbolAddress(&p, g_wqh); bf16* wqh = (bf16*)p;
    cudaGetSymbolAddress(&p, g_wql); bf16* wql = (bf16*)p;
    cudaGetSymbolAddress(&p, g_wkh); bf16* wkh = (bf16*)p;
    cudaGetSymbolAddress(&p, g_wkl); bf16* wkl = (bf16*)p;
    cudaGetSymbolAddress(&p, g_wvh); bf16* wvh = (bf16*)p;
    cudaGetSymbolAddress(&p, g_wvl); bf16* wvl = (bf16*)p;
    cudaGetSymbolAddress(&p, g_woh); bf16* woh = (bf16*)p;
    cudaGetSymbolAddress(&p, g_wol); bf16* wol = (bf16*)p;
    cudaGetSymbolAddress(&p, g_wgh); bf16* wgh = (bf16*)p;
    cudaGetSymbolAddress(&p, g_wgl); bf16* wgl = (bf16*)p;
    cudaGetSymbolAddress(&p, g_wuh); bf16* wuh = (bf16*)p;
    cudaGetSymbolAddress(&p, g_wul); bf16* wul = (bf16*)p;
    cudaGetSymbolAddress(&p, g_wdh); bf16* wdh = (bf16*)p;
    cudaGetSymbolAddress(&p, g_wdl); bf16* wdl = (bf16*)p;

    cudaFuncSetAttribute(gemm3_bf16, cudaFuncAttributeMaxDynamicSharedMemorySize, G_DSMEM);

    // 1. LN1 with fused split
    ln_split_kernel<<<S, 256>>>(memory, ln1w, ln1b, xh, xl);
    ln_split_kernel<<<S, 256>>>(hidden, ln1w, ln1b, xh + (size_t)S * Dm, xl + (size_t)S * Dm);

    // 2. weight splits
    {
        int nDD = Dm * Dm / 4, nFD = FF * Dm / 4;
        split_kernel<<<nDD / 256, 256>>>(Wq, wqh, wql, nDD);
        split_kernel<<<nDD / 256, 256>>>(Wk, wkh, wkl, nDD);
        split_kernel<<<nDD / 256, 256>>>(Wv, wvh, wvl, nDD);
        split_kernel<<<nDD / 256, 256>>>(Wo, woh, wol, nDD);
        split_kernel<<<nFD / 256, 256>>>(Wg, wgh, wgl, nFD);
        split_kernel<<<nFD / 256, 256>>>(Wu, wuh, wul, nFD);
        split_kernel<<<nFD / 256, 256>>>(Wd, wdh, wdl, nFD);
    }

    // 3. QKV projections (tensor cores via mma.sync)
    {
        dim3 gKV(Dm / 128, L / 128);
        gemm3_bf16<<<gKV, 256, G_DSMEM>>>(xh, xl, wkh, wkl, nullptr, k, L, Dm, Dm);
        gemm3_bf16<<<gKV, 256, G_DSMEM>>>(xh, xl, wvh, wvl, nullptr, v, L, Dm, Dm);
        dim3 gQ(Dm / 128, S / 128);
        gemm3_bf16<<<gQ, 256, G_DSMEM>>>(xh + (size_t)S * Dm, xl + (size_t)S * Dm,
                                         wqh, wql, nullptr, q, S, Dm, Dm);
    }

    // 4. RoPE
    rope_kernel<<<S, 256>>>(q, S);
    rope_kernel<<<L, 256>>>(k, L);

    // 5. sparse attention (epilogue emits bf16 hi/lo)
    {
        dim3 g(S / AM, NH);
        attn_kernel<<<g, 256>>>(q, k, v, ah, al);
    }

    // 6. output projection + residual
    {
        dim3 g(Dm / 128, S / 128);
        gemm3_bf16<<<g, 256, G_DSMEM>>>(ah, al, woh, wol, hidden, hbuf, S, Dm, Dm);
    }

    // 7. LN2 with fused split
    ln_split_kernel<<<S, 256>>>(hbuf, ln2w, ln2b, h2h, h2l);

    // 8. gate/up projections
    {
        dim3 g(FF / 128, S / 128);
        gemm3_bf16<<<g, 256, G_DSMEM>>>(h2h, h2l, wgh, wgl, nullptr, gr, S, FF, Dm);
        gemm3_bf16<<<g, 256, G_DSMEM>>>(h2h, h2l, wuh, wul, nullptr, ur, S, FF, Dm);
    }

    // 9. silu * up with fused split
    {
        int n4 = S * FF / 4;
        silu_split_kernel<<<n4 / 256, 256>>>(gr, ur, gh, gl, n4);
    }

    // 10. down projection + residual -> output
    {
        dim3 g(Dm / 128, S / 128);
        gemm3_bf16<<<g, 256, G_DSMEM>>>(gh, gl, wdh, wdl, hbuf, out, S, Dm, FF);
    }
}

// round 5
// speedup vs baseline: 1.6095x; 1.6095x over previous
#include <cuda_runtime.h>
#include <cuda_bf16.h>
#include <cstdint>

#define S    2048
#define Dm   2048
#define FF   8192
#define NH   32
#define HD   64
#define L    4096

typedef __nv_bfloat16 bf16;

__device__ __forceinline__ uint32_t smem_u32(const void* p) {
    uint32_t a;
    asm("{ .reg .u64 t; cvta.to.shared.u64 t, %1; cvt.u32.u64 %0, t; }" : "=r"(a) : "l"(p));
    return a;
}
__device__ __forceinline__ void ldm_x4(uint32_t* r, uint32_t a) {
    asm volatile("ldmatrix.sync.aligned.m8n8.x4.shared.b16 {%0,%1,%2,%3}, [%4];"
        : "=r"(r[0]), "=r"(r[1]), "=r"(r[2]), "=r"(r[3]) : "r"(a));
}
__device__ __forceinline__ void ldm_x4_t(uint32_t* r, uint32_t a) {
    asm volatile("ldmatrix.sync.aligned.m8n8.x4.trans.shared.b16 {%0,%1,%2,%3}, [%4];"
        : "=r"(r[0]), "=r"(r[1]), "=r"(r[2]), "=r"(r[3]) : "r"(a));
}
__device__ __forceinline__ void mma_bf16(float* c, const uint32_t* a, uint32_t b0, uint32_t b1) {
    asm volatile("mma.sync.aligned.m16n8k16.row.col.f32.bf16.bf16.f32 "
        "{%0,%1,%2,%3}, {%4,%5,%6,%7}, {%8,%9}, {%0,%1,%2,%3};"
        : "+f"(c[0]), "+f"(c[1]), "+f"(c[2]), "+f"(c[3])
        : "r"(a[0]), "r"(a[1]), "r"(a[2]), "r"(a[3]), "r"(b0), "r"(b1));
}
__device__ __forceinline__ uint32_t pack_bf16(float a, float b) {
    __nv_bfloat162 t; t.x = __float2bfloat16_rn(a); t.y = __float2bfloat16_rn(b);
    return *(uint32_t*)&t;
}
#define CP_ASYNC16(dst, src) \
    asm volatile("cp.async.cg.shared.global [%0], [%1], 16;" :: "r"(dst), "l"(src))
#define CP_COMMIT() asm volatile("cp.async.commit_group;" ::: "memory")
#define CP_WAIT1()  asm volatile("cp.async.wait_group 1;" ::: "memory")

// ------------- scratch -------------
__device__ bf16  g_xh [L * Dm]; __device__ bf16 g_xl [L * Dm];
__device__ float g_q  [S * Dm];
__device__ float g_k  [L * Dm];
__device__ float g_v  [L * Dm];
__device__ bf16  g_qh [S * Dm]; __device__ bf16 g_ql [S * Dm];
__device__ bf16  g_kh [L * Dm]; __device__ bf16 g_kl [L * Dm];
__device__ bf16  g_vh [L * Dm]; __device__ bf16 g_vl [L * Dm];
__device__ bf16  g_ah [S * Dm]; __device__ bf16 g_al [S * Dm];
__device__ float g_h  [S * Dm];
__device__ bf16  g_h2h[S * Dm]; __device__ bf16 g_h2l[S * Dm];
__device__ float g_gr [S * FF]; __device__ float g_ur [S * FF];
__device__ bf16  g_gh [S * FF]; __device__ bf16 g_gl [S * FF];
__device__ bf16  g_wqh[Dm * Dm]; __device__ bf16 g_wql[Dm * Dm];
__device__ bf16  g_wkh[Dm * Dm]; __device__ bf16 g_wkl[Dm * Dm];
__device__ bf16  g_wvh[Dm * Dm]; __device__ bf16 g_wvl[Dm * Dm];
__device__ bf16  g_woh[Dm * Dm]; __device__ bf16 g_wol[Dm * Dm];
__device__ bf16  g_wgh[FF * Dm]; __device__ bf16 g_wgl[FF * Dm];
__device__ bf16  g_wuh[FF * Dm]; __device__ bf16 g_wul[FF * Dm];
__device__ bf16  g_wdh[Dm * FF]; __device__ bf16 g_wdl[Dm * FF];

// ------------- hi/lo split -------------
__global__ __launch_bounds__(256) void split_kernel(
    const float* __restrict__ X, bf16* __restrict__ H, bf16* __restrict__ Lo, int n4)
{
    int i = blockIdx.x * blockDim.x + threadIdx.x;
    if (i >= n4) return;
    float4 x = ((const float4*)X)[i];
    bf16 h0 = __float2bfloat16_rn(x.x), h1 = __float2bfloat16_rn(x.y);
    bf16 h2 = __float2bfloat16_rn(x.z), h3 = __float2bfloat16_rn(x.w);
    uint2 hu, lu;
    hu.x = pack_bf16(x.x, x.y); hu.y = pack_bf16(x.z, x.w);
    lu.x = pack_bf16(x.x - __bfloat162float(h0), x.y - __bfloat162float(h1));
    lu.y = pack_bf16(x.z - __bfloat162float(h2), x.w - __bfloat162float(h3));
    ((uint2*)H)[i] = hu;
    ((uint2*)Lo)[i] = lu;
}

// ------------- LayerNorm + split -------------
__global__ __launch_bounds__(256) void ln_split_kernel(
    const float* __restrict__ X, const float* __restrict__ w,
    const float* __restrict__ b, bf16* __restrict__ OH, bf16* __restrict__ OL)
{
    int row = blockIdx.x, tid = threadIdx.x;
    const float* xr = X + (size_t)row * Dm;
    float4 a = ((const float4*)xr)[tid * 2];
    float4 c = ((const float4*)xr)[tid * 2 + 1];
    float s  = a.x + a.y + a.z + a.w + c.x + c.y + c.z + c.w;
    float ss = a.x*a.x + a.y*a.y + a.z*a.z + a.w*a.w
             + c.x*c.x + c.y*c.y + c.z*c.z + c.w*c.w;
#pragma unroll
    for (int o = 16; o; o >>= 1) {
        s  += __shfl_xor_sync(0xffffffffu, s,  o);
        ss += __shfl_xor_sync(0xffffffffu, ss, o);
    }
    __shared__ float bs[8], bss[8];
    if ((tid & 31) == 0) { bs[tid >> 5] = s; bss[tid >> 5] = ss; }
    __syncthreads();
    float ts = 0.f, tss = 0.f;
#pragma unroll
    for (int i = 0; i < 8; i++) { ts += bs[i]; tss += bss[i]; }
    float mean = ts * (1.f / Dm);
    float inv  = rsqrtf(tss * (1.f / Dm) - mean * mean + 1e-5f);
    int d = tid * 8;
    float4 w0 = ((const float4*)w)[tid*2], w1 = ((const float4*)w)[tid*2+1];
    float4 b0 = ((const float4*)b)[tid*2], b1 = ((const float4*)b)[tid*2+1];
    float v8[8];
    v8[0]=(a.x-mean)*inv*w0.x+b0.x; v8[1]=(a.y-mean)*inv*w0.y+b0.y;
    v8[2]=(a.z-mean)*inv*w0.z+b0.z; v8[3]=(a.w-mean)*inv*w0.w+b0.w;
    v8[4]=(c.x-mean)*inv*w1.x+b1.x; v8[5]=(c.y-mean)*inv*w1.y+b1.y;
    v8[6]=(c.z-mean)*inv*w1.z+b1.z; v8[7]=(c.w-mean)*inv*w1.w+b1.w;
    uint16_t h8[8], l8[8];
#pragma unroll
    for (int i = 0; i < 8; i++) {
        bf16 hv = __float2bfloat16_rn(v8[i]);
        bf16 lv = __float2bfloat16_rn(v8[i] - __bfloat162float(hv));
        h8[i] = *(uint16_t*)&hv; l8[i] = *(uint16_t*)&lv;
    }
    *(uint4*)(OH + (size_t)row * Dm + d) = *(uint4*)h8;
    *(uint4*)(OL + (size_t)row * Dm + d) = *(uint4*)l8;
}

// ------------- RoPE (dims 0..15/head) + fp32 writeback + scaled split -------------
__global__ __launch_bounds__(256) void rope_split_kernel(
    float* __restrict__ X, bf16* __restrict__ OH, bf16* __restrict__ OL, float scale)
{
    int row = blockIdx.x, tid = threadIdx.x;
    int pos = row & (S - 1);
    float* xr = X + (size_t)row * Dm;
    int dim0 = tid * 8;
    int hd = dim0 & 63;
    float v[8], part[8];
    *(float4*)v     = *(float4*)(xr + dim0);
    *(float4*)(v+4) = *(float4*)(xr + dim0 + 4);
    if (hd == 0) {
        *(float4*)part     = *(float4*)(xr + dim0 + 8);
        *(float4*)(part+4) = *(float4*)(xr + dim0 + 12);
    } else if (hd == 8) {
        *(float4*)part     = *(float4*)(xr + dim0 - 8);
        *(float4*)(part+4) = *(float4*)(xr + dim0 - 4);
    }
    __syncwarp();
    if (hd == 0 || hd == 8) {
#pragma unroll
        for (int j = 0; j < 8; j++) {
            float invf = __powf(10000.f, -(float)j * 0.125f);
            float sn, cs; sincosf(pos * invf, &sn, &cs);
            v[j] = (hd == 0) ? (v[j] * cs - part[j] * sn) : (v[j] * cs + part[j] * sn);
        }
        *(float4*)(xr + dim0)     = *(float4*)v;
        *(float4*)(xr + dim0 + 4) = *(float4*)(v+4);
    }
    uint16_t h8[8], l8[8];
#pragma unroll
    for (int j = 0; j < 8; j++) {
        float val = v[j] * scale;
        bf16 hv = __float2bfloat16_rn(val);
        bf16 lv = __float2bfloat16_rn(val - __bfloat162float(hv));
        h8[j] = *(uint16_t*)&hv; l8[j] = *(uint16_t*)&lv;
    }
    *(uint4*)(OH + (size_t)row * Dm + dim0) = *(uint4*)h8;
    *(uint4*)(OL + (size_t)row * Dm + dim0) = *(uint4*)l8;
}

// ------------- GEMM: 3-term bf16, 128x128, 2 stages, 2 CTAs/SM -------------
#define GBK 32
#define G_ROWB 80
#define G_TILEB (128 * G_ROWB)
#define G_STAGEB (4 * G_TILEB)
#define G_DSMEM (2 * G_STAGEB)

__global__ __launch_bounds__(256, 2)
void gemm3_bf16(const bf16* __restrict__ Ahi, const bf16* __restrict__ Alo,
                const bf16* __restrict__ Bhi, const bf16* __restrict__ Blo,
                const float* __restrict__ Res, float* __restrict__ C,
                int M, int N, int K)
{
    extern __shared__ char smem[];
    uint32_t sb = smem_u32(smem);
    int tid  = threadIdx.x, wid = tid >> 5, lane = tid & 31;
    int wm = wid & 3, wn = wid >> 2;
    int bm = blockIdx.y * 128, bn = blockIdx.x * 128;

    auto loadChunk = [&](int stg, int k0) {
        uint32_t base = sb + stg * G_STAGEB;
#pragma unroll
        for (int h = 0; h < 2; h++) {
            int cid = tid * 2 + h;
            int r = cid >> 2, c = cid & 3;
            uint32_t doff = r * G_ROWB + c * 16;
            size_t soff = (size_t)r * K + k0 + c * 8;
            CP_ASYNC16(base + doff,             Ahi + (size_t)bm * K + soff);
            CP_ASYNC16(base + G_TILEB + doff,   Alo + (size_t)bm * K + soff);
            CP_ASYNC16(base + 2*G_TILEB + doff, Bhi + (size_t)bn * K + soff);
            CP_ASYNC16(base + 3*G_TILEB + doff, Blo + (size_t)bn * K + soff);
        }
    };

    float acc[2][8][4];
#pragma unroll
    for (int i = 0; i < 2; i++)
#pragma unroll
        for (int j = 0; j < 8; j++)
#pragma unroll
            for (int t = 0; t < 4; t++) acc[i][j][t] = 0.f;

    int a_row = lane & 15;
    int b_row = lane & 7;
    int b_kb  = ((lane >> 3) & 1) * 16;
    int NKC = K / GBK;
    loadChunk(0, 0);    CP_COMMIT();
    loadChunk(1, GBK);  CP_COMMIT();

    for (int k = 0; k < NKC; k++) {
        int stg = k & 1;
        CP_WAIT1();
        __syncthreads();
        uint32_t base = sb + stg * G_STAGEB;
#pragma unroll
        for (int kk = 0; kk < 2; kk++) {
            uint32_t Ah[2][4], Al[2][4];
#pragma unroll
            for (int mf = 0; mf < 2; mf++) {
                uint32_t addr = base + (uint32_t)((wm*32 + mf*16 + a_row) * G_ROWB)
                              + kk*32 + (lane >> 4) * 16;
                ldm_x4(Ah[mf], addr);
                ldm_x4(Al[mf], addr + G_TILEB);
            }
#pragma unroll
            for (int g = 0; g < 2; g++) {
                uint32_t Bh[4][2], Bl[4][2];
#pragma unroll
                for (int p = 0; p < 2; p++) {
                    uint32_t addr = base + 2*G_TILEB
                        + (uint32_t)((wn*64 + (g*4 + p*2 + ((lane>>4)&1))*8 + b_row) * G_ROWB)
                        + kk*32 + b_kb;
                    uint32_t r4[4];
                    ldm_x4(r4, addr);
                    Bh[p*2][0] = r4[0]; Bh[p*2][1] = r4[1];
                    Bh[p*2+1][0] = r4[2]; Bh[p*2+1][1] = r4[3];
                    ldm_x4(r4, addr + G_TILEB);
                    Bl[p*2][0] = r4[0]; Bl[p*2][1] = r4[1];
                    Bl[p*2+1][0] = r4[2]; Bl[p*2+1][1] = r4[3];
                }
#pragma unroll
                for (int mf = 0; mf < 2; mf++)
#pragma unroll
                    for (int nf = 0; nf < 4; nf++) {
                        float* c = acc[mf][g*4 + nf];
                        mma_bf16(c, Ah[mf], Bh[nf][0], Bh[nf][1]);
                        mma_bf16(c, Al[mf], Bh[nf][0], Bh[nf][1]);
                        mma_bf16(c, Ah[mf], Bl[nf][0], Bl[nf][1]);
                    }
            }
        }
        __syncthreads();
        if (k + 2 < NKC) loadChunk(stg, (k + 2) * GBK);
        CP_COMMIT();
    }

    int rr = lane >> 2, cp = lane & 3;
#pragma unroll
    for (int mf = 0; mf < 2; mf++) {
        int row0 = bm + wm*32 + mf*16 + rr;
#pragma unroll
        for (int nf = 0; nf < 8; nf++) {
            int col = bn + wn*64 + nf*8 + cp*2;
            float* c = acc[mf][nf];
            size_t o0 = (size_t)row0 * N + col;
            size_t o1 = (size_t)(row0 + 8) * N + col;
            float2 v0 = make_float2(c[0], c[1]);
            float2 v1 = make_float2(c[2], c[3]);
            if (Res) {
                float2 e0 = *(const float2*)(Res + o0);
                float2 e1 = *(const float2*)(Res + o1);
                v0.x += e0.x; v0.y += e0.y; v1.x += e1.x; v1.y += e1.y;
            }
            *(float2*)(C + o0) = v0;
            *(float2*)(C + o1) = v1;
        }
    }
}

// ------------- flash attention via mma.sync -------------
// 64 q/CTA (4 warps x 16), memory keys j<i in 64-blocks, + scalar self token.
#define A_PITCH 144
#define A_SQH 0u
#define A_SQL 9216u
#define A_SKH 18432u
#define A_SKL 36864u
#define A_SVH 55296u
#define A_SVL 73728u
#define A_SMS 92160u
#define A_SLS 92416u
#define A_DSMEM 92672

__global__ __launch_bounds__(128)
void attn_mma_kernel(const bf16* __restrict__ Qh, const bf16* __restrict__ Ql,
                     const bf16* __restrict__ Kh, const bf16* __restrict__ Kl,
                     const bf16* __restrict__ Vh, const bf16* __restrict__ Vl,
                     const float* __restrict__ Qf, const float* __restrict__ Kf,
                     const float* __restrict__ Vf,
                     bf16* __restrict__ OH, bf16* __restrict__ OL)
{
    extern __shared__ char sm[];
    uint32_t sb = smem_u32(sm);
    const int qb = blockIdx.x, h = blockIdx.y;
    const int tid = threadIdx.x, wid = tid >> 5, lane = tid & 31;
    const int m0 = wid * 16;

#pragma unroll
    for (int j = 0; j < 4; j++) {
        int idx = tid + j * 128;
        int row = idx >> 3, c = idx & 7;
        size_t g = (size_t)(qb*64 + row) * Dm + h*64 + c*8;
        *(uint4*)(sm + A_SQH + row*A_PITCH + c*16) = *(const uint4*)(Qh + g);
        *(uint4*)(sm + A_SQL + row*A_PITCH + c*16) = *(const uint4*)(Ql + g);
    }
    auto loadKV = [&](int kb, int st) {
        uint32_t o = (uint32_t)st * 9216u;
#pragma unroll
        for (int j = 0; j < 4; j++) {
            int idx = tid + j * 128;
            int row = idx >> 3, c = idx & 7;
            size_t g = (size_t)(kb*64 + row) * Dm + h*64 + c*8;
            uint32_t d = o + row*A_PITCH + c*16;
            CP_ASYNC16(sb + A_SKH + d, Kh + g);
            CP_ASYNC16(sb + A_SKL + d, Kl + g);
            CP_ASYNC16(sb + A_SVH + d, Vh + g);
            CP_ASYNC16(sb + A_SVL + d, Vl + g);
        }
    };
    loadKV(0, 0); CP_COMMIT();
    __syncthreads();

    uint32_t qfh[4][4], qfl[4][4];
    {
        int a_row = lane & 15, koff = (lane >> 4) * 16;
#pragma unroll
        for (int kk = 0; kk < 4; kk++) {
            uint32_t ad = sb + A_SQH + (uint32_t)(m0 + a_row) * A_PITCH + kk*32 + koff;
            ldm_x4(qfh[kk], ad);
            ldm_x4(qfl[kk], ad + 9216u);
        }
    }

    float oacc[8][4];
#pragma unroll
    for (int nf = 0; nf < 8; nf++)
#pragma unroll
        for (int t = 0; t < 4; t++) oacc[nf][t] = 0.f;
    float mi0 = -1e30f, mi1 = -1e30f, li0 = 0.f, li1 = 0.f;
    const int r_l = lane >> 2, cq = (lane & 3) * 2;

    for (int kb = 0; kb <= qb; kb++) {
        if (kb < qb) loadKV(kb + 1, (kb + 1) & 1);
        CP_COMMIT();
        CP_WAIT1();
        __syncthreads();
        uint32_t st = (uint32_t)(kb & 1) * 9216u;

        float sf[8][4];
#pragma unroll
        for (int nf = 0; nf < 8; nf++)
#pragma unroll
            for (int t = 0; t < 4; t++) sf[nf][t] = 0.f;
        {
            int b_row = lane & 7, b_kb = ((lane >> 3) & 1) * 16, nsel = (lane >> 4) & 1;
#pragma unroll
            for (int kk = 0; kk < 4; kk++) {
                uint32_t bh[8][2], bl[8][2];
#pragma unroll
                for (int g = 0; g < 2; g++)
#pragma unroll
                    for (int p = 0; p < 2; p++) {
                        uint32_t ad = sb + A_SKH + st
                            + (uint32_t)(((g*4 + p*2 + nsel)*8 + b_row)) * A_PITCH
                            + kk*32 + b_kb;
                        uint32_t r4[4];
                        ldm_x4(r4, ad);
                        int f = g*4 + p*2;
                        bh[f][0] = r4[0]; bh[f][1] = r4[1];
                        bh[f+1][0] = r4[2]; bh[f+1][1] = r4[3];
                        ldm_x4(r4, ad + (A_SKL - A_SKH));
                        bl[f][0] = r4[0]; bl[f][1] = r4[1];
                        bl[f+1][0] = r4[2]; bl[f+1][1] = r4[3];
                    }
#pragma unroll
                for (int nf = 0; nf < 8; nf++) mma_bf16(sf[nf], qfh[kk], bh[nf][0], bh[nf][1]);
#pragma unroll
                for (int nf = 0; nf < 8; nf++) mma_bf16(sf[nf], qfl[kk], bh[nf][0], bh[nf][1]);
#pragma unroll
                for (int nf = 0; nf < 8; nf++) mma_bf16(sf[nf], qfh[kk], bl[nf][0], bl[nf][1]);
            }
        }
        if (kb == qb) {
#pragma unroll
            for (int nf = 0; nf < 8; nf++)
#pragma unroll
                for (int hh = 0; hh < 2; hh++) {
                    int jl = nf*8 + cq + hh;
                    if (jl >= m0 + r_l)     sf[nf][hh]     = -1e30f;
                    if (jl >= m0 + r_l + 8) sf[nf][2 + hh] = -1e30f;
                }
        }
        float mx0 = -1e30f, mx1 = -1e30f;
#pragma unroll
        for (int nf = 0; nf < 8; nf++) {
            mx0 = fmaxf(mx0, fmaxf(sf[nf][0], sf[nf][1]));
            mx1 = fmaxf(mx1, fmaxf(sf[nf][2], sf[nf][3]));
        }
        mx0 = fmaxf(mx0, __shfl_xor_sync(0xffffffffu, mx0, 1));
        mx0 = fmaxf(mx0, __shfl_xor_sync(0xffffffffu, mx0, 2));
        mx1 = fmaxf(mx1, __shfl_xor_sync(0xffffffffu, mx1, 1));
        mx1 = fmaxf(mx1, __shfl_xor_sync(0xffffffffu, mx1, 2));
        float nm0 = fmaxf(mi0, mx0), nm1 = fmaxf(mi1, mx1);
        float sc0 = __expf(mi0 - nm0), sc1 = __expf(mi1 - nm1);
        float sum0 = 0.f, sum1 = 0.f;
#pragma unroll
        for (int nf = 0; nf < 8; nf++) {
            sf[nf][0] = (sf[nf][0] <= -1e29f) ? 0.f : __expf(sf[nf][0] - nm0); sum0 += sf[nf][0];
            sf[nf][1] = (sf[nf][1] <= -1e29f) ? 0.f : __expf(sf[nf][1] - nm0); sum0 += sf[nf][1];
            sf[nf][2] = (sf[nf][2] <= -1e29f) ? 0.f : __expf(sf[nf][2] - nm1); sum1 += sf[nf][2];
            sf[nf][3] = (sf[nf][3] <= -1e29f) ? 0.f : __expf(sf[nf][3] - nm1); sum1 += sf[nf][3];
        }
        sum0 += __shfl_xor_sync(0xffffffffu, sum0, 1);
        sum0 += __shfl_xor_sync(0xffffffffu, sum0, 2);
        sum1 += __shfl_xor_sync(0xffffffffu, sum1, 1);
        sum1 += __shfl_xor_sync(0xffffffffu, sum1, 2);
        li0 = li0 * sc0 + sum0; li1 = li1 * sc1 + sum1;
        mi0 = nm0; mi1 = nm1;
#pragma unroll
        for (int nf = 0; nf < 8; nf++) {
            oacc[nf][0] *= sc0; oacc[nf][1] *= sc0;
            oacc[nf][2] *= sc1; oacc[nf][3] *= sc1;
        }
        {
            int vrow = lane & 15, vcol = (lane >> 4) * 8;
#pragma unroll
            for (int ks = 0; ks < 4; ks++) {
                uint32_t ah[4], al[4];
                ah[0] = pack_bf16(sf[2*ks][0],   sf[2*ks][1]);
                ah[1] = pack_bf16(sf[2*ks][2],   sf[2*ks][3]);
                ah[2] = pack_bf16(sf[2*ks+1][0], sf[2*ks+1][1]);
                ah[3] = pack_bf16(sf[2*ks+1][2], sf[2*ks+1][3]);
                {
                    __nv_bfloat162* hp;
                    hp = (__nv_bfloat162*)&ah[0];
                    al[0] = pack_bf16(sf[2*ks][0] - __bfloat162float(hp->x),
                                      sf[2*ks][1] - __bfloat162float(hp->y));
                    hp = (__nv_bfloat162*)&ah[1];
                    al[1] = pack_bf16(sf[2*ks][2] - __bfloat162float(hp->x),
                                      sf[2*ks][3] - __bfloat162float(hp->y));
                    hp = (__nv_bfloat162*)&ah[2];
                    al[2] = pack_bf16(sf[2*ks+1][0] - __bfloat162float(hp->x),
                                      sf[2*ks+1][1] - __bfloat162float(hp->y));
                    hp = (__nv_bfloat162*)&ah[3];
                    al[3] = pack_bf16(sf[2*ks+1][2] - __bfloat162float(hp->x),
                                      sf[2*ks+1][3] - __bfloat162float(hp->y));
                }
#pragma unroll
                for (int df = 0; df < 4; df++) {
                    uint32_t vh4[4], vl4[4];
                    uint32_t ad = sb + A_SVH + st
                        + (uint32_t)(ks*16 + vrow) * A_PITCH + (df*16 + vcol) * 2;
                    ldm_x4_t(vh4, ad);
                    ldm_x4_t(vl4, ad + (A_SVL - A_SVH));
                    mma_bf16(oacc[2*df],     ah, vh4[0], vh4[1]);
                    mma_bf16(oacc[2*df + 1], ah, vh4[2], vh4[3]);
                    mma_bf16(oacc[2*df],     al, vh4[0], vh4[1]);
                    mma_bf16(oacc[2*df + 1], al, vh4[2], vh4[3]);
                    mma_bf16(oacc[2*df],     ah, vl4[0], vl4[1]);
                    mma_bf16(oacc[2*df + 1], ah, vl4[2], vl4[3]);
                }
            }
        }
        __syncthreads();
    }

    float* ost = (float*)(sm + A_SKH);
#pragma unroll
    for (int nf = 0; nf < 8; nf++) {
        int c = nf*8 + cq;
        ost[(m0 + r_l) * 72 + c]         = oacc[nf][0];
        ost[(m0 + r_l) * 72 + c + 1]     = oacc[nf][1];
        ost[(m0 + r_l + 8) * 72 + c]     = oacc[nf][2];
        ost[(m0 + r_l + 8) * 72 + c + 1] = oacc[nf][3];
    }
    if ((lane & 3) == 0) {
        ((float*)(sm + A_SMS))[m0 + r_l]     = mi0;
        ((float*)(sm + A_SMS))[m0 + r_l + 8] = mi1;
        ((float*)(sm + A_SLS))[m0 + r_l]     = li0;
        ((float*)(sm + A_SLS))[m0 + r_l + 8] = li1;
    }
    __syncthreads();

    {
        int m = tid >> 1, hf = tid & 1;
        int i = qb*64 + m;
        const float* qrow = Qf + (size_t)i * Dm + h*64;
        const float* krow = Kf + (size_t)(S + i) * Dm + h*64;
        float dot = 0.f;
#pragma unroll
        for (int d4 = 0; d4 < 16; d4++) {
            float4 a = ((const float4*)qrow)[d4];
            float4 b = ((const float4*)krow)[d4];
            dot += a.x*b.x + a.y*b.y + a.z*b.z + a.w*b.w;
        }
        float ssf = 0.125f * dot;
        float mi = ((float*)(sm + A_SMS))[m];
        float li = ((float*)(sm + A_SLS))[m];
        float nm = fmaxf(mi, ssf);
        float sc = __expf(mi - nm);
        float pp = __expf(ssf - nm);
        float inv = 1.f / (li * sc + pp);
        const float* vrow = Vf + (size_t)(S + i) * Dm + h*64 + hf*32;
        float* orow = ost + m*72 + hf*32;
        uint16_t hh[32], lv[32];
#pragma unroll
        for (int d = 0; d < 32; d++) {
            float val = (orow[d] * sc + pp * vrow[d]) * inv;
            bf16 hv = __float2bfloat16_rn(val);
            bf16 l2 = __float2bfloat16_rn(val - __bfloat162float(hv));
            hh[d] = *(uint16_t*)&hv; lv[d] = *(uint16_t*)&l2;
        }
        bf16* po = OH + (size_t)i * Dm + h*64 + hf*32;
        bf16* pl = OL + (size_t)i * Dm + h*64 + hf*32;
#pragma unroll
        for (int t = 0; t < 4; t++) {
            *(uint4*)(po + t*8) = *(uint4*)(hh + t*8);
            *(uint4*)(pl + t*8) = *(uint4*)(lv + t*8);
        }
    }
}

// ------------- SiLU * up + split -------------
__global__ __launch_bounds__(256) void silu_split_kernel(
    const float* __restrict__ G, const float* __restrict__ U,
    bf16* __restrict__ OH, bf16* __restrict__ OL, int n4)
{
    int idx = blockIdx.x * blockDim.x + threadIdx.x;
    if (idx >= n4) return;
    float4 g = ((const float4*)G)[idx];
    float4 u = ((const float4*)U)[idx];
    float v[4];
    v[0] = g.x / (1.f + __expf(-g.x)) * u.x;
    v[1] = g.y / (1.f + __expf(-g.y)) * u.y;
    v[2] = g.z / (1.f + __expf(-g.z)) * u.z;
    v[3] = g.w / (1.f + __expf(-g.w)) * u.w;
    uint16_t h4[4], l4[4];
#pragma unroll
    for (int i = 0; i < 4; i++) {
        bf16 hv = __float2bfloat16_rn(v[i]);
        bf16 lv = __float2bfloat16_rn(v[i] - __bfloat162float(hv));
        h4[i] = *(uint16_t*)&hv; l4[i] = *(uint16_t*)&lv;
    }
    ((uint2*)OH)[idx] = *(uint2*)h4;
    ((uint2*)OL)[idx] = *(uint2*)l4;
}

// ------------- launch -------------
extern "C" void kernel_launch(void* const* d_in, const int* in_sizes, int n_in,
                              void* d_out, int out_size)
{
    const float* hidden = (const float*)d_in[0];
    const float* memory = (const float*)d_in[1];
    const float* ln1w = (const float*)d_in[4];
    const float* ln1b = (const float*)d_in[5];
    const float* ln2w = (const float*)d_in[6];
    const float* ln2b = (const float*)d_in[7];
    const float* Wq = (const float*)d_in[8];
    const float* Wk = (const float*)d_in[9];
    const float* Wv = (const float*)d_in[10];
    const float* Wo = (const float*)d_in[11];
    const float* Wg = (const float*)d_in[12];
    const float* Wu = (const float*)d_in[13];
    const float* Wd = (const float*)d_in[14];
    float* out = (float*)d_out;

    void* p;
    cudaGetSymbolAddress(&p, g_xh);  bf16* xh = (bf16*)p;
    cudaGetSymbolAddress(&p, g_xl);  bf16* xl = (bf16*)p;
    cudaGetSymbolAddress(&p, g_q);   float* q = (float*)p;
    cudaGetSymbolAddress(&p, g_k);   float* k = (float*)p;
    cudaGetSymbolAddress(&p, g_v);   float* v = (float*)p;
    cudaGetSymbolAddress(&p, g_qh);  bf16* qh = (bf16*)p;
    cudaGetSymbolAddress(&p, g_ql);  bf16* ql = (bf16*)p;
    cudaGetSymbolAddress(&p, g_kh);  bf16* kh = (bf16*)p;
    cudaGetSymbolAddress(&p, g_kl);  bf16* kl = (bf16*)p;
    cudaGetSymbolAddress(&p, g_vh);  bf16* vh = (bf16*)p;
    cudaGetSymbolAddress(&p, g_vl);  bf16* vl = (bf16*)p;
    cudaGetSymbolAddress(&p, g_ah);  bf16* ah = (bf16*)p;
    cudaGetSymbolAddress(&p, g_al);  bf16* al = (bf16*)p;
    cudaGetSymbolAddress(&p, g_h);   float* hbuf = (float*)p;
    cudaGetSymbolAddress(&p, g_h2h); bf16* h2h = (bf16*)p;
    cudaGetSymbolAddress(&p, g_h2l); bf16* h2l = (bf16*)p;
    cudaGetSymbolAddress(&p, g_gr);  float* gr = (float*)p;
    cudaGetSymbolAddress(&p, g_ur);  float* ur = (float*)p;
    cudaGetSymbolAddress(&p, g_gh);  bf16* gh = (bf16*)p;
    cudaGetSymbolAddress(&p, g_gl);  bf16* gl = (bf16*)p;
    cudaGetSymbolAddress(&p, g_wqh); bf16* wqh = (bf16*)p;
    cudaGetSymbolAddress(&p, g_wql); bf16* wql = (bf16*)p;
    cudaGetSymbolAddress(&p, g_wkh); bf16* wkh = (bf16*)p;
    cudaGetSymbolAddress(&p, g_wkl); bf16* wkl = (bf16*)p;
    cudaGetSymbolAddress(&p, g_wvh); bf16* wvh = (bf16*)p;
    cudaGetSymbolAddress(&p, g_wvl); bf16* wvl = (bf16*)p;
    cudaGetSymbolAddress(&p, g_woh); bf16* woh = (bf16*)p;
    cudaGetSymbolAddress(&p, g_wol); bf16* wol = (bf16*)p;
    cudaGetSymbolAddress(&p, g_wgh); bf16* wgh = (bf16*)p;
    cudaGetSymbolAddress(&p, g_wgl); bf16* wgl = (bf16*)p;
    cudaGetSymbolAddress(&p, g_wuh); bf16* wuh = (bf16*)p;
    cudaGetSymbolAddress(&p, g_wul); bf16* wul = (bf16*)p;
    cudaGetSymbolAddress(&p, g_wdh); bf16* wdh = (bf16*)p;
    cudaGetSymbolAddress(&p, g_wdl); bf16* wdl = (bf16*)p;

    cudaFuncSetAttribute(gemm3_bf16, cudaFuncAttributeMaxDynamicSharedMemorySize, G_DSMEM);
    cudaFuncSetAttribute(attn_mma_kernel, cudaFuncAttributeMaxDynamicSharedMemorySize, A_DSMEM);

    ln_split_kernel<<<S, 256>>>(memory, ln1w, ln1b, xh, xl);
    ln_split_kernel<<<S, 256>>>(hidden, ln1w, ln1b, xh + (size_t)S * Dm, xl + (size_t)S * Dm);

    int nDD = Dm * Dm / 4, nFD = FF * Dm / 4;
    split_kernel<<<nDD / 256, 256>>>(Wq, wqh, wql, nDD);
    split_kernel<<<nDD / 256, 256>>>(Wk, wkh, wkl, nDD);
    split_kernel<<<nDD / 256, 256>>>(Wv, wvh, wvl, nDD);
    split_kernel<<<nDD / 256, 256>>>(Wo, woh, wol, nDD);
    split_kernel<<<nFD / 256, 256>>>(Wg, wgh, wgl, nFD);
    split_kernel<<<nFD / 256, 256>>>(Wu, wuh, wul, nFD);
    split_kernel<<<nFD / 256, 256>>>(Wd, wdh, wdl, nFD);

    {
        dim3 gKV(Dm / 128, L / 128);
        gemm3_bf16<<<gKV, 256, G_DSMEM>>>(xh, xl, wkh, wkl, nullptr, k, L, Dm, Dm);
        gemm3_bf16<<<gKV, 256, G_DSMEM>>>(xh, xl, wvh, wvl, nullptr, v, L, Dm, Dm);
        dim3 gQ(Dm / 128, S / 128);
        gemm3_bf16<<<gQ, 256, G_DSMEM>>>(xh + (size_t)S * Dm, xl + (size_t)S * Dm,
                                         wqh, wql, nullptr, q, S, Dm, Dm);
    }

    rope_split_kernel<<<S, 256>>>(q, qh, ql, 0.125f);
    rope_split_kernel<<<L, 256>>>(k, kh, kl, 1.0f);
    split_kernel<<<L * Dm / 1024, 256>>>(v, vh, vl, L * Dm / 4);

    {
        dim3 g(S / 64, NH);
        attn_mma_kernel<<<g, 128, A_DSMEM>>>(qh, ql, kh, kl, vh, vl, q, k, v, ah, al);
    }

    {
        dim3 g(Dm / 128, S / 128);
        gemm3_bf16<<<g, 256, G_DSMEM>>>(ah, al, woh, wol, hidden, hbuf, S, Dm, Dm);
    }
    ln_split_kernel<<<S, 256>>>(hbuf, ln2w, ln2b, h2h, h2l);
    {
        dim3 g(FF / 128, S / 128);
        gemm3_bf16<<<g, 256, G_DSMEM>>>(h2h, h2l, wgh, wgl, nullptr, gr, S, FF, Dm);
        gemm3_bf16<<<g, 256, G_DSMEM>>>(h2h, h2l, wuh, wul, nullptr, ur, S, FF, Dm);
    }
    silu_split_kernel<<<S * FF / 1024, 256>>>(gr, ur, gh, gl, S * FF / 4);
    {
        dim3 g(Dm / 128, S / 128);
        gemm3_bf16<<<g, 256, G_DSMEM>>>(gh, gl, wdh, wdl, hbuf, out, S, Dm, FF);
    }
}

// round 6
// speedup vs baseline: 1.6154x; 1.0037x over previous
#include <cuda_runtime.h>
#include <cuda_bf16.h>
#include <cstdint>

#define S    2048
#define Dm   2048
#define FF   8192
#define NH   32
#define HD   64
#define L    4096

typedef __nv_bfloat16 bf16;

__device__ __forceinline__ uint32_t smem_u32(const void* p) {
    uint32_t a;
    asm("{ .reg .u64 t; cvta.to.shared.u64 t, %1; cvt.u32.u64 %0, t; }" : "=r"(a) : "l"(p));
    return a;
}
__device__ __forceinline__ void ldm_x4(uint32_t* r, uint32_t a) {
    asm volatile("ldmatrix.sync.aligned.m8n8.x4.shared.b16 {%0,%1,%2,%3}, [%4];"
        : "=r"(r[0]), "=r"(r[1]), "=r"(r[2]), "=r"(r[3]) : "r"(a));
}
__device__ __forceinline__ void ldm_x4_t(uint32_t* r, uint32_t a) {
    asm volatile("ldmatrix.sync.aligned.m8n8.x4.trans.shared.b16 {%0,%1,%2,%3}, [%4];"
        : "=r"(r[0]), "=r"(r[1]), "=r"(r[2]), "=r"(r[3]) : "r"(a));
}
__device__ __forceinline__ void mma_bf16(float* c, const uint32_t* a, uint32_t b0, uint32_t b1) {
    asm volatile("mma.sync.aligned.m16n8k16.row.col.f32.bf16.bf16.f32 "
        "{%0,%1,%2,%3}, {%4,%5,%6,%7}, {%8,%9}, {%0,%1,%2,%3};"
        : "+f"(c[0]), "+f"(c[1]), "+f"(c[2]), "+f"(c[3])
        : "r"(a[0]), "r"(a[1]), "r"(a[2]), "r"(a[3]), "r"(b0), "r"(b1));
}
__device__ __forceinline__ uint32_t pack_bf16(float a, float b) {
    __nv_bfloat162 t; t.x = __float2bfloat16_rn(a); t.y = __float2bfloat16_rn(b);
    return *(uint32_t*)&t;
}
__device__ __forceinline__ void split2(float a, float b, uint32_t& h, uint32_t& l) {
    bf16 ha = __float2bfloat16_rn(a), hb = __float2bfloat16_rn(b);
    __nv_bfloat162 hv; hv.x = ha; hv.y = hb;
    h = *(uint32_t*)&hv;
    l = pack_bf16(a - __bfloat162float(ha), b - __bfloat162float(hb));
}
#define CP_ASYNC16(dst, src) \
    asm volatile("cp.async.cg.shared.global [%0], [%1], 16;" :: "r"(dst), "l"(src))
#define CP_COMMIT() asm volatile("cp.async.commit_group;" ::: "memory")
#define CP_WAIT1()  asm volatile("cp.async.wait_group 1;" ::: "memory")

// ------------- scratch -------------
__device__ bf16  g_xh [L * Dm]; __device__ bf16 g_xl [L * Dm];
__device__ bf16  g_qh [S * Dm]; __device__ bf16 g_ql [S * Dm];
__device__ bf16  g_kh [L * Dm]; __device__ bf16 g_kl [L * Dm];
__device__ bf16  g_vh [L * Dm]; __device__ bf16 g_vl [L * Dm];
__device__ bf16  g_ah [S * Dm]; __device__ bf16 g_al [S * Dm];
__device__ float g_h  [S * Dm];
__device__ bf16  g_h2h[S * Dm]; __device__ bf16 g_h2l[S * Dm];
__device__ float g_gr [S * FF];
__device__ bf16  g_gh [S * FF]; __device__ bf16 g_gl [S * FF];
__device__ bf16  g_wqh[Dm * Dm]; __device__ bf16 g_wql[Dm * Dm];
__device__ bf16  g_wkh[Dm * Dm]; __device__ bf16 g_wkl[Dm * Dm];
__device__ bf16  g_wvh[Dm * Dm]; __device__ bf16 g_wvl[Dm * Dm];
__device__ bf16  g_woh[Dm * Dm]; __device__ bf16 g_wol[Dm * Dm];
__device__ bf16  g_wgh[FF * Dm]; __device__ bf16 g_wgl[FF * Dm];
__device__ bf16  g_wuh[FF * Dm]; __device__ bf16 g_wul[FF * Dm];
__device__ bf16  g_wdh[Dm * FF]; __device__ bf16 g_wdl[Dm * FF];

// ------------- hi/lo split -------------
__global__ __launch_bounds__(256) void split_kernel(
    const float* __restrict__ X, bf16* __restrict__ H, bf16* __restrict__ Lo, int n4)
{
    int i = blockIdx.x * blockDim.x + threadIdx.x;
    if (i >= n4) return;
    float4 x = ((const float4*)X)[i];
    uint2 hu, lu;
    split2(x.x, x.y, hu.x, lu.x);
    split2(x.z, x.w, hu.y, lu.y);
    ((uint2*)H)[i] = hu;
    ((uint2*)Lo)[i] = lu;
}

// ------------- LayerNorm + split -------------
__global__ __launch_bounds__(256) void ln_split_kernel(
    const float* __restrict__ X, const float* __restrict__ w,
    const float* __restrict__ b, bf16* __restrict__ OH, bf16* __restrict__ OL)
{
    int row = blockIdx.x, tid = threadIdx.x;
    const float* xr = X + (size_t)row * Dm;
    float4 a = ((const float4*)xr)[tid * 2];
    float4 c = ((const float4*)xr)[tid * 2 + 1];
    float s  = a.x + a.y + a.z + a.w + c.x + c.y + c.z + c.w;
    float ss = a.x*a.x + a.y*a.y + a.z*a.z + a.w*a.w
             + c.x*c.x + c.y*c.y + c.z*c.z + c.w*c.w;
#pragma unroll
    for (int o = 16; o; o >>= 1) {
        s  += __shfl_xor_sync(0xffffffffu, s,  o);
        ss += __shfl_xor_sync(0xffffffffu, ss, o);
    }
    __shared__ float bs[8], bss[8];
    if ((tid & 31) == 0) { bs[tid >> 5] = s; bss[tid >> 5] = ss; }
    __syncthreads();
    float ts = 0.f, tss = 0.f;
#pragma unroll
    for (int i = 0; i < 8; i++) { ts += bs[i]; tss += bss[i]; }
    float mean = ts * (1.f / Dm);
    float inv  = rsqrtf(tss * (1.f / Dm) - mean * mean + 1e-5f);
    int d = tid * 8;
    float4 w0 = ((const float4*)w)[tid*2], w1 = ((const float4*)w)[tid*2+1];
    float4 b0 = ((const float4*)b)[tid*2], b1 = ((const float4*)b)[tid*2+1];
    float v8[8];
    v8[0]=(a.x-mean)*inv*w0.x+b0.x; v8[1]=(a.y-mean)*inv*w0.y+b0.y;
    v8[2]=(a.z-mean)*inv*w0.z+b0.z; v8[3]=(a.w-mean)*inv*w0.w+b0.w;
    v8[4]=(c.x-mean)*inv*w1.x+b1.x; v8[5]=(c.y-mean)*inv*w1.y+b1.y;
    v8[6]=(c.z-mean)*inv*w1.z+b1.z; v8[7]=(c.w-mean)*inv*w1.w+b1.w;
    uint2 hu0, lu0, hu1, lu1;
    split2(v8[0], v8[1], hu0.x, lu0.x); split2(v8[2], v8[3], hu0.y, lu0.y);
    split2(v8[4], v8[5], hu1.x, lu1.x); split2(v8[6], v8[7], hu1.y, lu1.y);
    *(uint2*)(OH + (size_t)row * Dm + d)     = hu0;
    *(uint2*)(OH + (size_t)row * Dm + d + 4) = hu1;
    *(uint2*)(OL + (size_t)row * Dm + d)     = lu0;
    *(uint2*)(OL + (size_t)row * Dm + d + 4) = lu1;
}

// ------------- GEMM: 3-term bf16, fused epilogues -------------
// MODE 0: C fp32 = acc (+Res)
// MODE 1: rope(first 16 dims/head) + scale -> hi/lo bf16 (N tile aligned to heads)
// MODE 2: plain hi/lo bf16
// MODE 3: silu(Res)*acc -> hi/lo bf16
#define GBK 32
#define G_ROWB 80
#define G_TILEB (128 * G_ROWB)
#define G_STAGEB (4 * G_TILEB)
#define G_DSMEM (2 * G_STAGEB)

template<int MODE>
__global__ __launch_bounds__(256, 2)
void gemm3(const bf16* __restrict__ Ahi, const bf16* __restrict__ Alo,
           const bf16* __restrict__ Bhi, const bf16* __restrict__ Blo,
           const float* __restrict__ Res, float* __restrict__ C,
           bf16* __restrict__ OH, bf16* __restrict__ OL, float scale,
           int M, int N, int K)
{
    extern __shared__ char smem[];
    uint32_t sb = smem_u32(smem);
    int tid  = threadIdx.x, wid = tid >> 5, lane = tid & 31;
    int wm = wid & 3, wn = wid >> 2;
    int bm = blockIdx.y * 128, bn = blockIdx.x * 128;

    auto loadChunk = [&](int stg, int k0) {
        uint32_t base = sb + stg * G_STAGEB;
#pragma unroll
        for (int h = 0; h < 2; h++) {
            int cid = tid * 2 + h;
            int r = cid >> 2, c = cid & 3;
            uint32_t doff = r * G_ROWB + c * 16;
            size_t soff = (size_t)r * K + k0 + c * 8;
            CP_ASYNC16(base + doff,             Ahi + (size_t)bm * K + soff);
            CP_ASYNC16(base + G_TILEB + doff,   Alo + (size_t)bm * K + soff);
            CP_ASYNC16(base + 2*G_TILEB + doff, Bhi + (size_t)bn * K + soff);
            CP_ASYNC16(base + 3*G_TILEB + doff, Blo + (size_t)bn * K + soff);
        }
    };

    float acc[2][8][4];
#pragma unroll
    for (int i = 0; i < 2; i++)
#pragma unroll
        for (int j = 0; j < 8; j++)
#pragma unroll
            for (int t = 0; t < 4; t++) acc[i][j][t] = 0.f;

    int a_row = lane & 15;
    int b_row = lane & 7;
    int b_kb  = ((lane >> 3) & 1) * 16;
    int NKC = K / GBK;
    loadChunk(0, 0);    CP_COMMIT();
    loadChunk(1, GBK);  CP_COMMIT();

    for (int k = 0; k < NKC; k++) {
        int stg = k & 1;
        CP_WAIT1();
        __syncthreads();
        uint32_t base = sb + stg * G_STAGEB;
#pragma unroll
        for (int kk = 0; kk < 2; kk++) {
            uint32_t Ah[2][4], Al[2][4];
#pragma unroll
            for (int mf = 0; mf < 2; mf++) {
                uint32_t addr = base + (uint32_t)((wm*32 + mf*16 + a_row) * G_ROWB)
                              + kk*32 + (lane >> 4) * 16;
                ldm_x4(Ah[mf], addr);
                ldm_x4(Al[mf], addr + G_TILEB);
            }
#pragma unroll
            for (int g = 0; g < 2; g++) {
                uint32_t Bh[4][2], Bl[4][2];
#pragma unroll
                for (int p = 0; p < 2; p++) {
                    uint32_t addr = base + 2*G_TILEB
                        + (uint32_t)((wn*64 + (g*4 + p*2 + ((lane>>4)&1))*8 + b_row) * G_ROWB)
                        + kk*32 + b_kb;
                    uint32_t r4[4];
                    ldm_x4(r4, addr);
                    Bh[p*2][0] = r4[0]; Bh[p*2][1] = r4[1];
                    Bh[p*2+1][0] = r4[2]; Bh[p*2+1][1] = r4[3];
                    ldm_x4(r4, addr + G_TILEB);
                    Bl[p*2][0] = r4[0]; Bl[p*2][1] = r4[1];
                    Bl[p*2+1][0] = r4[2]; Bl[p*2+1][1] = r4[3];
                }
#pragma unroll
                for (int mf = 0; mf < 2; mf++)
#pragma unroll
                    for (int nf = 0; nf < 4; nf++) {
                        float* c = acc[mf][g*4 + nf];
                        mma_bf16(c, Ah[mf], Bh[nf][0], Bh[nf][1]);
                        mma_bf16(c, Al[mf], Bh[nf][0], Bh[nf][1]);
                        mma_bf16(c, Ah[mf], Bl[nf][0], Bl[nf][1]);
                    }
            }
        }
        __syncthreads();
        if (k + 2 < NKC) loadChunk(stg, (k + 2) * GBK);
        CP_COMMIT();
    }

    int rr = lane >> 2, cp = lane & 3;
    if (MODE == 1) {
        // rope: dims d=cp*2+{0,1} (frag nf=0) pair with d+8 (frag nf=1); same thread.
#pragma unroll
        for (int mf = 0; mf < 2; mf++)
#pragma unroll
            for (int j = 0; j < 4; j++) {
                int d = cp * 2 + (j & 1);
                int row = bm + wm*32 + mf*16 + rr + ((j >> 1) * 8);
                int pos = row & (S - 1);
                float invf = __powf(10000.f, -(float)d * 0.125f);
                float sn, cs; sincosf(pos * invf, &sn, &cs);
                float x1 = acc[mf][0][j], x2 = acc[mf][1][j];
                acc[mf][0][j] = x1 * cs - x2 * sn;
                acc[mf][1][j] = x2 * cs + x1 * sn;
            }
    }
#pragma unroll
    for (int mf = 0; mf < 2; mf++) {
        int row0 = bm + wm*32 + mf*16 + rr;
#pragma unroll
        for (int nf = 0; nf < 8; nf++) {
            int col = bn + wn*64 + nf*8 + cp*2;
            float* c = acc[mf][nf];
            size_t o0 = (size_t)row0 * N + col;
            size_t o1 = (size_t)(row0 + 8) * N + col;
            if (MODE == 0) {
                float2 v0 = make_float2(c[0], c[1]);
                float2 v1 = make_float2(c[2], c[3]);
                if (Res) {
                    float2 e0 = *(const float2*)(Res + o0);
                    float2 e1 = *(const float2*)(Res + o1);
                    v0.x += e0.x; v0.y += e0.y; v1.x += e1.x; v1.y += e1.y;
                }
                *(float2*)(C + o0) = v0;
                *(float2*)(C + o1) = v1;
            } else {
                float v0 = c[0], v1 = c[1], v2 = c[2], v3 = c[3];
                if (MODE == 3) {
                    float2 g0 = *(const float2*)(Res + o0);
                    float2 g1 = *(const float2*)(Res + o1);
                    v0 *= g0.x / (1.f + __expf(-g0.x));
                    v1 *= g0.y / (1.f + __expf(-g0.y));
                    v2 *= g1.x / (1.f + __expf(-g1.x));
                    v3 *= g1.y / (1.f + __expf(-g1.y));
                } else {
                    v0 *= scale; v1 *= scale; v2 *= scale; v3 *= scale;
                }
                uint32_t h0, l0, h1, l1;
                split2(v0, v1, h0, l0);
                split2(v2, v3, h1, l1);
                *(uint32_t*)(OH + o0) = h0;
                *(uint32_t*)(OL + o0) = l0;
                *(uint32_t*)(OH + o1) = h1;
                *(uint32_t*)(OL + o1) = l1;
            }
        }
    }
}

// ------------- flash attention via mma.sync -------------
#define A_PITCH 144
#define A_SQH 0u
#define A_SQL 9216u
#define A_SKH 18432u
#define A_SKL 36864u
#define A_SVH 55296u
#define A_SVL 73728u
#define A_SMS 92160u
#define A_SLS 92416u
#define A_DSMEM 92672

__global__ __launch_bounds__(128)
void attn_mma_kernel(const bf16* __restrict__ Qh, const bf16* __restrict__ Ql,
                     const bf16* __restrict__ Kh, const bf16* __restrict__ Kl,
                     const bf16* __restrict__ Vh, const bf16* __restrict__ Vl,
                     bf16* __restrict__ OH, bf16* __restrict__ OL)
{
    extern __shared__ char sm[];
    uint32_t sb = smem_u32(sm);
    const int qb = blockIdx.x, h = blockIdx.y;
    const int tid = threadIdx.x, wid = tid >> 5, lane = tid & 31;
    const int m0 = wid * 16;

#pragma unroll
    for (int j = 0; j < 4; j++) {
        int idx = tid + j * 128;
        int row = idx >> 3, c = idx & 7;
        size_t g = (size_t)(qb*64 + row) * Dm + h*64 + c*8;
        *(uint4*)(sm + A_SQH + row*A_PITCH + c*16) = *(const uint4*)(Qh + g);
        *(uint4*)(sm + A_SQL + row*A_PITCH + c*16) = *(const uint4*)(Ql + g);
    }
    auto loadKV = [&](int kb, int st) {
        uint32_t o = (uint32_t)st * 9216u;
#pragma unroll
        for (int j = 0; j < 4; j++) {
            int idx = tid + j * 128;
            int row = idx >> 3, c = idx & 7;
            size_t g = (size_t)(kb*64 + row) * Dm + h*64 + c*8;
            uint32_t d = o + row*A_PITCH + c*16;
            CP_ASYNC16(sb + A_SKH + d, Kh + g);
            CP_ASYNC16(sb + A_SKL + d, Kl + g);
            CP_ASYNC16(sb + A_SVH + d, Vh + g);
            CP_ASYNC16(sb + A_SVL + d, Vl + g);
        }
    };
    loadKV(0, 0); CP_COMMIT();
    __syncthreads();

    uint32_t qfh[4][4], qfl[4][4];
    {
        int a_row = lane & 15, koff = (lane >> 4) * 16;
#pragma unroll
        for (int kk = 0; kk < 4; kk++) {
            uint32_t ad = sb + A_SQH + (uint32_t)(m0 + a_row) * A_PITCH + kk*32 + koff;
            ldm_x4(qfh[kk], ad);
            ldm_x4(qfl[kk], ad + 9216u);
        }
    }

    float oacc[8][4];
#pragma unroll
    for (int nf = 0; nf < 8; nf++)
#pragma unroll
        for (int t = 0; t < 4; t++) oacc[nf][t] = 0.f;
    float mi0 = -1e30f, mi1 = -1e30f, li0 = 0.f, li1 = 0.f;
    const int r_l = lane >> 2, cq = (lane & 3) * 2;

    for (int kb = 0; kb <= qb; kb++) {
        if (kb < qb) loadKV(kb + 1, (kb + 1) & 1);
        CP_COMMIT();
        CP_WAIT1();
        __syncthreads();
        uint32_t st = (uint32_t)(kb & 1) * 9216u;

        float sf[8][4];
#pragma unroll
        for (int nf = 0; nf < 8; nf++)
#pragma unroll
            for (int t = 0; t < 4; t++) sf[nf][t] = 0.f;
        {
            int b_row = lane & 7, b_kb = ((lane >> 3) & 1) * 16, nsel = (lane >> 4) & 1;
#pragma unroll
            for (int kk = 0; kk < 4; kk++) {
                uint32_t bh[8][2], bl[8][2];
#pragma unroll
                for (int g = 0; g < 2; g++)
#pragma unroll
                    for (int p = 0; p < 2; p++) {
                        uint32_t ad = sb + A_SKH + st
                            + (uint32_t)(((g*4 + p*2 + nsel)*8 + b_row)) * A_PITCH
                            + kk*32 + b_kb;
                        uint32_t r4[4];
                        ldm_x4(r4, ad);
                        int f = g*4 + p*2;
                        bh[f][0] = r4[0]; bh[f][1] = r4[1];
                        bh[f+1][0] = r4[2]; bh[f+1][1] = r4[3];
                        ldm_x4(r4, ad + (A_SKL - A_SKH));
                        bl[f][0] = r4[0]; bl[f][1] = r4[1];
                        bl[f+1][0] = r4[2]; bl[f+1][1] = r4[3];
                    }
#pragma unroll
                for (int nf = 0; nf < 8; nf++) mma_bf16(sf[nf], qfh[kk], bh[nf][0], bh[nf][1]);
#pragma unroll
                for (int nf = 0; nf < 8; nf++) mma_bf16(sf[nf], qfl[kk], bh[nf][0], bh[nf][1]);
#pragma unroll
                for (int nf = 0; nf < 8; nf++) mma_bf16(sf[nf], qfh[kk], bl[nf][0], bl[nf][1]);
            }
        }
        if (kb == qb) {
#pragma unroll
            for (int nf = 0; nf < 8; nf++)
#pragma unroll
                for (int hh = 0; hh < 2; hh++) {
                    int jl = nf*8 + cq + hh;
                    if (jl >= m0 + r_l)     sf[nf][hh]     = -1e30f;
                    if (jl >= m0 + r_l + 8) sf[nf][2 + hh] = -1e30f;
                }
        }
        float mx0 = -1e30f, mx1 = -1e30f;
#pragma unroll
        for (int nf = 0; nf < 8; nf++) {
            mx0 = fmaxf(mx0, fmaxf(sf[nf][0], sf[nf][1]));
            mx1 = fmaxf(mx1, fmaxf(sf[nf][2], sf[nf][3]));
        }
        mx0 = fmaxf(mx0, __shfl_xor_sync(0xffffffffu, mx0, 1));
        mx0 = fmaxf(mx0, __shfl_xor_sync(0xffffffffu, mx0, 2));
        mx1 = fmaxf(mx1, __shfl_xor_sync(0xffffffffu, mx1, 1));
        mx1 = fmaxf(mx1, __shfl_xor_sync(0xffffffffu, mx1, 2));
        float nm0 = fmaxf(mi0, mx0), nm1 = fmaxf(mi1, mx1);
        float sc0 = __expf(mi0 - nm0), sc1 = __expf(mi1 - nm1);
        float sum0 = 0.f, sum1 = 0.f;
#pragma unroll
        for (int nf = 0; nf < 8; nf++) {
            sf[nf][0] = (sf[nf][0] <= -1e29f) ? 0.f : __expf(sf[nf][0] - nm0); sum0 += sf[nf][0];
            sf[nf][1] = (sf[nf][1] <= -1e29f) ? 0.f : __expf(sf[nf][1] - nm0); sum0 += sf[nf][1];
            sf[nf][2] = (sf[nf][2] <= -1e29f) ? 0.f : __expf(sf[nf][2] - nm1); sum1 += sf[nf][2];
            sf[nf][3] = (sf[nf][3] <= -1e29f) ? 0.f : __expf(sf[nf][3] - nm1); sum1 += sf[nf][3];
        }
        sum0 += __shfl_xor_sync(0xffffffffu, sum0, 1);
        sum0 += __shfl_xor_sync(0xffffffffu, sum0, 2);
        sum1 += __shfl_xor_sync(0xffffffffu, sum1, 1);
        sum1 += __shfl_xor_sync(0xffffffffu, sum1, 2);
        li0 = li0 * sc0 + sum0; li1 = li1 * sc1 + sum1;
        mi0 = nm0; mi1 = nm1;
#pragma unroll
        for (int nf = 0; nf < 8; nf++) {
            oacc[nf][0] *= sc0; oacc[nf][1] *= sc0;
            oacc[nf][2] *= sc1; oacc[nf][3] *= sc1;
        }
        {
            int vrow = lane & 15, vcol = (lane >> 4) * 8;
#pragma unroll
            for (int ks = 0; ks < 4; ks++) {
                uint32_t ah[4], al[4];
                split2(sf[2*ks][0],   sf[2*ks][1],   ah[0], al[0]);
                split2(sf[2*ks][2],   sf[2*ks][3],   ah[1], al[1]);
                split2(sf[2*ks+1][0], sf[2*ks+1][1], ah[2], al[2]);
                split2(sf[2*ks+1][2], sf[2*ks+1][3], ah[3], al[3]);
#pragma unroll
                for (int df = 0; df < 4; df++) {
                    uint32_t vh4[4], vl4[4];
                    uint32_t ad = sb + A_SVH + st
                        + (uint32_t)(ks*16 + vrow) * A_PITCH + (df*16 + vcol) * 2;
                    ldm_x4_t(vh4, ad);
                    ldm_x4_t(vl4, ad + (A_SVL - A_SVH));
                    mma_bf16(oacc[2*df],     ah, vh4[0], vh4[1]);
                    mma_bf16(oacc[2*df + 1], ah, vh4[2], vh4[3]);
                    mma_bf16(oacc[2*df],     al, vh4[0], vh4[1]);
                    mma_bf16(oacc[2*df + 1], al, vh4[2], vh4[3]);
                    mma_bf16(oacc[2*df],     ah, vl4[0], vl4[1]);
                    mma_bf16(oacc[2*df + 1], ah, vl4[2], vl4[3]);
                }
            }
        }
        __syncthreads();
    }

    float* ost = (float*)(sm + A_SKH);
#pragma unroll
    for (int nf = 0; nf < 8; nf++) {
        int c = nf*8 + cq;
        ost[(m0 + r_l) * 72 + c]         = oacc[nf][0];
        ost[(m0 + r_l) * 72 + c + 1]     = oacc[nf][1];
        ost[(m0 + r_l + 8) * 72 + c]     = oacc[nf][2];
        ost[(m0 + r_l + 8) * 72 + c + 1] = oacc[nf][3];
    }
    if ((lane & 3) == 0) {
        ((float*)(sm + A_SMS))[m0 + r_l]     = mi0;
        ((float*)(sm + A_SMS))[m0 + r_l + 8] = mi1;
        ((float*)(sm + A_SLS))[m0 + r_l]     = li0;
        ((float*)(sm + A_SLS))[m0 + r_l + 8] = li1;
    }
    __syncthreads();

    {
        int m = tid >> 1, hf = tid & 1;
        int i = qb*64 + m;
        // self-token score: q (pre-scaled by 1/8) . k[S+i], fp32 via hi+lo
        const __nv_bfloat162* q2h = (const __nv_bfloat162*)(Qh + (size_t)i * Dm + h*64);
        const __nv_bfloat162* q2l = (const __nv_bfloat162*)(Ql + (size_t)i * Dm + h*64);
        const __nv_bfloat162* k2h = (const __nv_bfloat162*)(Kh + (size_t)(S + i) * Dm + h*64);
        const __nv_bfloat162* k2l = (const __nv_bfloat162*)(Kl + (size_t)(S + i) * Dm + h*64);
        float dot = 0.f;
#pragma unroll
        for (int t = 0; t < 32; t++) {
            float2 qa = __bfloat1622float2(q2h[t]);
            float2 qb2 = __bfloat1622float2(q2l[t]);
            float2 ka = __bfloat1622float2(k2h[t]);
            float2 kb = __bfloat1622float2(k2l[t]);
            dot += (qa.x + qb2.x) * (ka.x + kb.x) + (qa.y + qb2.y) * (ka.y + kb.y);
        }
        float ssf = dot;
        float mi = ((float*)(sm + A_SMS))[m];
        float li = ((float*)(sm + A_SLS))[m];
        float nm = fmaxf(mi, ssf);
        float sc = __expf(mi - nm);
        float pp = __expf(ssf - nm);
        float inv = 1.f / (li * sc + pp);
        const __nv_bfloat162* v2h = (const __nv_bfloat162*)(Vh + (size_t)(S + i) * Dm + h*64 + hf*32);
        const __nv_bfloat162* v2l = (const __nv_bfloat162*)(Vl + (size_t)(S + i) * Dm + h*64 + hf*32);
        float* orow = ost + m*72 + hf*32;
        uint32_t hh[8], ll[8];
#pragma unroll
        for (int t = 0; t < 16; t++) {
            float2 va = __bfloat1622float2(v2h[t]);
            float2 vb = __bfloat1622float2(v2l[t]);
            float val0 = (orow[t*2]   * sc + pp * (va.x + vb.x)) * inv;
            float val1 = (orow[t*2+1] * sc + pp * (va.y + vb.y)) * inv;
            split2(val0, val1, hh[t & 7], ll[t & 7]);
            if ((t & 7) == 7) {
                int t8 = t >> 3;
                *(uint4*)(OH + (size_t)i * Dm + h*64 + hf*32 + t8*16)     = *(uint4*)(hh);
                *(uint4*)(OH + (size_t)i * Dm + h*64 + hf*32 + t8*16 + 8) = *(uint4*)(hh + 4);
                *(uint4*)(OL + (size_t)i * Dm + h*64 + hf*32 + t8*16)     = *(uint4*)(ll);
                *(uint4*)(OL + (size_t)i * Dm + h*64 + hf*32 + t8*16 + 8) = *(uint4*)(ll + 4);
            }
        }
    }
}

// ------------- launch -------------
extern "C" void kernel_launch(void* const* d_in, const int* in_sizes, int n_in,
                              void* d_out, int out_size)
{
    const float* hidden = (const float*)d_in[0];
    const float* memory = (const float*)d_in[1];
    const float* ln1w = (const float*)d_in[4];
    const float* ln1b = (const float*)d_in[5];
    const float* ln2w = (const float*)d_in[6];
    const float* ln2b = (const float*)d_in[7];
    const float* Wq = (const float*)d_in[8];
    const float* Wk = (const float*)d_in[9];
    const float* Wv = (const float*)d_in[10];
    const float* Wo = (const float*)d_in[11];
    const float* Wg = (const float*)d_in[12];
    const float* Wu = (const float*)d_in[13];
    const float* Wd = (const float*)d_in[14];
    float* out = (float*)d_out;

    void* p;
    cudaGetSymbolAddress(&p, g_xh);  bf16* xh = (bf16*)p;
    cudaGetSymbolAddress(&p, g_xl);  bf16* xl = (bf16*)p;
    cudaGetSymbolAddress(&p, g_qh);  bf16* qh = (bf16*)p;
    cudaGetSymbolAddress(&p, g_ql);  bf16* ql = (bf16*)p;
    cudaGetSymbolAddress(&p, g_kh);  bf16* kh = (bf16*)p;
    cudaGetSymbolAddress(&p, g_kl);  bf16* kl = (bf16*)p;
    cudaGetSymbolAddress(&p, g_vh);  bf16* vh = (bf16*)p;
    cudaGetSymbolAddress(&p, g_vl);  bf16* vl = (bf16*)p;
    cudaGetSymbolAddress(&p, g_ah);  bf16* ah = (bf16*)p;
    cudaGetSymbolAddress(&p, g_al);  bf16* al = (bf16*)p;
    cudaGetSymbolAddress(&p, g_h);   float* hbuf = (float*)p;
    cudaGetSymbolAddress(&p, g_h2h); bf16* h2h = (bf16*)p;
    cudaGetSymbolAddress(&p, g_h2l); bf16* h2l = (bf16*)p;
    cudaGetSymbolAddress(&p, g_gr);  float* gr = (float*)p;
    cudaGetSymbolAddress(&p, g_gh);  bf16* gh = (bf16*)p;
    cudaGetSymbolAddress(&p, g_gl);  bf16* gl = (bf16*)p;
    cudaGetSymbolAddress(&p, g_wqh); bf16* wqh = (bf16*)p;
    cudaGetSymbolAddress(&p, g_wql); bf16* wql = (bf16*)p;
    cudaGetSymbolAddress(&p, g_wkh); bf16* wkh = (bf16*)p;
    cudaGetSymbolAddress(&p, g_wkl); bf16* wkl = (bf16*)p;
    cudaGetSymbolAddress(&p, g_wvh); bf16* wvh = (bf16*)p;
    cudaGetSymbolAddress(&p, g_wvl); bf16* wvl = (bf16*)p;
    cudaGetSymbolAddress(&p, g_woh); bf16* woh = (bf16*)p;
    cudaGetSymbolAddress(&p, g_wol); bf16* wol = (bf16*)p;
    cudaGetSymbolAddress(&p, g_wgh); bf16* wgh = (bf16*)p;
    cudaGetSymbolAddress(&p, g_wgl); bf16* wgl = (bf16*)p;
    cudaGetSymbolAddress(&p, g_wuh); bf16* wuh = (bf16*)p;
    cudaGetSymbolAddress(&p, g_wul); bf16* wul = (bf16*)p;
    cudaGetSymbolAddress(&p, g_wdh); bf16* wdh = (bf16*)p;
    cudaGetSymbolAddress(&p, g_wdl); bf16* wdl = (bf16*)p;

    cudaFuncSetAttribute(gemm3<0>, cudaFuncAttributeMaxDynamicSharedMemorySize, G_DSMEM);
    cudaFuncSetAttribute(gemm3<1>, cudaFuncAttributeMaxDynamicSharedMemorySize, G_DSMEM);
    cudaFuncSetAttribute(gemm3<2>, cudaFuncAttributeMaxDynamicSharedMemorySize, G_DSMEM);
    cudaFuncSetAttribute(gemm3<3>, cudaFuncAttributeMaxDynamicSharedMemorySize, G_DSMEM);
    cudaFuncSetAttribute(attn_mma_kernel, cudaFuncAttributeMaxDynamicSharedMemorySize, A_DSMEM);

    ln_split_kernel<<<S, 256>>>(memory, ln1w, ln1b, xh, xl);
    ln_split_kernel<<<S, 256>>>(hidden, ln1w, ln1b, xh + (size_t)S * Dm, xl + (size_t)S * Dm);

    int nDD = Dm * Dm / 4, nFD = FF * Dm / 4;
    split_kernel<<<nDD / 256, 256>>>(Wq, wqh, wql, nDD);
    split_kernel<<<nDD / 256, 256>>>(Wk, wkh, wkl, nDD);
    split_kernel<<<nDD / 256, 256>>>(Wv, wvh, wvl, nDD);
    split_kernel<<<nDD / 256, 256>>>(Wo, woh, wol, nDD);
    split_kernel<<<nFD / 256, 256>>>(Wg, wgh, wgl, nFD);
    split_kernel<<<nFD / 256, 256>>>(Wu, wuh, wul, nFD);
    split_kernel<<<nFD / 256, 256>>>(Wd, wdh, wdl, nFD);

    {
        dim3 gKV(Dm / 128, L / 128);
        gemm3<1><<<gKV, 256, G_DSMEM>>>(xh, xl, wkh, wkl, nullptr, nullptr, kh, kl, 1.0f, L, Dm, Dm);
        gemm3<2><<<gKV, 256, G_DSMEM>>>(xh, xl, wvh, wvl, nullptr, nullptr, vh, vl, 1.0f, L, Dm, Dm);
        dim3 gQ(Dm / 128, S / 128);
        gemm3<1><<<gQ, 256, G_DSMEM>>>(xh + (size_t)S * Dm, xl + (size_t)S * Dm,
                                       wqh, wql, nullptr, nullptr, qh, ql, 0.125f, S, Dm, Dm);
    }

    {
        dim3 g(S / 64, NH);
        attn_mma_kernel<<<g, 128, A_DSMEM>>>(qh, ql, kh, kl, vh, vl, ah, al);
    }

    {
        dim3 g(Dm / 128, S / 128);
        gemm3<0><<<g, 256, G_DSMEM>>>(ah, al, woh, wol, hidden, hbuf, nullptr, nullptr, 1.0f, S, Dm, Dm);
    }
    ln_split_kernel<<<S, 256>>>(hbuf, ln2w, ln2b, h2h, h2l);
    {
        dim3 g(FF / 128, S / 128);
        gemm3<0><<<g, 256, G_DSMEM>>>(h2h, h2l, wgh, wgl, nullptr, gr, nullptr, nullptr, 1.0f, S, FF, Dm);
        gemm3<3><<<g, 256, G_DSMEM>>>(h2h, h2l, wuh, wul, gr, nullptr, gh, gl, 1.0f, S, FF, Dm);
    }
    {
        dim3 g(Dm / 128, S / 128);
        gemm3<0><<<g, 256, G_DSMEM>>>(gh, gl, wdh, wdl, hbuf, out, nullptr, nullptr, 1.0f, S, Dm, FF);
    }
}

// round 7
// speedup vs baseline: 1.7765x; 1.0997x over previous
#include <cuda_runtime.h>
#include <cuda_bf16.h>
#include <cstdint>

#define S    2048
#define Dm   2048
#define FF   8192
#define NH   32
#define HD   64
#define L    4096

typedef __nv_bfloat16 bf16;

__device__ __forceinline__ uint32_t smem_u32(const void* p) {
    uint32_t a;
    asm("{ .reg .u64 t; cvta.to.shared.u64 t, %1; cvt.u32.u64 %0, t; }" : "=r"(a) : "l"(p));
    return a;
}
__device__ __forceinline__ void ldm_x4(uint32_t* r, uint32_t a) {
    asm volatile("ldmatrix.sync.aligned.m8n8.x4.shared.b16 {%0,%1,%2,%3}, [%4];"
        : "=r"(r[0]), "=r"(r[1]), "=r"(r[2]), "=r"(r[3]) : "r"(a));
}
__device__ __forceinline__ void ldm_x4_t(uint32_t* r, uint32_t a) {
    asm volatile("ldmatrix.sync.aligned.m8n8.x4.trans.shared.b16 {%0,%1,%2,%3}, [%4];"
        : "=r"(r[0]), "=r"(r[1]), "=r"(r[2]), "=r"(r[3]) : "r"(a));
}
__device__ __forceinline__ void mma_bf16(float* c, const uint32_t* a, uint32_t b0, uint32_t b1) {
    asm volatile("mma.sync.aligned.m16n8k16.row.col.f32.bf16.bf16.f32 "
        "{%0,%1,%2,%3}, {%4,%5,%6,%7}, {%8,%9}, {%0,%1,%2,%3};"
        : "+f"(c[0]), "+f"(c[1]), "+f"(c[2]), "+f"(c[3])
        : "r"(a[0]), "r"(a[1]), "r"(a[2]), "r"(a[3]), "r"(b0), "r"(b1));
}
__device__ __forceinline__ uint32_t pack_bf16(float a, float b) {
    __nv_bfloat162 t; t.x = __float2bfloat16_rn(a); t.y = __float2bfloat16_rn(b);
    return *(uint32_t*)&t;
}
__device__ __forceinline__ void split2(float a, float b, uint32_t& h, uint32_t& l) {
    bf16 ha = __float2bfloat16_rn(a), hb = __float2bfloat16_rn(b);
    __nv_bfloat162 hv; hv.x = ha; hv.y = hb;
    h = *(uint32_t*)&hv;
    l = pack_bf16(a - __bfloat162float(ha), b - __bfloat162float(hb));
}
#define CP_ASYNC16(dst, src) \
    asm volatile("cp.async.cg.shared.global [%0], [%1], 16;" :: "r"(dst), "l"(src))
#define CP_COMMIT() asm volatile("cp.async.commit_group;" ::: "memory")
#define CP_WAIT1()  asm volatile("cp.async.wait_group 1;" ::: "memory")
#define CP_WAIT2()  asm volatile("cp.async.wait_group 2;" ::: "memory")

// ------------- scratch -------------
__device__ bf16  g_xh [L * Dm]; __device__ bf16 g_xl [L * Dm];
__device__ bf16  g_qh [S * Dm]; __device__ bf16 g_ql [S * Dm];
__device__ bf16  g_kh [L * Dm]; __device__ bf16 g_kl [L * Dm];
__device__ bf16  g_vh [L * Dm]; __device__ bf16 g_vl [L * Dm];
__device__ bf16  g_ah [S * Dm]; __device__ bf16 g_al [S * Dm];
__device__ float g_h  [S * Dm];
__device__ bf16  g_h2h[S * Dm]; __device__ bf16 g_h2l[S * Dm];
__device__ float g_gr [S * FF];
__device__ bf16  g_gh [S * FF]; __device__ bf16 g_gl [S * FF];
__device__ bf16  g_wqh[Dm * Dm]; __device__ bf16 g_wql[Dm * Dm];
__device__ bf16  g_wkh[Dm * Dm]; __device__ bf16 g_wkl[Dm * Dm];
__device__ bf16  g_wvh[Dm * Dm]; __device__ bf16 g_wvl[Dm * Dm];
__device__ bf16  g_woh[Dm * Dm]; __device__ bf16 g_wol[Dm * Dm];
__device__ bf16  g_wgh[FF * Dm]; __device__ bf16 g_wgl[FF * Dm];
__device__ bf16  g_wuh[FF * Dm]; __device__ bf16 g_wul[FF * Dm];
__device__ bf16  g_wdh[Dm * FF]; __device__ bf16 g_wdl[Dm * FF];

// ------------- hi/lo split -------------
__global__ __launch_bounds__(256) void split_kernel(
    const float* __restrict__ X, bf16* __restrict__ H, bf16* __restrict__ Lo, int n4)
{
    int i = blockIdx.x * blockDim.x + threadIdx.x;
    if (i >= n4) return;
    float4 x = ((const float4*)X)[i];
    uint2 hu, lu;
    split2(x.x, x.y, hu.x, lu.x);
    split2(x.z, x.w, hu.y, lu.y);
    ((uint2*)H)[i] = hu;
    ((uint2*)Lo)[i] = lu;
}

// ------------- LayerNorm + split -------------
__global__ __launch_bounds__(256) void ln_split_kernel(
    const float* __restrict__ X, const float* __restrict__ w,
    const float* __restrict__ b, bf16* __restrict__ OH, bf16* __restrict__ OL)
{
    int row = blockIdx.x, tid = threadIdx.x;
    const float* xr = X + (size_t)row * Dm;
    float4 a = ((const float4*)xr)[tid * 2];
    float4 c = ((const float4*)xr)[tid * 2 + 1];
    float s  = a.x + a.y + a.z + a.w + c.x + c.y + c.z + c.w;
    float ss = a.x*a.x + a.y*a.y + a.z*a.z + a.w*a.w
             + c.x*c.x + c.y*c.y + c.z*c.z + c.w*c.w;
#pragma unroll
    for (int o = 16; o; o >>= 1) {
        s  += __shfl_xor_sync(0xffffffffu, s,  o);
        ss += __shfl_xor_sync(0xffffffffu, ss, o);
    }
    __shared__ float bs[8], bss[8];
    if ((tid & 31) == 0) { bs[tid >> 5] = s; bss[tid >> 5] = ss; }
    __syncthreads();
    float ts = 0.f, tss = 0.f;
#pragma unroll
    for (int i = 0; i < 8; i++) { ts += bs[i]; tss += bss[i]; }
    float mean = ts * (1.f / Dm);
    float inv  = rsqrtf(tss * (1.f / Dm) - mean * mean + 1e-5f);
    int d = tid * 8;
    float4 w0 = ((const float4*)w)[tid*2], w1 = ((const float4*)w)[tid*2+1];
    float4 b0 = ((const float4*)b)[tid*2], b1 = ((const float4*)b)[tid*2+1];
    float v8[8];
    v8[0]=(a.x-mean)*inv*w0.x+b0.x; v8[1]=(a.y-mean)*inv*w0.y+b0.y;
    v8[2]=(a.z-mean)*inv*w0.z+b0.z; v8[3]=(a.w-mean)*inv*w0.w+b0.w;
    v8[4]=(c.x-mean)*inv*w1.x+b1.x; v8[5]=(c.y-mean)*inv*w1.y+b1.y;
    v8[6]=(c.z-mean)*inv*w1.z+b1.z; v8[7]=(c.w-mean)*inv*w1.w+b1.w;
    uint2 hu0, lu0, hu1, lu1;
    split2(v8[0], v8[1], hu0.x, lu0.x); split2(v8[2], v8[3], hu0.y, lu0.y);
    split2(v8[4], v8[5], hu1.x, lu1.x); split2(v8[6], v8[7], hu1.y, lu1.y);
    *(uint2*)(OH + (size_t)row * Dm + d)     = hu0;
    *(uint2*)(OH + (size_t)row * Dm + d + 4) = hu1;
    *(uint2*)(OL + (size_t)row * Dm + d)     = lu0;
    *(uint2*)(OL + (size_t)row * Dm + d + 4) = lu1;
}

// ------------- GEMM: 3-term bf16, 4-stage multistage, 1 sync/chunk -------------
// MODE 0: C fp32 = acc (+Res) | MODE 1: rope+scale -> hi/lo | MODE 2: hi/lo | MODE 3: silu(Res)*acc -> hi/lo
#define GBK 16
#define G_ROWB 48
#define G_TILEB (128 * G_ROWB)            // 6144
#define G_STAGEB (4 * G_TILEB)            // 24576
#define G_NST 4
#define G_DSMEM (G_NST * G_STAGEB)        // 98304

template<int MODE>
__global__ __launch_bounds__(256, 2)
void gemm3(const bf16* __restrict__ Ahi, const bf16* __restrict__ Alo,
           const bf16* __restrict__ Bhi, const bf16* __restrict__ Blo,
           const float* __restrict__ Res, float* __restrict__ C,
           bf16* __restrict__ OH, bf16* __restrict__ OL, float scale,
           int M, int N, int K)
{
    extern __shared__ char smem[];
    uint32_t sb = smem_u32(smem);
    int tid  = threadIdx.x, wid = tid >> 5, lane = tid & 31;
    int wm = wid & 3, wn = wid >> 2;
    int bm = blockIdx.y * 128, bn = blockIdx.x * 128;

    auto loadChunk = [&](int stg, int k0) {
        uint32_t base = sb + stg * G_STAGEB;
        int r = tid >> 1, c = tid & 1;            // 2 chunks of 8 bf16 per row
        uint32_t doff = r * G_ROWB + c * 16;
        size_t soff = (size_t)r * K + k0 + c * 8;
        CP_ASYNC16(base + doff,             Ahi + (size_t)bm * K + soff);
        CP_ASYNC16(base + G_TILEB + doff,   Alo + (size_t)bm * K + soff);
        CP_ASYNC16(base + 2*G_TILEB + doff, Bhi + (size_t)bn * K + soff);
        CP_ASYNC16(base + 3*G_TILEB + doff, Blo + (size_t)bn * K + soff);
        // second half of rows
        r += 128; // rows 128..255 map to row r-128 second 16B? no: 256 threads cover 128 rows x 2 cols exactly
    };
    // 256 threads x (1 row-slot) covers 128 rows x 2 col-chunks exactly per tile.

    float acc[2][8][4];
#pragma unroll
    for (int i = 0; i < 2; i++)
#pragma unroll
        for (int j = 0; j < 8; j++)
#pragma unroll
            for (int t = 0; t < 4; t++) acc[i][j][t] = 0.f;

    int NKC = K / GBK;
    loadChunk(0, 0);        CP_COMMIT();
    loadChunk(1, GBK);      CP_COMMIT();
    loadChunk(2, 2 * GBK);  CP_COMMIT();

    int a_row = lane & 15;
    int a_kb  = (lane >> 4) * 16;
    int b_row = lane & 7;
    int b_kb  = ((lane >> 3) & 1) * 16;
    int nsel  = (lane >> 4) & 1;

    for (int k = 0; k < NKC; k++) {
        int stg = k & (G_NST - 1);
        CP_WAIT2();
        __syncthreads();
        if (k + 3 < NKC) { loadChunk((k + 3) & (G_NST - 1), (k + 3) * GBK); }
        CP_COMMIT();
        uint32_t base = sb + stg * G_STAGEB;
        uint32_t Ah[2][4], Al[2][4];
#pragma unroll
        for (int mf = 0; mf < 2; mf++) {
            uint32_t addr = base + (uint32_t)((wm*32 + mf*16 + a_row) * G_ROWB) + a_kb;
            ldm_x4(Ah[mf], addr);
            ldm_x4(Al[mf], addr + G_TILEB);
        }
#pragma unroll
        for (int g = 0; g < 2; g++) {
            uint32_t Bh[4][2], Bl[4][2];
#pragma unroll
            for (int p = 0; p < 2; p++) {
                uint32_t addr = base + 2*G_TILEB
                    + (uint32_t)((wn*64 + (g*4 + p*2 + nsel)*8 + b_row) * G_ROWB) + b_kb;
                uint32_t r4[4];
                ldm_x4(r4, addr);
                Bh[p*2][0] = r4[0]; Bh[p*2][1] = r4[1];
                Bh[p*2+1][0] = r4[2]; Bh[p*2+1][1] = r4[3];
                ldm_x4(r4, addr + G_TILEB);
                Bl[p*2][0] = r4[0]; Bl[p*2][1] = r4[1];
                Bl[p*2+1][0] = r4[2]; Bl[p*2+1][1] = r4[3];
            }
#pragma unroll
            for (int mf = 0; mf < 2; mf++)
#pragma unroll
                for (int nf = 0; nf < 4; nf++) {
                    float* c = acc[mf][g*4 + nf];
                    mma_bf16(c, Ah[mf], Bh[nf][0], Bh[nf][1]);
                    mma_bf16(c, Al[mf], Bh[nf][0], Bh[nf][1]);
                    mma_bf16(c, Ah[mf], Bl[nf][0], Bl[nf][1]);
                }
        }
    }

    int rr = lane >> 2, cp = lane & 3;
    if (MODE == 1) {
#pragma unroll
        for (int mf = 0; mf < 2; mf++)
#pragma unroll
            for (int j = 0; j < 4; j++) {
                int d = cp * 2 + (j & 1);
                int row = bm + wm*32 + mf*16 + rr + ((j >> 1) * 8);
                int pos = row & (S - 1);
                float invf = __powf(10000.f, -(float)d * 0.125f);
                float sn, cs; sincosf(pos * invf, &sn, &cs);
                float x1 = acc[mf][0][j], x2 = acc[mf][1][j];
                acc[mf][0][j] = x1 * cs - x2 * sn;
                acc[mf][1][j] = x2 * cs + x1 * sn;
            }
    }
#pragma unroll
    for (int mf = 0; mf < 2; mf++) {
        int row0 = bm + wm*32 + mf*16 + rr;
#pragma unroll
        for (int nf = 0; nf < 8; nf++) {
            int col = bn + wn*64 + nf*8 + cp*2;
            float* c = acc[mf][nf];
            size_t o0 = (size_t)row0 * N + col;
            size_t o1 = (size_t)(row0 + 8) * N + col;
            if (MODE == 0) {
                float2 v0 = make_float2(c[0], c[1]);
                float2 v1 = make_float2(c[2], c[3]);
                if (Res) {
                    float2 e0 = *(const float2*)(Res + o0);
                    float2 e1 = *(const float2*)(Res + o1);
                    v0.x += e0.x; v0.y += e0.y; v1.x += e1.x; v1.y += e1.y;
                }
                *(float2*)(C + o0) = v0;
                *(float2*)(C + o1) = v1;
            } else {
                float v0 = c[0], v1 = c[1], v2 = c[2], v3 = c[3];
                if (MODE == 3) {
                    float2 g0 = *(const float2*)(Res + o0);
                    float2 g1 = *(const float2*)(Res + o1);
                    v0 *= g0.x / (1.f + __expf(-g0.x));
                    v1 *= g0.y / (1.f + __expf(-g0.y));
                    v2 *= g1.x / (1.f + __expf(-g1.x));
                    v3 *= g1.y / (1.f + __expf(-g1.y));
                } else {
                    v0 *= scale; v1 *= scale; v2 *= scale; v3 *= scale;
                }
                uint32_t h0, l0, h1, l1;
                split2(v0, v1, h0, l0);
                split2(v2, v3, h1, l1);
                *(uint32_t*)(OH + o0) = h0;
                *(uint32_t*)(OL + o0) = l0;
                *(uint32_t*)(OH + o1) = h1;
                *(uint32_t*)(OL + o1) = l1;
            }
        }
    }
}

// ------------- flash attention via mma.sync -------------
#define A_PITCH 144
#define A_SQH 0u
#define A_SQL 9216u
#define A_SKH 18432u
#define A_SKL 36864u
#define A_SVH 55296u
#define A_SVL 73728u
#define A_SMS 92160u
#define A_SLS 92416u
#define A_DSMEM 92672

__global__ __launch_bounds__(128)
void attn_mma_kernel(const bf16* __restrict__ Qh, const bf16* __restrict__ Ql,
                     const bf16* __restrict__ Kh, const bf16* __restrict__ Kl,
                     const bf16* __restrict__ Vh, const bf16* __restrict__ Vl,
                     bf16* __restrict__ OH, bf16* __restrict__ OL)
{
    extern __shared__ char sm[];
    uint32_t sb = smem_u32(sm);
    const int qb = blockIdx.x, h = blockIdx.y;
    const int tid = threadIdx.x, wid = tid >> 5, lane = tid & 31;
    const int m0 = wid * 16;

#pragma unroll
    for (int j = 0; j < 4; j++) {
        int idx = tid + j * 128;
        int row = idx >> 3, c = idx & 7;
        size_t g = (size_t)(qb*64 + row) * Dm + h*64 + c*8;
        *(uint4*)(sm + A_SQH + row*A_PITCH + c*16) = *(const uint4*)(Qh + g);
        *(uint4*)(sm + A_SQL + row*A_PITCH + c*16) = *(const uint4*)(Ql + g);
    }
    auto loadKV = [&](int kb, int st) {
        uint32_t o = (uint32_t)st * 9216u;
#pragma unroll
        for (int j = 0; j < 4; j++) {
            int idx = tid + j * 128;
            int row = idx >> 3, c = idx & 7;
            size_t g = (size_t)(kb*64 + row) * Dm + h*64 + c*8;
            uint32_t d = o + row*A_PITCH + c*16;
            CP_ASYNC16(sb + A_SKH + d, Kh + g);
            CP_ASYNC16(sb + A_SKL + d, Kl + g);
            CP_ASYNC16(sb + A_SVH + d, Vh + g);
            CP_ASYNC16(sb + A_SVL + d, Vl + g);
        }
    };
    loadKV(0, 0); CP_COMMIT();
    __syncthreads();

    uint32_t qfh[4][4], qfl[4][4];
    {
        int a_row = lane & 15, koff = (lane >> 4) * 16;
#pragma unroll
        for (int kk = 0; kk < 4; kk++) {
            uint32_t ad = sb + A_SQH + (uint32_t)(m0 + a_row) * A_PITCH + kk*32 + koff;
            ldm_x4(qfh[kk], ad);
            ldm_x4(qfl[kk], ad + 9216u);
        }
    }

    float oacc[8][4];
#pragma unroll
    for (int nf = 0; nf < 8; nf++)
#pragma unroll
        for (int t = 0; t < 4; t++) oacc[nf][t] = 0.f;
    float mi0 = -1e30f, mi1 = -1e30f, li0 = 0.f, li1 = 0.f;
    const int r_l = lane >> 2, cq = (lane & 3) * 2;

    for (int kb = 0; kb <= qb; kb++) {
        if (kb < qb) loadKV(kb + 1, (kb + 1) & 1);
        CP_COMMIT();
        CP_WAIT1();
        __syncthreads();
        uint32_t st = (uint32_t)(kb & 1) * 9216u;

        float sf[8][4];
#pragma unroll
        for (int nf = 0; nf < 8; nf++)
#pragma unroll
            for (int t = 0; t < 4; t++) sf[nf][t] = 0.f;
        {
            int b_row = lane & 7, b_kb = ((lane >> 3) & 1) * 16, nsel = (lane >> 4) & 1;
#pragma unroll
            for (int kk = 0; kk < 4; kk++) {
                uint32_t bh[8][2], bl[8][2];
#pragma unroll
                for (int g = 0; g < 2; g++)
#pragma unroll
                    for (int p = 0; p < 2; p++) {
                        uint32_t ad = sb + A_SKH + st
                            + (uint32_t)(((g*4 + p*2 + nsel)*8 + b_row)) * A_PITCH
                            + kk*32 + b_kb;
                        uint32_t r4[4];
                        ldm_x4(r4, ad);
                        int f = g*4 + p*2;
                        bh[f][0] = r4[0]; bh[f][1] = r4[1];
                        bh[f+1][0] = r4[2]; bh[f+1][1] = r4[3];
                        ldm_x4(r4, ad + (A_SKL - A_SKH));
                        bl[f][0] = r4[0]; bl[f][1] = r4[1];
                        bl[f+1][0] = r4[2]; bl[f+1][1] = r4[3];
                    }
#pragma unroll
                for (int nf = 0; nf < 8; nf++) mma_bf16(sf[nf], qfh[kk], bh[nf][0], bh[nf][1]);
#pragma unroll
                for (int nf = 0; nf < 8; nf++) mma_bf16(sf[nf], qfl[kk], bh[nf][0], bh[nf][1]);
#pragma unroll
                for (int nf = 0; nf < 8; nf++) mma_bf16(sf[nf], qfh[kk], bl[nf][0], bl[nf][1]);
            }
        }
        if (kb == qb) {
#pragma unroll
            for (int nf = 0; nf < 8; nf++)
#pragma unroll
                for (int hh = 0; hh < 2; hh++) {
                    int jl = nf*8 + cq + hh;
                    if (jl >= m0 + r_l)     sf[nf][hh]     = -1e30f;
                    if (jl >= m0 + r_l + 8) sf[nf][2 + hh] = -1e30f;
                }
        }
        float mx0 = -1e30f, mx1 = -1e30f;
#pragma unroll
        for (int nf = 0; nf < 8; nf++) {
            mx0 = fmaxf(mx0, fmaxf(sf[nf][0], sf[nf][1]));
            mx1 = fmaxf(mx1, fmaxf(sf[nf][2], sf[nf][3]));
        }
        mx0 = fmaxf(mx0, __shfl_xor_sync(0xffffffffu, mx0, 1));
        mx0 = fmaxf(mx0, __shfl_xor_sync(0xffffffffu, mx0, 2));
        mx1 = fmaxf(mx1, __shfl_xor_sync(0xffffffffu, mx1, 1));
        mx1 = fmaxf(mx1, __shfl_xor_sync(0xffffffffu, mx1, 2));
        float nm0 = fmaxf(mi0, mx0), nm1 = fmaxf(mi1, mx1);
        float sc0 = __expf(mi0 - nm0), sc1 = __expf(mi1 - nm1);
        float sum0 = 0.f, sum1 = 0.f;
#pragma unroll
        for (int nf = 0; nf < 8; nf++) {
            sf[nf][0] = (sf[nf][0] <= -1e29f) ? 0.f : __expf(sf[nf][0] - nm0); sum0 += sf[nf][0];
            sf[nf][1] = (sf[nf][1] <= -1e29f) ? 0.f : __expf(sf[nf][1] - nm0); sum0 += sf[nf][1];
            sf[nf][2] = (sf[nf][2] <= -1e29f) ? 0.f : __expf(sf[nf][2] - nm1); sum1 += sf[nf][2];
            sf[nf][3] = (sf[nf][3] <= -1e29f) ? 0.f : __expf(sf[nf][3] - nm1); sum1 += sf[nf][3];
        }
        sum0 += __shfl_xor_sync(0xffffffffu, sum0, 1);
        sum0 += __shfl_xor_sync(0xffffffffu, sum0, 2);
        sum1 += __shfl_xor_sync(0xffffffffu, sum1, 1);
        sum1 += __shfl_xor_sync(0xffffffffu, sum1, 2);
        li0 = li0 * sc0 + sum0; li1 = li1 * sc1 + sum1;
        mi0 = nm0; mi1 = nm1;
#pragma unroll
        for (int nf = 0; nf < 8; nf++) {
            oacc[nf][0] *= sc0; oacc[nf][1] *= sc0;
            oacc[nf][2] *= sc1; oacc[nf][3] *= sc1;
        }
        {
            int vrow = lane & 15, vcol = (lane >> 4) * 8;
#pragma unroll
            for (int ks = 0; ks < 4; ks++) {
                uint32_t ah[4], al[4];
                split2(sf[2*ks][0],   sf[2*ks][1],   ah[0], al[0]);
                split2(sf[2*ks][2],   sf[2*ks][3],   ah[1], al[1]);
                split2(sf[2*ks+1][0], sf[2*ks+1][1], ah[2], al[2]);
                split2(sf[2*ks+1][2], sf[2*ks+1][3], ah[3], al[3]);
#pragma unroll
                for (int df = 0; df < 4; df++) {
                    uint32_t vh4[4], vl4[4];
                    uint32_t ad = sb + A_SVH + st
                        + (uint32_t)(ks*16 + vrow) * A_PITCH + (df*16 + vcol) * 2;
                    ldm_x4_t(vh4, ad);
                    ldm_x4_t(vl4, ad + (A_SVL - A_SVH));
                    mma_bf16(oacc[2*df],     ah, vh4[0], vh4[1]);
                    mma_bf16(oacc[2*df + 1], ah, vh4[2], vh4[3]);
                    mma_bf16(oacc[2*df],     al, vh4[0], vh4[1]);
                    mma_bf16(oacc[2*df + 1], al, vh4[2], vh4[3]);
                    mma_bf16(oacc[2*df],     ah, vl4[0], vl4[1]);
                    mma_bf16(oacc[2*df + 1], ah, vl4[2], vl4[3]);
                }
            }
        }
        __syncthreads();
    }

    float* ost = (float*)(sm + A_SKH);
#pragma unroll
    for (int nf = 0; nf < 8; nf++) {
        int c = nf*8 + cq;
        ost[(m0 + r_l) * 72 + c]         = oacc[nf][0];
        ost[(m0 + r_l) * 72 + c + 1]     = oacc[nf][1];
        ost[(m0 + r_l + 8) * 72 + c]     = oacc[nf][2];
        ost[(m0 + r_l + 8) * 72 + c + 1] = oacc[nf][3];
    }
    if ((lane & 3) == 0) {
        ((float*)(sm + A_SMS))[m0 + r_l]     = mi0;
        ((float*)(sm + A_SMS))[m0 + r_l + 8] = mi1;
        ((float*)(sm + A_SLS))[m0 + r_l]     = li0;
        ((float*)(sm + A_SLS))[m0 + r_l + 8] = li1;
    }
    __syncthreads();

    {
        int m = tid >> 1, hf = tid & 1;
        int i = qb*64 + m;
        const __nv_bfloat162* q2h = (const __nv_bfloat162*)(Qh + (size_t)i * Dm + h*64);
        const __nv_bfloat162* q2l = (const __nv_bfloat162*)(Ql + (size_t)i * Dm + h*64);
        const __nv_bfloat162* k2h = (const __nv_bfloat162*)(Kh + (size_t)(S + i) * Dm + h*64);
        const __nv_bfloat162* k2l = (const __nv_bfloat162*)(Kl + (size_t)(S + i) * Dm + h*64);
        float dot = 0.f;
#pragma unroll
        for (int t = 0; t < 32; t++) {
            float2 qa = __bfloat1622float2(q2h[t]);
            float2 qb2 = __bfloat1622float2(q2l[t]);
            float2 ka = __bfloat1622float2(k2h[t]);
            float2 kb = __bfloat1622float2(k2l[t]);
            dot += (qa.x + qb2.x) * (ka.x + kb.x) + (qa.y + qb2.y) * (ka.y + kb.y);
        }
        float ssf = dot;
        float mi = ((float*)(sm + A_SMS))[m];
        float li = ((float*)(sm + A_SLS))[m];
        float nm = fmaxf(mi, ssf);
        float sc = __expf(mi - nm);
        float pp = __expf(ssf - nm);
        float inv = 1.f / (li * sc + pp);
        const __nv_bfloat162* v2h = (const __nv_bfloat162*)(Vh + (size_t)(S + i) * Dm + h*64 + hf*32);
        const __nv_bfloat162* v2l = (const __nv_bfloat162*)(Vl + (size_t)(S + i) * Dm + h*64 + hf*32);
        float* orow = ost + m*72 + hf*32;
        uint32_t hh[8], ll[8];
#pragma unroll
        for (int t = 0; t < 16; t++) {
            float2 va = __bfloat1622float2(v2h[t]);
            float2 vb = __bfloat1622float2(v2l[t]);
            float val0 = (orow[t*2]   * sc + pp * (va.x + vb.x)) * inv;
            float val1 = (orow[t*2+1] * sc + pp * (va.y + vb.y)) * inv;
            split2(val0, val1, hh[t & 7], ll[t & 7]);
            if ((t & 7) == 7) {
                int t8 = t >> 3;
                *(uint4*)(OH + (size_t)i * Dm + h*64 + hf*32 + t8*16)     = *(uint4*)(hh);
                *(uint4*)(OH + (size_t)i * Dm + h*64 + hf*32 + t8*16 + 8) = *(uint4*)(hh + 4);
                *(uint4*)(OL + (size_t)i * Dm + h*64 + hf*32 + t8*16)     = *(uint4*)(ll);
                *(uint4*)(OL + (size_t)i * Dm + h*64 + hf*32 + t8*16 + 8) = *(uint4*)(ll + 4);
            }
        }
    }
}

// ------------- launch -------------
extern "C" void kernel_launch(void* const* d_in, const int* in_sizes, int n_in,
                              void* d_out, int out_size)
{
    const float* hidden = (const float*)d_in[0];
    const float* memory = (const float*)d_in[1];
    const float* ln1w = (const float*)d_in[4];
    const float* ln1b = (const float*)d_in[5];
    const float* ln2w = (const float*)d_in[6];
    const float* ln2b = (const float*)d_in[7];
    const float* Wq = (const float*)d_in[8];
    const float* Wk = (const float*)d_in[9];
    const float* Wv = (const float*)d_in[10];
    const float* Wo = (const float*)d_in[11];
    const float* Wg = (const float*)d_in[12];
    const float* Wu = (const float*)d_in[13];
    const float* Wd = (const float*)d_in[14];
    float* out = (float*)d_out;

    void* p;
    cudaGetSymbolAddress(&p, g_xh);  bf16* xh = (bf16*)p;
    cudaGetSymbolAddress(&p, g_xl);  bf16* xl = (bf16*)p;
    cudaGetSymbolAddress(&p, g_qh);  bf16* qh = (bf16*)p;
    cudaGetSymbolAddress(&p, g_ql);  bf16* ql = (bf16*)p;
    cudaGetSymbolAddress(&p, g_kh);  bf16* kh = (bf16*)p;
    cudaGetSymbolAddress(&p, g_kl);  bf16* kl = (bf16*)p;
    cudaGetSymbolAddress(&p, g_vh);  bf16* vh = (bf16*)p;
    cudaGetSymbolAddress(&p, g_vl);  bf16* vl = (bf16*)p;
    cudaGetSymbolAddress(&p, g_ah);  bf16* ah = (bf16*)p;
    cudaGetSymbolAddress(&p, g_al);  bf16* al = (bf16*)p;
    cudaGetSymbolAddress(&p, g_h);   float* hbuf = (float*)p;
    cudaGetSymbolAddress(&p, g_h2h); bf16* h2h = (bf16*)p;
    cudaGetSymbolAddress(&p, g_h2l); bf16* h2l = (bf16*)p;
    cudaGetSymbolAddress(&p, g_gr);  float* gr = (float*)p;
    cudaGetSymbolAddress(&p, g_gh);  bf16* gh = (bf16*)p;
    cudaGetSymbolAddress(&p, g_gl);  bf16* gl = (bf16*)p;
    cudaGetSymbolAddress(&p, g_wqh); bf16* wqh = (bf16*)p;
    cudaGetSymbolAddress(&p, g_wql); bf16* wql = (bf16*)p;
    cudaGetSymbolAddress(&p, g_wkh); bf16* wkh = (bf16*)p;
    cudaGetSymbolAddress(&p, g_wkl); bf16* wkl = (bf16*)p;
    cudaGetSymbolAddress(&p, g_wvh); bf16* wvh = (bf16*)p;
    cudaGetSymbolAddress(&p, g_wvl); bf16* wvl = (bf16*)p;
    cudaGetSymbolAddress(&p, g_woh); bf16* woh = (bf16*)p;
    cudaGetSymbolAddress(&p, g_wol); bf16* wol = (bf16*)p;
    cudaGetSymbolAddress(&p, g_wgh); bf16* wgh = (bf16*)p;
    cudaGetSymbolAddress(&p, g_wgl); bf16* wgl = (bf16*)p;
    cudaGetSymbolAddress(&p, g_wuh); bf16* wuh = (bf16*)p;
    cudaGetSymbolAddress(&p, g_wul); bf16* wul = (bf16*)p;
    cudaGetSymbolAddress(&p, g_wdh); bf16* wdh = (bf16*)p;
    cudaGetSymbolAddress(&p, g_wdl); bf16* wdl = (bf16*)p;

    cudaFuncSetAttribute(gemm3<0>, cudaFuncAttributeMaxDynamicSharedMemorySize, G_DSMEM);
    cudaFuncSetAttribute(gemm3<1>, cudaFuncAttributeMaxDynamicSharedMemorySize, G_DSMEM);
    cudaFuncSetAttribute(gemm3<2>, cudaFuncAttributeMaxDynamicSharedMemorySize, G_DSMEM);
    cudaFuncSetAttribute(gemm3<3>, cudaFuncAttributeMaxDynamicSharedMemorySize, G_DSMEM);
    cudaFuncSetAttribute(attn_mma_kernel, cudaFuncAttributeMaxDynamicSharedMemorySize, A_DSMEM);

    ln_split_kernel<<<S, 256>>>(memory, ln1w, ln1b, xh, xl);
    ln_split_kernel<<<S, 256>>>(hidden, ln1w, ln1b, xh + (size_t)S * Dm, xl + (size_t)S * Dm);

    int nDD = Dm * Dm / 4, nFD = FF * Dm / 4;
    split_kernel<<<nDD / 256, 256>>>(Wq, wqh, wql, nDD);
    split_kernel<<<nDD / 256, 256>>>(Wk, wkh, wkl, nDD);
    split_kernel<<<nDD / 256, 256>>>(Wv, wvh, wvl, nDD);
    split_kernel<<<nDD / 256, 256>>>(Wo, woh, wol, nDD);
    split_kernel<<<nFD / 256, 256>>>(Wg, wgh, wgl, nFD);
    split_kernel<<<nFD / 256, 256>>>(Wu, wuh, wul, nFD);
    split_kernel<<<nFD / 256, 256>>>(Wd, wdh, wdl, nFD);

    {
        dim3 gKV(Dm / 128, L / 128);
        gemm3<1><<<gKV, 256, G_DSMEM>>>(xh, xl, wkh, wkl, nullptr, nullptr, kh, kl, 1.0f, L, Dm, Dm);
        gemm3<2><<<gKV, 256, G_DSMEM>>>(xh, xl, wvh, wvl, nullptr, nullptr, vh, vl, 1.0f, L, Dm, Dm);
        dim3 gQ(Dm / 128, S / 128);
        gemm3<1><<<gQ, 256, G_DSMEM>>>(xh + (size_t)S * Dm, xl + (size_t)S * Dm,
                                       wqh, wql, nullptr, nullptr, qh, ql, 0.125f, S, Dm, Dm);
    }

    {
        dim3 g(S / 64, NH);
        attn_mma_kernel<<<g, 128, A_DSMEM>>>(qh, ql, kh, kl, vh, vl, ah, al);
    }

    {
        dim3 g(Dm / 128, S / 128);
        gemm3<0><<<g, 256, G_DSMEM>>>(ah, al, woh, wol, hidden, hbuf, nullptr, nullptr, 1.0f, S, Dm, Dm);
    }
    ln_split_kernel<<<S, 256>>>(hbuf, ln2w, ln2b, h2h, h2l);
    {
        dim3 g(FF / 128, S / 128);
        gemm3<0><<<g, 256, G_DSMEM>>>(h2h, h2l, wgh, wgl, nullptr, gr, nullptr, nullptr, 1.0f, S, FF, Dm);
        gemm3<3><<<g, 256, G_DSMEM>>>(h2h, h2l, wuh, wul, gr, nullptr, gh, gl, 1.0f, S, FF, Dm);
    }
    {
        dim3 g(Dm / 128, S / 128);
        gemm3<0><<<g, 256, G_DSMEM>>>(gh, gl, wdh, wdl, hbuf, out, nullptr, nullptr, 1.0f, S, Dm, FF);
    }
}

// round 8
// speedup vs baseline: 1.8559x; 1.0447x over previous
#include <cuda_runtime.h>
#include <cuda_bf16.h>
#include <cstdint>

#define S    2048
#define Dm   2048
#define FF   8192
#define NH   32
#define HD   64
#define L    4096

typedef __nv_bfloat16 bf16;

__device__ __forceinline__ uint32_t smem_u32(const void* p) {
    uint32_t a;
    asm("{ .reg .u64 t; cvta.to.shared.u64 t, %1; cvt.u32.u64 %0, t; }" : "=r"(a) : "l"(p));
    return a;
}
__device__ __forceinline__ void ldm_x4(uint32_t* r, uint32_t a) {
    asm volatile("ldmatrix.sync.aligned.m8n8.x4.shared.b16 {%0,%1,%2,%3}, [%4];"
        : "=r"(r[0]), "=r"(r[1]), "=r"(r[2]), "=r"(r[3]) : "r"(a));
}
__device__ __forceinline__ void ldm_x4_t(uint32_t* r, uint32_t a) {
    asm volatile("ldmatrix.sync.aligned.m8n8.x4.trans.shared.b16 {%0,%1,%2,%3}, [%4];"
        : "=r"(r[0]), "=r"(r[1]), "=r"(r[2]), "=r"(r[3]) : "r"(a));
}
__device__ __forceinline__ void mma_bf16(float* c, const uint32_t* a, uint32_t b0, uint32_t b1) {
    asm volatile("mma.sync.aligned.m16n8k16.row.col.f32.bf16.bf16.f32 "
        "{%0,%1,%2,%3}, {%4,%5,%6,%7}, {%8,%9}, {%0,%1,%2,%3};"
        : "+f"(c[0]), "+f"(c[1]), "+f"(c[2]), "+f"(c[3])
        : "r"(a[0]), "r"(a[1]), "r"(a[2]), "r"(a[3]), "r"(b0), "r"(b1));
}
__device__ __forceinline__ uint32_t pack_bf16(float a, float b) {
    __nv_bfloat162 t; t.x = __float2bfloat16_rn(a); t.y = __float2bfloat16_rn(b);
    return *(uint32_t*)&t;
}
__device__ __forceinline__ void split2(float a, float b, uint32_t& h, uint32_t& l) {
    bf16 ha = __float2bfloat16_rn(a), hb = __float2bfloat16_rn(b);
    __nv_bfloat162 hv; hv.x = ha; hv.y = hb;
    h = *(uint32_t*)&hv;
    l = pack_bf16(a - __bfloat162float(ha), b - __bfloat162float(hb));
}
#define CP_ASYNC16(dst, src) \
    asm volatile("cp.async.cg.shared.global [%0], [%1], 16;" :: "r"(dst), "l"(src))
#define CP_COMMIT() asm volatile("cp.async.commit_group;" ::: "memory")
#define CP_WAIT1()  asm volatile("cp.async.wait_group 1;" ::: "memory")
#define CP_WAIT2()  asm volatile("cp.async.wait_group 2;" ::: "memory")

// ------------- scratch -------------
__device__ bf16  g_xh [L * Dm]; __device__ bf16 g_xl [L * Dm];
__device__ bf16  g_qh [S * Dm]; __device__ bf16 g_ql [S * Dm];
__device__ bf16  g_kh [L * Dm]; __device__ bf16 g_kl [L * Dm];
__device__ bf16  g_vh [L * Dm]; __device__ bf16 g_vl [L * Dm];
__device__ bf16  g_ah [S * Dm]; __device__ bf16 g_al [S * Dm];
__device__ float g_h  [S * Dm];
__device__ bf16  g_h2h[S * Dm]; __device__ bf16 g_h2l[S * Dm];
__device__ float g_gr [S * FF];
__device__ bf16  g_gh [S * FF]; __device__ bf16 g_gl [S * FF];
__device__ bf16  g_wqh[Dm * Dm]; __device__ bf16 g_wql[Dm * Dm];
__device__ bf16  g_wkh[Dm * Dm]; __device__ bf16 g_wkl[Dm * Dm];
__device__ bf16  g_wvh[Dm * Dm]; __device__ bf16 g_wvl[Dm * Dm];
__device__ bf16  g_woh[Dm * Dm]; __device__ bf16 g_wol[Dm * Dm];
__device__ bf16  g_wgh[FF * Dm]; __device__ bf16 g_wgl[FF * Dm];
__device__ bf16  g_wuh[FF * Dm]; __device__ bf16 g_wul[FF * Dm];
__device__ bf16  g_wdh[Dm * FF]; __device__ bf16 g_wdl[Dm * FF];

// ------------- hi/lo split -------------
__global__ __launch_bounds__(256) void split_kernel(
    const float* __restrict__ X, bf16* __restrict__ H, bf16* __restrict__ Lo, int n4)
{
    int i = blockIdx.x * blockDim.x + threadIdx.x;
    if (i >= n4) return;
    float4 x = ((const float4*)X)[i];
    uint2 hu, lu;
    split2(x.x, x.y, hu.x, lu.x);
    split2(x.z, x.w, hu.y, lu.y);
    ((uint2*)H)[i] = hu;
    ((uint2*)Lo)[i] = lu;
}

// ------------- LayerNorm + split -------------
__global__ __launch_bounds__(256) void ln_split_kernel(
    const float* __restrict__ X, const float* __restrict__ w,
    const float* __restrict__ b, bf16* __restrict__ OH, bf16* __restrict__ OL)
{
    int row = blockIdx.x, tid = threadIdx.x;
    const float* xr = X + (size_t)row * Dm;
    float4 a = ((const float4*)xr)[tid * 2];
    float4 c = ((const float4*)xr)[tid * 2 + 1];
    float s  = a.x + a.y + a.z + a.w + c.x + c.y + c.z + c.w;
    float ss = a.x*a.x + a.y*a.y + a.z*a.z + a.w*a.w
             + c.x*c.x + c.y*c.y + c.z*c.z + c.w*c.w;
#pragma unroll
    for (int o = 16; o; o >>= 1) {
        s  += __shfl_xor_sync(0xffffffffu, s,  o);
        ss += __shfl_xor_sync(0xffffffffu, ss, o);
    }
    __shared__ float bs[8], bss[8];
    if ((tid & 31) == 0) { bs[tid >> 5] = s; bss[tid >> 5] = ss; }
    __syncthreads();
    float ts = 0.f, tss = 0.f;
#pragma unroll
    for (int i = 0; i < 8; i++) { ts += bs[i]; tss += bss[i]; }
    float mean = ts * (1.f / Dm);
    float inv  = rsqrtf(tss * (1.f / Dm) - mean * mean + 1e-5f);
    int d = tid * 8;
    float4 w0 = ((const float4*)w)[tid*2], w1 = ((const float4*)w)[tid*2+1];
    float4 b0 = ((const float4*)b)[tid*2], b1 = ((const float4*)b)[tid*2+1];
    float v8[8];
    v8[0]=(a.x-mean)*inv*w0.x+b0.x; v8[1]=(a.y-mean)*inv*w0.y+b0.y;
    v8[2]=(a.z-mean)*inv*w0.z+b0.z; v8[3]=(a.w-mean)*inv*w0.w+b0.w;
    v8[4]=(c.x-mean)*inv*w1.x+b1.x; v8[5]=(c.y-mean)*inv*w1.y+b1.y;
    v8[6]=(c.z-mean)*inv*w1.z+b1.z; v8[7]=(c.w-mean)*inv*w1.w+b1.w;
    uint2 hu0, lu0, hu1, lu1;
    split2(v8[0], v8[1], hu0.x, lu0.x); split2(v8[2], v8[3], hu0.y, lu0.y);
    split2(v8[4], v8[5], hu1.x, lu1.x); split2(v8[6], v8[7], hu1.y, lu1.y);
    *(uint2*)(OH + (size_t)row * Dm + d)     = hu0;
    *(uint2*)(OH + (size_t)row * Dm + d + 4) = hu1;
    *(uint2*)(OL + (size_t)row * Dm + d)     = lu0;
    *(uint2*)(OL + (size_t)row * Dm + d + 4) = lu1;
}

// ------------- GEMM: 3-term bf16, 4-stage, 4 warps x 64x64 warp tile -------------
// MODE 0: C fp32 = acc (+Res) | MODE 1: rope+scale -> hi/lo | MODE 2: hi/lo | MODE 3: silu(Res)*acc -> hi/lo
#define GBK 16
#define G_ROWB 48
#define G_TILEB (128 * G_ROWB)            // 6144
#define G_STAGEB (4 * G_TILEB)            // 24576
#define G_NST 4
#define G_DSMEM (G_NST * G_STAGEB)        // 98304

template<int MODE>
__global__ __launch_bounds__(128, 2)
void gemm3(const bf16* __restrict__ Ahi, const bf16* __restrict__ Alo,
           const bf16* __restrict__ Bhi, const bf16* __restrict__ Blo,
           const float* __restrict__ Res, float* __restrict__ C,
           bf16* __restrict__ OH, bf16* __restrict__ OL, float scale,
           int M, int N, int K)
{
    extern __shared__ char smem[];
    uint32_t sb = smem_u32(smem);
    int tid  = threadIdx.x, wid = tid >> 5, lane = tid & 31;
    int wm = wid & 1, wn = wid >> 1;          // 2x2 warp grid, 64x64 tiles
    int bm = blockIdx.y * 128, bn = blockIdx.x * 128;

    auto loadChunk = [&](int stg, int k0) {
        uint32_t base = sb + stg * G_STAGEB;
#pragma unroll
        for (int h = 0; h < 2; h++) {
            int idx = tid + h * 128;
            int r = idx >> 1, c = idx & 1;
            uint32_t doff = r * G_ROWB + c * 16;
            size_t soff = (size_t)r * K + k0 + c * 8;
            CP_ASYNC16(base + doff,             Ahi + (size_t)bm * K + soff);
            CP_ASYNC16(base + G_TILEB + doff,   Alo + (size_t)bm * K + soff);
            CP_ASYNC16(base + 2*G_TILEB + doff, Bhi + (size_t)bn * K + soff);
            CP_ASYNC16(base + 3*G_TILEB + doff, Blo + (size_t)bn * K + soff);
        }
    };

    float acc[4][8][4];
#pragma unroll
    for (int i = 0; i < 4; i++)
#pragma unroll
        for (int j = 0; j < 8; j++)
#pragma unroll
            for (int t = 0; t < 4; t++) acc[i][j][t] = 0.f;

    int NKC = K / GBK;
    loadChunk(0, 0);        CP_COMMIT();
    loadChunk(1, GBK);      CP_COMMIT();
    loadChunk(2, 2 * GBK);  CP_COMMIT();

    int a_row = lane & 15;
    int a_kb  = (lane >> 4) * 16;
    int b_row = lane & 7;
    int b_kb  = ((lane >> 3) & 1) * 16;
    int nsel  = (lane >> 4) & 1;

    for (int k = 0; k < NKC; k++) {
        int stg = k & (G_NST - 1);
        CP_WAIT2();
        __syncthreads();
        if (k + 3 < NKC) { loadChunk((k + 3) & (G_NST - 1), (k + 3) * GBK); }
        CP_COMMIT();
        uint32_t base = sb + stg * G_STAGEB;
        uint32_t Ah[4][4], Al[4][4];
#pragma unroll
        for (int mf = 0; mf < 4; mf++) {
            uint32_t addr = base + (uint32_t)((wm*64 + mf*16 + a_row) * G_ROWB) + a_kb;
            ldm_x4(Ah[mf], addr);
            ldm_x4(Al[mf], addr + G_TILEB);
        }
#pragma unroll
        for (int g = 0; g < 2; g++) {
            uint32_t Bh[4][2], Bl[4][2];
#pragma unroll
            for (int p = 0; p < 2; p++) {
                uint32_t addr = base + 2*G_TILEB
                    + (uint32_t)((wn*64 + (g*4 + p*2 + nsel)*8 + b_row) * G_ROWB) + b_kb;
                uint32_t r4[4];
                ldm_x4(r4, addr);
                Bh[p*2][0] = r4[0]; Bh[p*2][1] = r4[1];
                Bh[p*2+1][0] = r4[2]; Bh[p*2+1][1] = r4[3];
                ldm_x4(r4, addr + G_TILEB);
                Bl[p*2][0] = r4[0]; Bl[p*2][1] = r4[1];
                Bl[p*2+1][0] = r4[2]; Bl[p*2+1][1] = r4[3];
            }
#pragma unroll
            for (int mf = 0; mf < 4; mf++)
#pragma unroll
                for (int nf = 0; nf < 4; nf++) {
                    float* c = acc[mf][g*4 + nf];
                    mma_bf16(c, Ah[mf], Bh[nf][0], Bh[nf][1]);
                    mma_bf16(c, Al[mf], Bh[nf][0], Bh[nf][1]);
                    mma_bf16(c, Ah[mf], Bl[nf][0], Bl[nf][1]);
                }
        }
    }

    int rr = lane >> 2, cp = lane & 3;
    if (MODE == 1) {
#pragma unroll
        for (int mf = 0; mf < 4; mf++)
#pragma unroll
            for (int j = 0; j < 4; j++) {
                int d = cp * 2 + (j & 1);
                int row = bm + wm*64 + mf*16 + rr + ((j >> 1) * 8);
                int pos = row & (S - 1);
                float invf = __powf(10000.f, -(float)d * 0.125f);
                float sn, cs; sincosf(pos * invf, &sn, &cs);
                float x1 = acc[mf][0][j], x2 = acc[mf][1][j];
                acc[mf][0][j] = x1 * cs - x2 * sn;
                acc[mf][1][j] = x2 * cs + x1 * sn;
            }
    }
#pragma unroll
    for (int mf = 0; mf < 4; mf++) {
        int row0 = bm + wm*64 + mf*16 + rr;
#pragma unroll
        for (int nf = 0; nf < 8; nf++) {
            int col = bn + wn*64 + nf*8 + cp*2;
            float* c = acc[mf][nf];
            size_t o0 = (size_t)row0 * N + col;
            size_t o1 = (size_t)(row0 + 8) * N + col;
            if (MODE == 0) {
                float2 v0 = make_float2(c[0], c[1]);
                float2 v1 = make_float2(c[2], c[3]);
                if (Res) {
                    float2 e0 = *(const float2*)(Res + o0);
                    float2 e1 = *(const float2*)(Res + o1);
                    v0.x += e0.x; v0.y += e0.y; v1.x += e1.x; v1.y += e1.y;
                }
                *(float2*)(C + o0) = v0;
                *(float2*)(C + o1) = v1;
            } else {
                float v0 = c[0], v1 = c[1], v2 = c[2], v3 = c[3];
                if (MODE == 3) {
                    float2 g0 = *(const float2*)(Res + o0);
                    float2 g1 = *(const float2*)(Res + o1);
                    v0 *= g0.x / (1.f + __expf(-g0.x));
                    v1 *= g0.y / (1.f + __expf(-g0.y));
                    v2 *= g1.x / (1.f + __expf(-g1.x));
                    v3 *= g1.y / (1.f + __expf(-g1.y));
                } else {
                    v0 *= scale; v1 *= scale; v2 *= scale; v3 *= scale;
                }
                uint32_t h0, l0, h1, l1;
                split2(v0, v1, h0, l0);
                split2(v2, v3, h1, l1);
                *(uint32_t*)(OH + o0) = h0;
                *(uint32_t*)(OL + o0) = l0;
                *(uint32_t*)(OH + o1) = h1;
                *(uint32_t*)(OL + o1) = l1;
            }
        }
    }
}

// ------------- flash attention via mma.sync -------------
#define A_PITCH 144
#define A_SQH 0u
#define A_SQL 9216u
#define A_SKH 18432u
#define A_SKL 36864u
#define A_SVH 55296u
#define A_SVL 73728u
#define A_SMS 92160u
#define A_SLS 92416u
#define A_DSMEM 92672

__global__ __launch_bounds__(128)
void attn_mma_kernel(const bf16* __restrict__ Qh, const bf16* __restrict__ Ql,
                     const bf16* __restrict__ Kh, const bf16* __restrict__ Kl,
                     const bf16* __restrict__ Vh, const bf16* __restrict__ Vl,
                     bf16* __restrict__ OH, bf16* __restrict__ OL)
{
    extern __shared__ char sm[];
    uint32_t sb = smem_u32(sm);
    const int qb = blockIdx.x, h = blockIdx.y;
    const int tid = threadIdx.x, wid = tid >> 5, lane = tid & 31;
    const int m0 = wid * 16;

#pragma unroll
    for (int j = 0; j < 4; j++) {
        int idx = tid + j * 128;
        int row = idx >> 3, c = idx & 7;
        size_t g = (size_t)(qb*64 + row) * Dm + h*64 + c*8;
        *(uint4*)(sm + A_SQH + row*A_PITCH + c*16) = *(const uint4*)(Qh + g);
        *(uint4*)(sm + A_SQL + row*A_PITCH + c*16) = *(const uint4*)(Ql + g);
    }
    auto loadKV = [&](int kb, int st) {
        uint32_t o = (uint32_t)st * 9216u;
#pragma unroll
        for (int j = 0; j < 4; j++) {
            int idx = tid + j * 128;
            int row = idx >> 3, c = idx & 7;
            size_t g = (size_t)(kb*64 + row) * Dm + h*64 + c*8;
            uint32_t d = o + row*A_PITCH + c*16;
            CP_ASYNC16(sb + A_SKH + d, Kh + g);
            CP_ASYNC16(sb + A_SKL + d, Kl + g);
            CP_ASYNC16(sb + A_SVH + d, Vh + g);
            CP_ASYNC16(sb + A_SVL + d, Vl + g);
        }
    };
    loadKV(0, 0); CP_COMMIT();
    __syncthreads();

    uint32_t qfh[4][4], qfl[4][4];
    {
        int a_row = lane & 15, koff = (lane >> 4) * 16;
#pragma unroll
        for (int kk = 0; kk < 4; kk++) {
            uint32_t ad = sb + A_SQH + (uint32_t)(m0 + a_row) * A_PITCH + kk*32 + koff;
            ldm_x4(qfh[kk], ad);
            ldm_x4(qfl[kk], ad + 9216u);
        }
    }

    float oacc[8][4];
#pragma unroll
    for (int nf = 0; nf < 8; nf++)
#pragma unroll
        for (int t = 0; t < 4; t++) oacc[nf][t] = 0.f;
    float mi0 = -1e30f, mi1 = -1e30f, li0 = 0.f, li1 = 0.f;
    const int r_l = lane >> 2, cq = (lane & 3) * 2;

    for (int kb = 0; kb <= qb; kb++) {
        if (kb < qb) loadKV(kb + 1, (kb + 1) & 1);
        CP_COMMIT();
        CP_WAIT1();
        __syncthreads();
        uint32_t st = (uint32_t)(kb & 1) * 9216u;

        float sf[8][4];
#pragma unroll
        for (int nf = 0; nf < 8; nf++)
#pragma unroll
            for (int t = 0; t < 4; t++) sf[nf][t] = 0.f;
        {
            int b_row = lane & 7, b_kb = ((lane >> 3) & 1) * 16, nsel = (lane >> 4) & 1;
#pragma unroll
            for (int kk = 0; kk < 4; kk++) {
                uint32_t bh[8][2], bl[8][2];
#pragma unroll
                for (int g = 0; g < 2; g++)
#pragma unroll
                    for (int p = 0; p < 2; p++) {
                        uint32_t ad = sb + A_SKH + st
                            + (uint32_t)(((g*4 + p*2 + nsel)*8 + b_row)) * A_PITCH
                            + kk*32 + b_kb;
                        uint32_t r4[4];
                        ldm_x4(r4, ad);
                        int f = g*4 + p*2;
                        bh[f][0] = r4[0]; bh[f][1] = r4[1];
                        bh[f+1][0] = r4[2]; bh[f+1][1] = r4[3];
                        ldm_x4(r4, ad + (A_SKL - A_SKH));
                        bl[f][0] = r4[0]; bl[f][1] = r4[1];
                        bl[f+1][0] = r4[2]; bl[f+1][1] = r4[3];
                    }
#pragma unroll
                for (int nf = 0; nf < 8; nf++) mma_bf16(sf[nf], qfh[kk], bh[nf][0], bh[nf][1]);
#pragma unroll
                for (int nf = 0; nf < 8; nf++) mma_bf16(sf[nf], qfl[kk], bh[nf][0], bh[nf][1]);
#pragma unroll
                for (int nf = 0; nf < 8; nf++) mma_bf16(sf[nf], qfh[kk], bl[nf][0], bl[nf][1]);
            }
        }
        if (kb == qb) {
#pragma unroll
            for (int nf = 0; nf < 8; nf++)
#pragma unroll
                for (int hh = 0; hh < 2; hh++) {
                    int jl = nf*8 + cq + hh;
                    if (jl >= m0 + r_l)     sf[nf][hh]     = -1e30f;
                    if (jl >= m0 + r_l + 8) sf[nf][2 + hh] = -1e30f;
                }
        }
        float mx0 = -1e30f, mx1 = -1e30f;
#pragma unroll
        for (int nf = 0; nf < 8; nf++) {
            mx0 = fmaxf(mx0, fmaxf(sf[nf][0], sf[nf][1]));
            mx1 = fmaxf(mx1, fmaxf(sf[nf][2], sf[nf][3]));
        }
        mx0 = fmaxf(mx0, __shfl_xor_sync(0xffffffffu, mx0, 1));
        mx0 = fmaxf(mx0, __shfl_xor_sync(0xffffffffu, mx0, 2));
        mx1 = fmaxf(mx1, __shfl_xor_sync(0xffffffffu, mx1, 1));
        mx1 = fmaxf(mx1, __shfl_xor_sync(0xffffffffu, mx1, 2));
        float nm0 = fmaxf(mi0, mx0), nm1 = fmaxf(mi1, mx1);
        float sc0 = __expf(mi0 - nm0), sc1 = __expf(mi1 - nm1);
        float sum0 = 0.f, sum1 = 0.f;
#pragma unroll
        for (int nf = 0; nf < 8; nf++) {
            sf[nf][0] = (sf[nf][0] <= -1e29f) ? 0.f : __expf(sf[nf][0] - nm0); sum0 += sf[nf][0];
            sf[nf][1] = (sf[nf][1] <= -1e29f) ? 0.f : __expf(sf[nf][1] - nm0); sum0 += sf[nf][1];
            sf[nf][2] = (sf[nf][2] <= -1e29f) ? 0.f : __expf(sf[nf][2] - nm1); sum1 += sf[nf][2];
            sf[nf][3] = (sf[nf][3] <= -1e29f) ? 0.f : __expf(sf[nf][3] - nm1); sum1 += sf[nf][3];
        }
        sum0 += __shfl_xor_sync(0xffffffffu, sum0, 1);
        sum0 += __shfl_xor_sync(0xffffffffu, sum0, 2);
        sum1 += __shfl_xor_sync(0xffffffffu, sum1, 1);
        sum1 += __shfl_xor_sync(0xffffffffu, sum1, 2);
        li0 = li0 * sc0 + sum0; li1 = li1 * sc1 + sum1;
        mi0 = nm0; mi1 = nm1;
#pragma unroll
        for (int nf = 0; nf < 8; nf++) {
            oacc[nf][0] *= sc0; oacc[nf][1] *= sc0;
            oacc[nf][2] *= sc1; oacc[nf][3] *= sc1;
        }
        {
            int vrow = lane & 15, vcol = (lane >> 4) * 8;
#pragma unroll
            for (int ks = 0; ks < 4; ks++) {
                uint32_t ah[4], al[4];
                split2(sf[2*ks][0],   sf[2*ks][1],   ah[0], al[0]);
                split2(sf[2*ks][2],   sf[2*ks][3],   ah[1], al[1]);
                split2(sf[2*ks+1][0], sf[2*ks+1][1], ah[2], al[2]);
                split2(sf[2*ks+1][2], sf[2*ks+1][3], ah[3], al[3]);
#pragma unroll
                for (int df = 0; df < 4; df++) {
                    uint32_t vh4[4], vl4[4];
                    uint32_t ad = sb + A_SVH + st
                        + (uint32_t)(ks*16 + vrow) * A_PITCH + (df*16 + vcol) * 2;
                    ldm_x4_t(vh4, ad);
                    ldm_x4_t(vl4, ad + (A_SVL - A_SVH));
                    mma_bf16(oacc[2*df],     ah, vh4[0], vh4[1]);
                    mma_bf16(oacc[2*df + 1], ah, vh4[2], vh4[3]);
                    mma_bf16(oacc[2*df],     al, vh4[0], vh4[1]);
                    mma_bf16(oacc[2*df + 1], al, vh4[2], vh4[3]);
                    mma_bf16(oacc[2*df],     ah, vl4[0], vl4[1]);
                    mma_bf16(oacc[2*df + 1], ah, vl4[2], vl4[3]);
                }
            }
        }
        __syncthreads();
    }

    float* ost = (float*)(sm + A_SKH);
#pragma unroll
    for (int nf = 0; nf < 8; nf++) {
        int c = nf*8 + cq;
        ost[(m0 + r_l) * 72 + c]         = oacc[nf][0];
        ost[(m0 + r_l) * 72 + c + 1]     = oacc[nf][1];
        ost[(m0 + r_l + 8) * 72 + c]     = oacc[nf][2];
        ost[(m0 + r_l + 8) * 72 + c + 1] = oacc[nf][3];
    }
    if ((lane & 3) == 0) {
        ((float*)(sm + A_SMS))[m0 + r_l]     = mi0;
        ((float*)(sm + A_SMS))[m0 + r_l + 8] = mi1;
        ((float*)(sm + A_SLS))[m0 + r_l]     = li0;
        ((float*)(sm + A_SLS))[m0 + r_l + 8] = li1;
    }
    __syncthreads();

    {
        int m = tid >> 1, hf = tid & 1;
        int i = qb*64 + m;
        const __nv_bfloat162* q2h = (const __nv_bfloat162*)(Qh + (size_t)i * Dm + h*64);
        const __nv_bfloat162* q2l = (const __nv_bfloat162*)(Ql + (size_t)i * Dm + h*64);
        const __nv_bfloat162* k2h = (const __nv_bfloat162*)(Kh + (size_t)(S + i) * Dm + h*64);
        const __nv_bfloat162* k2l = (const __nv_bfloat162*)(Kl + (size_t)(S + i) * Dm + h*64);
        float dot = 0.f;
#pragma unroll
        for (int t = 0; t < 32; t++) {
            float2 qa = __bfloat1622float2(q2h[t]);
            float2 qb2 = __bfloat1622float2(q2l[t]);
            float2 ka = __bfloat1622float2(k2h[t]);
            float2 kb = __bfloat1622float2(k2l[t]);
            dot += (qa.x + qb2.x) * (ka.x + kb.x) + (qa.y + qb2.y) * (ka.y + kb.y);
        }
        float ssf = dot;
        float mi = ((float*)(sm + A_SMS))[m];
        float li = ((float*)(sm + A_SLS))[m];
        float nm = fmaxf(mi, ssf);
        float sc = __expf(mi - nm);
        float pp = __expf(ssf - nm);
        float inv = 1.f / (li * sc + pp);
        const __nv_bfloat162* v2h = (const __nv_bfloat162*)(Vh + (size_t)(S + i) * Dm + h*64 + hf*32);
        const __nv_bfloat162* v2l = (const __nv_bfloat162*)(Vl + (size_t)(S + i) * Dm + h*64 + hf*32);
        float* orow = ost + m*72 + hf*32;
        uint32_t hh[8], ll[8];
#pragma unroll
        for (int t = 0; t < 16; t++) {
            float2 va = __bfloat1622float2(v2h[t]);
            float2 vb = __bfloat1622float2(v2l[t]);
            float val0 = (orow[t*2]   * sc + pp * (va.x + vb.x)) * inv;
            float val1 = (orow[t*2+1] * sc + pp * (va.y + vb.y)) * inv;
            split2(val0, val1, hh[t & 7], ll[t & 7]);
            if ((t & 7) == 7) {
                int t8 = t >> 3;
                *(uint4*)(OH + (size_t)i * Dm + h*64 + hf*32 + t8*16)     = *(uint4*)(hh);
                *(uint4*)(OH + (size_t)i * Dm + h*64 + hf*32 + t8*16 + 8) = *(uint4*)(hh + 4);
                *(uint4*)(OL + (size_t)i * Dm + h*64 + hf*32 + t8*16)     = *(uint4*)(ll);
                *(uint4*)(OL + (size_t)i * Dm + h*64 + hf*32 + t8*16 + 8) = *(uint4*)(ll + 4);
            }
        }
    }
}

// ------------- launch -------------
extern "C" void kernel_launch(void* const* d_in, const int* in_sizes, int n_in,
                              void* d_out, int out_size)
{
    const float* hidden = (const float*)d_in[0];
    const float* memory = (const float*)d_in[1];
    const float* ln1w = (const float*)d_in[4];
    const float* ln1b = (const float*)d_in[5];
    const float* ln2w = (const float*)d_in[6];
    const float* ln2b = (const float*)d_in[7];
    const float* Wq = (const float*)d_in[8];
    const float* Wk = (const float*)d_in[9];
    const float* Wv = (const float*)d_in[10];
    const float* Wo = (const float*)d_in[11];
    const float* Wg = (const float*)d_in[12];
    const float* Wu = (const float*)d_in[13];
    const float* Wd = (const float*)d_in[14];
    float* out = (float*)d_out;

    void* p;
    cudaGetSymbolAddress(&p, g_xh);  bf16* xh = (bf16*)p;
    cudaGetSymbolAddress(&p, g_xl);  bf16* xl = (bf16*)p;
    cudaGetSymbolAddress(&p, g_qh);  bf16* qh = (bf16*)p;
    cudaGetSymbolAddress(&p, g_ql);  bf16* ql = (bf16*)p;
    cudaGetSymbolAddress(&p, g_kh);  bf16* kh = (bf16*)p;
    cudaGetSymbolAddress(&p, g_kl);  bf16* kl = (bf16*)p;
    cudaGetSymbolAddress(&p, g_vh);  bf16* vh = (bf16*)p;
    cudaGetSymbolAddress(&p, g_vl);  bf16* vl = (bf16*)p;
    cudaGetSymbolAddress(&p, g_ah);  bf16* ah = (bf16*)p;
    cudaGetSymbolAddress(&p, g_al);  bf16* al = (bf16*)p;
    cudaGetSymbolAddress(&p, g_h);   float* hbuf = (float*)p;
    cudaGetSymbolAddress(&p, g_h2h); bf16* h2h = (bf16*)p;
    cudaGetSymbolAddress(&p, g_h2l); bf16* h2l = (bf16*)p;
    cudaGetSymbolAddress(&p, g_gr);  float* gr = (float*)p;
    cudaGetSymbolAddress(&p, g_gh);  bf16* gh = (bf16*)p;
    cudaGetSymbolAddress(&p, g_gl);  bf16* gl = (bf16*)p;
    cudaGetSymbolAddress(&p, g_wqh); bf16* wqh = (bf16*)p;
    cudaGetSymbolAddress(&p, g_wql); bf16* wql = (bf16*)p;
    cudaGetSymbolAddress(&p, g_wkh); bf16* wkh = (bf16*)p;
    cudaGetSymbolAddress(&p, g_wkl); bf16* wkl = (bf16*)p;
    cudaGetSymbolAddress(&p, g_wvh); bf16* wvh = (bf16*)p;
    cudaGetSymbolAddress(&p, g_wvl); bf16* wvl = (bf16*)p;
    cudaGetSymbolAddress(&p, g_woh); bf16* woh = (bf16*)p;
    cudaGetSymbolAddress(&p, g_wol); bf16* wol = (bf16*)p;
    cudaGetSymbolAddress(&p, g_wgh); bf16* wgh = (bf16*)p;
    cudaGetSymbolAddress(&p, g_wgl); bf16* wgl = (bf16*)p;
    cudaGetSymbolAddress(&p, g_wuh); bf16* wuh = (bf16*)p;
    cudaGetSymbolAddress(&p, g_wul); bf16* wul = (bf16*)p;
    cudaGetSymbolAddress(&p, g_wdh); bf16* wdh = (bf16*)p;
    cudaGetSymbolAddress(&p, g_wdl); bf16* wdl = (bf16*)p;

    cudaFuncSetAttribute(gemm3<0>, cudaFuncAttributeMaxDynamicSharedMemorySize, G_DSMEM);
    cudaFuncSetAttribute(gemm3<1>, cudaFuncAttributeMaxDynamicSharedMemorySize, G_DSMEM);
    cudaFuncSetAttribute(gemm3<2>, cudaFuncAttributeMaxDynamicSharedMemorySize, G_DSMEM);
    cudaFuncSetAttribute(gemm3<3>, cudaFuncAttributeMaxDynamicSharedMemorySize, G_DSMEM);
    cudaFuncSetAttribute(attn_mma_kernel, cudaFuncAttributeMaxDynamicSharedMemorySize, A_DSMEM);

    ln_split_kernel<<<S, 256>>>(memory, ln1w, ln1b, xh, xl);
    ln_split_kernel<<<S, 256>>>(hidden, ln1w, ln1b, xh + (size_t)S * Dm, xl + (size_t)S * Dm);

    int nDD = Dm * Dm / 4, nFD = FF * Dm / 4;
    split_kernel<<<nDD / 256, 256>>>(Wq, wqh, wql, nDD);
    split_kernel<<<nDD / 256, 256>>>(Wk, wkh, wkl, nDD);
    split_kernel<<<nDD / 256, 256>>>(Wv, wvh, wvl, nDD);
    split_kernel<<<nDD / 256, 256>>>(Wo, woh, wol, nDD);
    split_kernel<<<nFD / 256, 256>>>(Wg, wgh, wgl, nFD);
    split_kernel<<<nFD / 256, 256>>>(Wu, wuh, wul, nFD);
    split_kernel<<<nFD / 256, 256>>>(Wd, wdh, wdl, nFD);

    {
        dim3 gKV(Dm / 128, L / 128);
        gemm3<1><<<gKV, 128, G_DSMEM>>>(xh, xl, wkh, wkl, nullptr, nullptr, kh, kl, 1.0f, L, Dm, Dm);
        gemm3<2><<<gKV, 128, G_DSMEM>>>(xh, xl, wvh, wvl, nullptr, nullptr, vh, vl, 1.0f, L, Dm, Dm);
        dim3 gQ(Dm / 128, S / 128);
        gemm3<1><<<gQ, 128, G_DSMEM>>>(xh + (size_t)S * Dm, xl + (size_t)S * Dm,
                                       wqh, wql, nullptr, nullptr, qh, ql, 0.125f, S, Dm, Dm);
    }

    {
        dim3 g(S / 64, NH);
        attn_mma_kernel<<<g, 128, A_DSMEM>>>(qh, ql, kh, kl, vh, vl, ah, al);
    }

    {
        dim3 g(Dm / 128, S / 128);
        gemm3<0><<<g, 128, G_DSMEM>>>(ah, al, woh, wol, hidden, hbuf, nullptr, nullptr, 1.0f, S, Dm, Dm);
    }
    ln_split_kernel<<<S, 256>>>(hbuf, ln2w, ln2b, h2h, h2l);
    {
        dim3 g(FF / 128, S / 128);
        gemm3<0><<<g, 128, G_DSMEM>>>(h2h, h2l, wgh, wgl, nullptr, gr, nullptr, nullptr, 1.0f, S, FF, Dm);
        gemm3<3><<<g, 128, G_DSMEM>>>(h2h, h2l, wuh, wul, gr, nullptr, gh, gl, 1.0f, S, FF, Dm);
    }
    {
        dim3 g(Dm / 128, S / 128);
        gemm3<0><<<g, 128, G_DSMEM>>>(gh, gl, wdh, wdl, hbuf, out, nullptr, nullptr, 1.0f, S, Dm, FF);
    }
}

// round 9
// speedup vs baseline: 2.6793x; 1.4437x over previous
#include <cuda_runtime.h>
#include <cuda_bf16.h>
#include <cuda_fp16.h>
#include <cstdint>

#define S    2048
#define Dm   2048
#define FF   8192
#define NH   32
#define HD   64
#define L    4096

typedef __nv_bfloat16 bf16;

__device__ __forceinline__ uint32_t smem_u32(const void* p) {
    uint32_t a;
    asm("{ .reg .u64 t; cvta.to.shared.u64 t, %1; cvt.u32.u64 %0, t; }" : "=r"(a) : "l"(p));
    return a;
}
__device__ __forceinline__ void ldm_x4(uint32_t* r, uint32_t a) {
    asm volatile("ldmatrix.sync.aligned.m8n8.x4.shared.b16 {%0,%1,%2,%3}, [%4];"
        : "=r"(r[0]), "=r"(r[1]), "=r"(r[2]), "=r"(r[3]) : "r"(a));
}
__device__ __forceinline__ void ldm_x4_t(uint32_t* r, uint32_t a) {
    asm volatile("ldmatrix.sync.aligned.m8n8.x4.trans.shared.b16 {%0,%1,%2,%3}, [%4];"
        : "=r"(r[0]), "=r"(r[1]), "=r"(r[2]), "=r"(r[3]) : "r"(a));
}
__device__ __forceinline__ void mma_bf16(float* c, const uint32_t* a, uint32_t b0, uint32_t b1) {
    asm volatile("mma.sync.aligned.m16n8k16.row.col.f32.bf16.bf16.f32 "
        "{%0,%1,%2,%3}, {%4,%5,%6,%7}, {%8,%9}, {%0,%1,%2,%3};"
        : "+f"(c[0]), "+f"(c[1]), "+f"(c[2]), "+f"(c[3])
        : "r"(a[0]), "r"(a[1]), "r"(a[2]), "r"(a[3]), "r"(b0), "r"(b1));
}
__device__ __forceinline__ void mma_f16(float* c, const uint32_t* a, uint32_t b0, uint32_t b1) {
    asm volatile("mma.sync.aligned.m16n8k16.row.col.f32.f16.f16.f32 "
        "{%0,%1,%2,%3}, {%4,%5,%6,%7}, {%8,%9}, {%0,%1,%2,%3};"
        : "+f"(c[0]), "+f"(c[1]), "+f"(c[2]), "+f"(c[3])
        : "r"(a[0]), "r"(a[1]), "r"(a[2]), "r"(a[3]), "r"(b0), "r"(b1));
}
__device__ __forceinline__ uint32_t pack_bf16(float a, float b) {
    __nv_bfloat162 t; t.x = __float2bfloat16_rn(a); t.y = __float2bfloat16_rn(b);
    return *(uint32_t*)&t;
}
__device__ __forceinline__ void split2b(float a, float b, uint32_t& h, uint32_t& l) {
    bf16 ha = __float2bfloat16_rn(a), hb = __float2bfloat16_rn(b);
    __nv_bfloat162 hv; hv.x = ha; hv.y = hb;
    h = *(uint32_t*)&hv;
    l = pack_bf16(a - __bfloat162float(ha), b - __bfloat162float(hb));
}
__device__ __forceinline__ void split2h(float a, float b, uint32_t& h, uint32_t& l) {
    __half2 hv; hv.x = __float2half_rn(a); hv.y = __float2half_rn(b);
    h = *(uint32_t*)&hv;
    __half2 lv;
    lv.x = __float2half_rn(a - __half2float(hv.x));
    lv.y = __float2half_rn(b - __half2float(hv.y));
    l = *(uint32_t*)&lv;
}
#define CP_ASYNC16(dst, src) \
    asm volatile("cp.async.cg.shared.global [%0], [%1], 16;" :: "r"(dst), "l"(src))
#define CP_COMMIT() asm volatile("cp.async.commit_group;" ::: "memory")
#define CP_WAIT1()  asm volatile("cp.async.wait_group 1;" ::: "memory")
#define CP_WAIT2()  asm volatile("cp.async.wait_group 2;" ::: "memory")

// ------------- scratch -------------
__device__ __half g_xh [L * Dm]; __device__ __half g_xl [L * Dm];
__device__ bf16   g_qh [S * Dm]; __device__ bf16   g_ql [S * Dm];
__device__ bf16   g_kh [L * Dm]; __device__ bf16   g_kl [L * Dm];
__device__ bf16   g_vh [L * Dm]; __device__ bf16   g_vl [L * Dm];
__device__ __half g_ah [S * Dm]; __device__ __half g_al [S * Dm];
__device__ float  g_h  [S * Dm];
__device__ __half g_h2h[S * Dm]; __device__ __half g_h2l[S * Dm];
__device__ float  g_gr [S * FF];
__device__ __half g_gh [S * FF]; __device__ __half g_gl [S * FF];
__device__ __half g_wq[Dm * Dm];
__device__ __half g_wk[Dm * Dm];
__device__ __half g_wv[Dm * Dm];
__device__ __half g_wo[Dm * Dm];
__device__ __half g_wg[FF * Dm];
__device__ __half g_wu[FF * Dm];
__device__ __half g_wd[Dm * FF];

// ------------- fp32 -> fp16 convert (weights) -------------
__global__ __launch_bounds__(256) void conv_kernel(
    const float* __restrict__ X, __half* __restrict__ H, int n4)
{
    int i = blockIdx.x * blockDim.x + threadIdx.x;
    if (i >= n4) return;
    float4 x = ((const float4*)X)[i];
    __half2 a, b;
    a.x = __float2half_rn(x.x); a.y = __float2half_rn(x.y);
    b.x = __float2half_rn(x.z); b.y = __float2half_rn(x.w);
    uint2 o; o.x = *(uint32_t*)&a; o.y = *(uint32_t*)&b;
    ((uint2*)H)[i] = o;
}

// ------------- LayerNorm + fp16 hi/lo split -------------
__global__ __launch_bounds__(256) void ln_split_kernel(
    const float* __restrict__ X, const float* __restrict__ w,
    const float* __restrict__ b, __half* __restrict__ OH, __half* __restrict__ OL)
{
    int row = blockIdx.x, tid = threadIdx.x;
    const float* xr = X + (size_t)row * Dm;
    float4 a = ((const float4*)xr)[tid * 2];
    float4 c = ((const float4*)xr)[tid * 2 + 1];
    float s  = a.x + a.y + a.z + a.w + c.x + c.y + c.z + c.w;
    float ss = a.x*a.x + a.y*a.y + a.z*a.z + a.w*a.w
             + c.x*c.x + c.y*c.y + c.z*c.z + c.w*c.w;
#pragma unroll
    for (int o = 16; o; o >>= 1) {
        s  += __shfl_xor_sync(0xffffffffu, s,  o);
        ss += __shfl_xor_sync(0xffffffffu, ss, o);
    }
    __shared__ float bs[8], bss[8];
    if ((tid & 31) == 0) { bs[tid >> 5] = s; bss[tid >> 5] = ss; }
    __syncthreads();
    float ts = 0.f, tss = 0.f;
#pragma unroll
    for (int i = 0; i < 8; i++) { ts += bs[i]; tss += bss[i]; }
    float mean = ts * (1.f / Dm);
    float inv  = rsqrtf(tss * (1.f / Dm) - mean * mean + 1e-5f);
    int d = tid * 8;
    float4 w0 = ((const float4*)w)[tid*2], w1 = ((const float4*)w)[tid*2+1];
    float4 b0 = ((const float4*)b)[tid*2], b1 = ((const float4*)b)[tid*2+1];
    float v8[8];
    v8[0]=(a.x-mean)*inv*w0.x+b0.x; v8[1]=(a.y-mean)*inv*w0.y+b0.y;
    v8[2]=(a.z-mean)*inv*w0.z+b0.z; v8[3]=(a.w-mean)*inv*w0.w+b0.w;
    v8[4]=(c.x-mean)*inv*w1.x+b1.x; v8[5]=(c.y-mean)*inv*w1.y+b1.y;
    v8[6]=(c.z-mean)*inv*w1.z+b1.z; v8[7]=(c.w-mean)*inv*w1.w+b1.w;
    uint2 hu0, lu0, hu1, lu1;
    split2h(v8[0], v8[1], hu0.x, lu0.x); split2h(v8[2], v8[3], hu0.y, lu0.y);
    split2h(v8[4], v8[5], hu1.x, lu1.x); split2h(v8[6], v8[7], hu1.y, lu1.y);
    *(uint2*)(OH + (size_t)row * Dm + d)     = hu0;
    *(uint2*)(OH + (size_t)row * Dm + d + 4) = hu1;
    *(uint2*)(OL + (size_t)row * Dm + d)     = lu0;
    *(uint2*)(OL + (size_t)row * Dm + d + 4) = lu1;
}

// ------------- GEMM: 2-term fp16, 4-stage, 4 warps x 64x64 warp tile -------------
// C = (Ah+Al) @ Bh^T; MODE 0: fp32 (+Res) | 1: rope+scale -> bf16 hi/lo | 2: bf16 hi/lo | 3: silu(Res)*acc -> fp16 hi/lo
#define GBK 16
#define G_ROWB 48
#define G_TILEB (128 * G_ROWB)            // 6144
#define G_STAGEB (3 * G_TILEB)            // 18432 (Ah, Al, Bh)
#define G_NST 4
#define G_DSMEM (G_NST * G_STAGEB)        // 73728

template<int MODE>
__global__ __launch_bounds__(128, 2)
void gemm2(const __half* __restrict__ Ahi, const __half* __restrict__ Alo,
           const __half* __restrict__ Bh, const float* __restrict__ Res,
           float* __restrict__ C, void* __restrict__ OHv, void* __restrict__ OLv,
           float scale, int M, int N, int K)
{
    extern __shared__ char smem[];
    uint32_t sb = smem_u32(smem);
    int tid  = threadIdx.x, wid = tid >> 5, lane = tid & 31;
    int wm = wid & 1, wn = wid >> 1;
    int bm = blockIdx.y * 128, bn = blockIdx.x * 128;

    auto loadChunk = [&](int stg, int k0) {
        uint32_t base = sb + stg * G_STAGEB;
#pragma unroll
        for (int h = 0; h < 2; h++) {
            int idx = tid + h * 128;
            int r = idx >> 1, c = idx & 1;
            uint32_t doff = r * G_ROWB + c * 16;
            size_t soff = (size_t)r * K + k0 + c * 8;
            CP_ASYNC16(base + doff,             Ahi + (size_t)bm * K + soff);
            CP_ASYNC16(base + G_TILEB + doff,   Alo + (size_t)bm * K + soff);
            CP_ASYNC16(base + 2*G_TILEB + doff, Bh  + (size_t)bn * K + soff);
        }
    };

    float acc[4][8][4];
#pragma unroll
    for (int i = 0; i < 4; i++)
#pragma unroll
        for (int j = 0; j < 8; j++)
#pragma unroll
            for (int t = 0; t < 4; t++) acc[i][j][t] = 0.f;

    int NKC = K / GBK;
    loadChunk(0, 0);        CP_COMMIT();
    loadChunk(1, GBK);      CP_COMMIT();
    loadChunk(2, 2 * GBK);  CP_COMMIT();

    int a_row = lane & 15;
    int a_kb  = (lane >> 4) * 16;
    int b_row = lane & 7;
    int b_kb  = ((lane >> 3) & 1) * 16;
    int nsel  = (lane >> 4) & 1;

    for (int k = 0; k < NKC; k++) {
        int stg = k & (G_NST - 1);
        CP_WAIT2();
        __syncthreads();
        if (k + 3 < NKC) { loadChunk((k + 3) & (G_NST - 1), (k + 3) * GBK); }
        CP_COMMIT();
        uint32_t base = sb + stg * G_STAGEB;
        uint32_t Ah[4][4], Al[4][4];
#pragma unroll
        for (int mf = 0; mf < 4; mf++) {
            uint32_t addr = base + (uint32_t)((wm*64 + mf*16 + a_row) * G_ROWB) + a_kb;
            ldm_x4(Ah[mf], addr);
            ldm_x4(Al[mf], addr + G_TILEB);
        }
#pragma unroll
        for (int g = 0; g < 2; g++) {
            uint32_t Bf[4][2];
#pragma unroll
            for (int p = 0; p < 2; p++) {
                uint32_t addr = base + 2*G_TILEB
                    + (uint32_t)((wn*64 + (g*4 + p*2 + nsel)*8 + b_row) * G_ROWB) + b_kb;
                uint32_t r4[4];
                ldm_x4(r4, addr);
                Bf[p*2][0] = r4[0]; Bf[p*2][1] = r4[1];
                Bf[p*2+1][0] = r4[2]; Bf[p*2+1][1] = r4[3];
            }
#pragma unroll
            for (int mf = 0; mf < 4; mf++)
#pragma unroll
                for (int nf = 0; nf < 4; nf++) {
                    float* c = acc[mf][g*4 + nf];
                    mma_f16(c, Ah[mf], Bf[nf][0], Bf[nf][1]);
                    mma_f16(c, Al[mf], Bf[nf][0], Bf[nf][1]);
                }
        }
    }

    int rr = lane >> 2, cp = lane & 3;
    if (MODE == 1) {
#pragma unroll
        for (int mf = 0; mf < 4; mf++)
#pragma unroll
            for (int j = 0; j < 4; j++) {
                int d = cp * 2 + (j & 1);
                int row = bm + wm*64 + mf*16 + rr + ((j >> 1) * 8);
                int pos = row & (S - 1);
                float invf = __powf(10000.f, -(float)d * 0.125f);
                float sn, cs; sincosf(pos * invf, &sn, &cs);
                float x1 = acc[mf][0][j], x2 = acc[mf][1][j];
                acc[mf][0][j] = x1 * cs - x2 * sn;
                acc[mf][1][j] = x2 * cs + x1 * sn;
            }
    }
#pragma unroll
    for (int mf = 0; mf < 4; mf++) {
        int row0 = bm + wm*64 + mf*16 + rr;
#pragma unroll
        for (int nf = 0; nf < 8; nf++) {
            int col = bn + wn*64 + nf*8 + cp*2;
            float* c = acc[mf][nf];
            size_t o0 = (size_t)row0 * N + col;
            size_t o1 = (size_t)(row0 + 8) * N + col;
            if (MODE == 0) {
                float2 v0 = make_float2(c[0], c[1]);
                float2 v1 = make_float2(c[2], c[3]);
                if (Res) {
                    float2 e0 = *(const float2*)(Res + o0);
                    float2 e1 = *(const float2*)(Res + o1);
                    v0.x += e0.x; v0.y += e0.y; v1.x += e1.x; v1.y += e1.y;
                }
                *(float2*)(C + o0) = v0;
                *(float2*)(C + o1) = v1;
            } else {
                float v0 = c[0], v1 = c[1], v2 = c[2], v3 = c[3];
                if (MODE == 3) {
                    float2 g0 = *(const float2*)(Res + o0);
                    float2 g1 = *(const float2*)(Res + o1);
                    v0 *= g0.x / (1.f + __expf(-g0.x));
                    v1 *= g0.y / (1.f + __expf(-g0.y));
                    v2 *= g1.x / (1.f + __expf(-g1.x));
                    v3 *= g1.y / (1.f + __expf(-g1.y));
                } else {
                    v0 *= scale; v1 *= scale; v2 *= scale; v3 *= scale;
                }
                uint32_t h0, l0, h1, l1;
                if (MODE == 3) { split2h(v0, v1, h0, l0); split2h(v2, v3, h1, l1); }
                else           { split2b(v0, v1, h0, l0); split2b(v2, v3, h1, l1); }
                uint32_t* OH = (uint32_t*)OHv;
                uint32_t* OL = (uint32_t*)OLv;
                // o0/o1 are element offsets; each uint32 covers 2 elements
                *(uint32_t*)((uint16_t*)OHv + o0) = h0;
                *(uint32_t*)((uint16_t*)OLv + o0) = l0;
                *(uint32_t*)((uint16_t*)OHv + o1) = h1;
                *(uint32_t*)((uint16_t*)OLv + o1) = l1;
                (void)OH; (void)OL;
            }
        }
    }
}

// ------------- flash attention via mma.sync (bf16 3-term, fp16 hi/lo out) -------------
#define A_PITCH 144
#define A_SQH 0u
#define A_SQL 9216u
#define A_SKH 18432u
#define A_SKL 36864u
#define A_SVH 55296u
#define A_SVL 73728u
#define A_SMS 92160u
#define A_SLS 92416u
#define A_DSMEM 92672

__global__ __launch_bounds__(128)
void attn_mma_kernel(const bf16* __restrict__ Qh, const bf16* __restrict__ Ql,
                     const bf16* __restrict__ Kh, const bf16* __restrict__ Kl,
                     const bf16* __restrict__ Vh, const bf16* __restrict__ Vl,
                     __half* __restrict__ OH, __half* __restrict__ OL)
{
    extern __shared__ char sm[];
    uint32_t sb = smem_u32(sm);
    const int qb = blockIdx.x, h = blockIdx.y;
    const int tid = threadIdx.x, wid = tid >> 5, lane = tid & 31;
    const int m0 = wid * 16;

#pragma unroll
    for (int j = 0; j < 4; j++) {
        int idx = tid + j * 128;
        int row = idx >> 3, c = idx & 7;
        size_t g = (size_t)(qb*64 + row) * Dm + h*64 + c*8;
        *(uint4*)(sm + A_SQH + row*A_PITCH + c*16) = *(const uint4*)(Qh + g);
        *(uint4*)(sm + A_SQL + row*A_PITCH + c*16) = *(const uint4*)(Ql + g);
    }
    auto loadKV = [&](int kb, int st) {
        uint32_t o = (uint32_t)st * 9216u;
#pragma unroll
        for (int j = 0; j < 4; j++) {
            int idx = tid + j * 128;
            int row = idx >> 3, c = idx & 7;
            size_t g = (size_t)(kb*64 + row) * Dm + h*64 + c*8;
            uint32_t d = o + row*A_PITCH + c*16;
            CP_ASYNC16(sb + A_SKH + d, Kh + g);
            CP_ASYNC16(sb + A_SKL + d, Kl + g);
            CP_ASYNC16(sb + A_SVH + d, Vh + g);
            CP_ASYNC16(sb + A_SVL + d, Vl + g);
        }
    };
    loadKV(0, 0); CP_COMMIT();
    __syncthreads();

    uint32_t qfh[4][4], qfl[4][4];
    {
        int a_row = lane & 15, koff = (lane >> 4) * 16;
#pragma unroll
        for (int kk = 0; kk < 4; kk++) {
            uint32_t ad = sb + A_SQH + (uint32_t)(m0 + a_row) * A_PITCH + kk*32 + koff;
            ldm_x4(qfh[kk], ad);
            ldm_x4(qfl[kk], ad + 9216u);
        }
    }

    float oacc[8][4];
#pragma unroll
    for (int nf = 0; nf < 8; nf++)
#pragma unroll
        for (int t = 0; t < 4; t++) oacc[nf][t] = 0.f;
    float mi0 = -1e30f, mi1 = -1e30f, li0 = 0.f, li1 = 0.f;
    const int r_l = lane >> 2, cq = (lane & 3) * 2;

    for (int kb = 0; kb <= qb; kb++) {
        if (kb < qb) loadKV(kb + 1, (kb + 1) & 1);
        CP_COMMIT();
        CP_WAIT1();
        __syncthreads();
        uint32_t st = (uint32_t)(kb & 1) * 9216u;

        float sf[8][4];
#pragma unroll
        for (int nf = 0; nf < 8; nf++)
#pragma unroll
            for (int t = 0; t < 4; t++) sf[nf][t] = 0.f;
        {
            int b_row = lane & 7, b_kb = ((lane >> 3) & 1) * 16, nsel = (lane >> 4) & 1;
#pragma unroll
            for (int kk = 0; kk < 4; kk++) {
                uint32_t bh[8][2], bl[8][2];
#pragma unroll
                for (int g = 0; g < 2; g++)
#pragma unroll
                    for (int p = 0; p < 2; p++) {
                        uint32_t ad = sb + A_SKH + st
                            + (uint32_t)(((g*4 + p*2 + nsel)*8 + b_row)) * A_PITCH
                            + kk*32 + b_kb;
                        uint32_t r4[4];
                        ldm_x4(r4, ad);
                        int f = g*4 + p*2;
                        bh[f][0] = r4[0]; bh[f][1] = r4[1];
                        bh[f+1][0] = r4[2]; bh[f+1][1] = r4[3];
                        ldm_x4(r4, ad + (A_SKL - A_SKH));
                        bl[f][0] = r4[0]; bl[f][1] = r4[1];
                        bl[f+1][0] = r4[2]; bl[f+1][1] = r4[3];
                    }
#pragma unroll
                for (int nf = 0; nf < 8; nf++) mma_bf16(sf[nf], qfh[kk], bh[nf][0], bh[nf][1]);
#pragma unroll
                for (int nf = 0; nf < 8; nf++) mma_bf16(sf[nf], qfl[kk], bh[nf][0], bh[nf][1]);
#pragma unroll
                for (int nf = 0; nf < 8; nf++) mma_bf16(sf[nf], qfh[kk], bl[nf][0], bl[nf][1]);
            }
        }
        if (kb == qb) {
#pragma unroll
            for (int nf = 0; nf < 8; nf++)
#pragma unroll
                for (int hh = 0; hh < 2; hh++) {
                    int jl = nf*8 + cq + hh;
                    if (jl >= m0 + r_l)     sf[nf][hh]     = -1e30f;
                    if (jl >= m0 + r_l + 8) sf[nf][2 + hh] = -1e30f;
                }
        }
        float mx0 = -1e30f, mx1 = -1e30f;
#pragma unroll
        for (int nf = 0; nf < 8; nf++) {
            mx0 = fmaxf(mx0, fmaxf(sf[nf][0], sf[nf][1]));
            mx1 = fmaxf(mx1, fmaxf(sf[nf][2], sf[nf][3]));
        }
        mx0 = fmaxf(mx0, __shfl_xor_sync(0xffffffffu, mx0, 1));
        mx0 = fmaxf(mx0, __shfl_xor_sync(0xffffffffu, mx0, 2));
        mx1 = fmaxf(mx1, __shfl_xor_sync(0xffffffffu, mx1, 1));
        mx1 = fmaxf(mx1, __shfl_xor_sync(0xffffffffu, mx1, 2));
        float nm0 = fmaxf(mi0, mx0), nm1 = fmaxf(mi1, mx1);
        float sc0 = __expf(mi0 - nm0), sc1 = __expf(mi1 - nm1);
        float sum0 = 0.f, sum1 = 0.f;
#pragma unroll
        for (int nf = 0; nf < 8; nf++) {
            sf[nf][0] = (sf[nf][0] <= -1e29f) ? 0.f : __expf(sf[nf][0] - nm0); sum0 += sf[nf][0];
            sf[nf][1] = (sf[nf][1] <= -1e29f) ? 0.f : __expf(sf[nf][1] - nm0); sum0 += sf[nf][1];
            sf[nf][2] = (sf[nf][2] <= -1e29f) ? 0.f : __expf(sf[nf][2] - nm1); sum1 += sf[nf][2];
            sf[nf][3] = (sf[nf][3] <= -1e29f) ? 0.f : __expf(sf[nf][3] - nm1); sum1 += sf[nf][3];
        }
        sum0 += __shfl_xor_sync(0xffffffffu, sum0, 1);
        sum0 += __shfl_xor_sync(0xffffffffu, sum0, 2);
        sum1 += __shfl_xor_sync(0xffffffffu, sum1, 1);
        sum1 += __shfl_xor_sync(0xffffffffu, sum1, 2);
        li0 = li0 * sc0 + sum0; li1 = li1 * sc1 + sum1;
        mi0 = nm0; mi1 = nm1;
#pragma unroll
        for (int nf = 0; nf < 8; nf++) {
            oacc[nf][0] *= sc0; oacc[nf][1] *= sc0;
            oacc[nf][2] *= sc1; oacc[nf][3] *= sc1;
        }
        {
            int vrow = lane & 15, vcol = (lane >> 4) * 8;
#pragma unroll
            for (int ks = 0; ks < 4; ks++) {
                uint32_t ah[4], al[4];
                split2b(sf[2*ks][0],   sf[2*ks][1],   ah[0], al[0]);
                split2b(sf[2*ks][2],   sf[2*ks][3],   ah[1], al[1]);
                split2b(sf[2*ks+1][0], sf[2*ks+1][1], ah[2], al[2]);
                split2b(sf[2*ks+1][2], sf[2*ks+1][3], ah[3], al[3]);
#pragma unroll
                for (int df = 0; df < 4; df++) {
                    uint32_t vh4[4], vl4[4];
                    uint32_t ad = sb + A_SVH + st
                        + (uint32_t)(ks*16 + vrow) * A_PITCH + (df*16 + vcol) * 2;
                    ldm_x4_t(vh4, ad);
                    ldm_x4_t(vl4, ad + (A_SVL - A_SVH));
                    mma_bf16(oacc[2*df],     ah, vh4[0], vh4[1]);
                    mma_bf16(oacc[2*df + 1], ah, vh4[2], vh4[3]);
                    mma_bf16(oacc[2*df],     al, vh4[0], vh4[1]);
                    mma_bf16(oacc[2*df + 1], al, vh4[2], vh4[3]);
                    mma_bf16(oacc[2*df],     ah, vl4[0], vl4[1]);
                    mma_bf16(oacc[2*df + 1], ah, vl4[2], vl4[3]);
                }
            }
        }
        __syncthreads();
    }

    float* ost = (float*)(sm + A_SKH);
#pragma unroll
    for (int nf = 0; nf < 8; nf++) {
        int c = nf*8 + cq;
        ost[(m0 + r_l) * 72 + c]         = oacc[nf][0];
        ost[(m0 + r_l) * 72 + c + 1]     = oacc[nf][1];
        ost[(m0 + r_l + 8) * 72 + c]     = oacc[nf][2];
        ost[(m0 + r_l + 8) * 72 + c + 1] = oacc[nf][3];
    }
    if ((lane & 3) == 0) {
        ((float*)(sm + A_SMS))[m0 + r_l]     = mi0;
        ((float*)(sm + A_SMS))[m0 + r_l + 8] = mi1;
        ((float*)(sm + A_SLS))[m0 + r_l]     = li0;
        ((float*)(sm + A_SLS))[m0 + r_l + 8] = li1;
    }
    __syncthreads();

    {
        int m = tid >> 1, hf = tid & 1;
        int i = qb*64 + m;
        const __nv_bfloat162* q2h = (const __nv_bfloat162*)(Qh + (size_t)i * Dm + h*64);
        const __nv_bfloat162* q2l = (const __nv_bfloat162*)(Ql + (size_t)i * Dm + h*64);
        const __nv_bfloat162* k2h = (const __nv_bfloat162*)(Kh + (size_t)(S + i) * Dm + h*64);
        const __nv_bfloat162* k2l = (const __nv_bfloat162*)(Kl + (size_t)(S + i) * Dm + h*64);
        float dot = 0.f;
#pragma unroll
        for (int t = 0; t < 32; t++) {
            float2 qa = __bfloat1622float2(q2h[t]);
            float2 qb2 = __bfloat1622float2(q2l[t]);
            float2 ka = __bfloat1622float2(k2h[t]);
            float2 kb = __bfloat1622float2(k2l[t]);
            dot += (qa.x + qb2.x) * (ka.x + kb.x) + (qa.y + qb2.y) * (ka.y + kb.y);
        }
        float ssf = dot;
        float mi = ((float*)(sm + A_SMS))[m];
        float li = ((float*)(sm + A_SLS))[m];
        float nm = fmaxf(mi, ssf);
        float sc = __expf(mi - nm);
        float pp = __expf(ssf - nm);
        float inv = 1.f / (li * sc + pp);
        const __nv_bfloat162* v2h = (const __nv_bfloat162*)(Vh + (size_t)(S + i) * Dm + h*64 + hf*32);
        const __nv_bfloat162* v2l = (const __nv_bfloat162*)(Vl + (size_t)(S + i) * Dm + h*64 + hf*32);
        float* orow = ost + m*72 + hf*32;
        uint32_t hh[8], ll[8];
#pragma unroll
        for (int t = 0; t < 16; t++) {
            float2 va = __bfloat1622float2(v2h[t]);
            float2 vb = __bfloat1622float2(v2l[t]);
            float val0 = (orow[t*2]   * sc + pp * (va.x + vb.x)) * inv;
            float val1 = (orow[t*2+1] * sc + pp * (va.y + vb.y)) * inv;
            split2h(val0, val1, hh[t & 7], ll[t & 7]);
            if ((t & 7) == 7) {
                int t8 = t >> 3;
                *(uint4*)(OH + (size_t)i * Dm + h*64 + hf*32 + t8*16)     = *(uint4*)(hh);
                *(uint4*)(OH + (size_t)i * Dm + h*64 + hf*32 + t8*16 + 8) = *(uint4*)(hh + 4);
                *(uint4*)(OL + (size_t)i * Dm + h*64 + hf*32 + t8*16)     = *(uint4*)(ll);
                *(uint4*)(OL + (size_t)i * Dm + h*64 + hf*32 + t8*16 + 8) = *(uint4*)(ll + 4);
            }
        }
    }
}

// ------------- launch -------------
extern "C" void kernel_launch(void* const* d_in, const int* in_sizes, int n_in,
                              void* d_out, int out_size)
{
    const float* hidden = (const float*)d_in[0];
    const float* memory = (const float*)d_in[1];
    const float* ln1w = (const float*)d_in[4];
    const float* ln1b = (const float*)d_in[5];
    const float* ln2w = (const float*)d_in[6];
    const float* ln2b = (const float*)d_in[7];
    const float* Wq = (const float*)d_in[8];
    const float* Wk = (const float*)d_in[9];
    const float* Wv = (const float*)d_in[10];
    const float* Wo = (const float*)d_in[11];
    const float* Wg = (const float*)d_in[12];
    const float* Wu = (const float*)d_in[13];
    const float* Wd = (const float*)d_in[14];
    float* out = (float*)d_out;

    void* p;
    cudaGetSymbolAddress(&p, g_xh);  __half* xh = (__half*)p;
    cudaGetSymbolAddress(&p, g_xl);  __half* xl = (__half*)p;
    cudaGetSymbolAddress(&p, g_qh);  bf16* qh = (bf16*)p;
    cudaGetSymbolAddress(&p, g_ql);  bf16* ql = (bf16*)p;
    cudaGetSymbolAddress(&p, g_kh);  bf16* kh = (bf16*)p;
    cudaGetSymbolAddress(&p, g_kl);  bf16* kl = (bf16*)p;
    cudaGetSymbolAddress(&p, g_vh);  bf16* vh = (bf16*)p;
    cudaGetSymbolAddress(&p, g_vl);  bf16* vl = (bf16*)p;
    cudaGetSymbolAddress(&p, g_ah);  __half* ah = (__half*)p;
    cudaGetSymbolAddress(&p, g_al);  __half* al = (__half*)p;
    cudaGetSymbolAddress(&p, g_h);   float* hbuf = (float*)p;
    cudaGetSymbolAddress(&p, g_h2h); __half* h2h = (__half*)p;
    cudaGetSymbolAddress(&p, g_h2l); __half* h2l = (__half*)p;
    cudaGetSymbolAddress(&p, g_gr);  float* gr = (float*)p;
    cudaGetSymbolAddress(&p, g_gh);  __half* gh = (__half*)p;
    cudaGetSymbolAddress(&p, g_gl);  __half* gl = (__half*)p;
    cudaGetSymbolAddress(&p, g_wq);  __half* wq = (__half*)p;
    cudaGetSymbolAddress(&p, g_wk);  __half* wk = (__half*)p;
    cudaGetSymbolAddress(&p, g_wv);  __half* wv = (__half*)p;
    cudaGetSymbolAddress(&p, g_wo);  __half* wo = (__half*)p;
    cudaGetSymbolAddress(&p, g_wg);  __half* wg = (__half*)p;
    cudaGetSymbolAddress(&p, g_wu);  __half* wu = (__half*)p;
    cudaGetSymbolAddress(&p, g_wd);  __half* wd = (__half*)p;

    cudaFuncSetAttribute(gemm2<0>, cudaFuncAttributeMaxDynamicSharedMemorySize, G_DSMEM);
    cudaFuncSetAttribute(gemm2<1>, cudaFuncAttributeMaxDynamicSharedMemorySize, G_DSMEM);
    cudaFuncSetAttribute(gemm2<2>, cudaFuncAttributeMaxDynamicSharedMemorySize, G_DSMEM);
    cudaFuncSetAttribute(gemm2<3>, cudaFuncAttributeMaxDynamicSharedMemorySize, G_DSMEM);
    cudaFuncSetAttribute(attn_mma_kernel, cudaFuncAttributeMaxDynamicSharedMemorySize, A_DSMEM);

    ln_split_kernel<<<S, 256>>>(memory, ln1w, ln1b, xh, xl);
    ln_split_kernel<<<S, 256>>>(hidden, ln1w, ln1b, xh + (size_t)S * Dm, xl + (size_t)S * Dm);

    int nDD = Dm * Dm / 4, nFD = FF * Dm / 4;
    conv_kernel<<<nDD / 256, 256>>>(Wq, wq, nDD);
    conv_kernel<<<nDD / 256, 256>>>(Wk, wk, nDD);
    conv_kernel<<<nDD / 256, 256>>>(Wv, wv, nDD);
    conv_kernel<<<nDD / 256, 256>>>(Wo, wo, nDD);
    conv_kernel<<<nFD / 256, 256>>>(Wg, wg, nFD);
    conv_kernel<<<nFD / 256, 256>>>(Wu, wu, nFD);
    conv_kernel<<<nFD / 256, 256>>>(Wd, wd, nFD);

    {
        dim3 gKV(Dm / 128, L / 128);
        gemm2<1><<<gKV, 128, G_DSMEM>>>(xh, xl, wk, nullptr, nullptr, kh, kl, 1.0f, L, Dm, Dm);
        gemm2<2><<<gKV, 128, G_DSMEM>>>(xh, xl, wv, nullptr, nullptr, vh, vl, 1.0f, L, Dm, Dm);
        dim3 gQ(Dm / 128, S / 128);
        gemm2<1><<<gQ, 128, G_DSMEM>>>(xh + (size_t)S * Dm, xl + (size_t)S * Dm,
                                       wq, nullptr, nullptr, qh, ql, 0.125f, S, Dm, Dm);
    }

    {
        dim3 g(S / 64, NH);
        attn_mma_kernel<<<g, 128, A_DSMEM>>>(qh, ql, kh, kl, vh, vl, ah, al);
    }

    {
        dim3 g(Dm / 128, S / 128);
        gemm2<0><<<g, 128, G_DSMEM>>>(ah, al, wo, hidden, hbuf, nullptr, nullptr, 1.0f, S, Dm, Dm);
    }
    ln_split_kernel<<<S, 256>>>(hbuf, ln2w, ln2b, h2h, h2l);
    {
        dim3 g(FF / 128, S / 128);
        gemm2<0><<<g, 128, G_DSMEM>>>(h2h, h2l, wg, nullptr, gr, nullptr, nullptr, 1.0f, S, FF, Dm);
        gemm2<3><<<g, 128, G_DSMEM>>>(h2h, h2l, wu, gr, nullptr, gh, gl, 1.0f, S, FF, Dm);
    }
    {
        dim3 g(Dm / 128, S / 128);
        gemm2<0><<<g, 128, G_DSMEM>>>(gh, gl, wd, hbuf, out, nullptr, nullptr, 1.0f, S, Dm, FF);
    }
}

// round 10
// speedup vs baseline: 3.8810x; 1.4485x over previous
#include <cuda_runtime.h>
#include <cuda_bf16.h>
#include <cuda_fp16.h>
#include <cstdint>

#define S    2048
#define Dm   2048
#define FF   8192
#define NH   32
#define HD   64
#define L    4096

typedef __nv_bfloat16 bf16;

__device__ __forceinline__ uint32_t smem_u32(const void* p) {
    uint32_t a;
    asm("{ .reg .u64 t; cvta.to.shared.u64 t, %1; cvt.u32.u64 %0, t; }" : "=r"(a) : "l"(p));
    return a;
}
__device__ __forceinline__ void ldm_x4(uint32_t* r, uint32_t a) {
    asm volatile("ldmatrix.sync.aligned.m8n8.x4.shared.b16 {%0,%1,%2,%3}, [%4];"
        : "=r"(r[0]), "=r"(r[1]), "=r"(r[2]), "=r"(r[3]) : "r"(a));
}
__device__ __forceinline__ void ldm_x4_t(uint32_t* r, uint32_t a) {
    asm volatile("ldmatrix.sync.aligned.m8n8.x4.trans.shared.b16 {%0,%1,%2,%3}, [%4];"
        : "=r"(r[0]), "=r"(r[1]), "=r"(r[2]), "=r"(r[3]) : "r"(a));
}
__device__ __forceinline__ void mma_bf16(float* c, const uint32_t* a, uint32_t b0, uint32_t b1) {
    asm volatile("mma.sync.aligned.m16n8k16.row.col.f32.bf16.bf16.f32 "
        "{%0,%1,%2,%3}, {%4,%5,%6,%7}, {%8,%9}, {%0,%1,%2,%3};"
        : "+f"(c[0]), "+f"(c[1]), "+f"(c[2]), "+f"(c[3])
        : "r"(a[0]), "r"(a[1]), "r"(a[2]), "r"(a[3]), "r"(b0), "r"(b1));
}
__device__ __forceinline__ void mma_f16(float* c, const uint32_t* a, uint32_t b0, uint32_t b1) {
    asm volatile("mma.sync.aligned.m16n8k16.row.col.f32.f16.f16.f32 "
        "{%0,%1,%2,%3}, {%4,%5,%6,%7}, {%8,%9}, {%0,%1,%2,%3};"
        : "+f"(c[0]), "+f"(c[1]), "+f"(c[2]), "+f"(c[3])
        : "r"(a[0]), "r"(a[1]), "r"(a[2]), "r"(a[3]), "r"(b0), "r"(b1));
}
__device__ __forceinline__ uint32_t pack_bf16(float a, float b) {
    __nv_bfloat162 t; t.x = __float2bfloat16_rn(a); t.y = __float2bfloat16_rn(b);
    return *(uint32_t*)&t;
}
__device__ __forceinline__ uint32_t pack_f16(float a, float b) {
    __half2 t; t.x = __float2half_rn(a); t.y = __float2half_rn(b);
    return *(uint32_t*)&t;
}
__device__ __forceinline__ void split2b(float a, float b, uint32_t& h, uint32_t& l) {
    bf16 ha = __float2bfloat16_rn(a), hb = __float2bfloat16_rn(b);
    __nv_bfloat162 hv; hv.x = ha; hv.y = hb;
    h = *(uint32_t*)&hv;
    l = pack_bf16(a - __bfloat162float(ha), b - __bfloat162float(hb));
}
#define CP_ASYNC16(dst, src) \
    asm volatile("cp.async.cg.shared.global [%0], [%1], 16;" :: "r"(dst), "l"(src))
#define CP_COMMIT() asm volatile("cp.async.commit_group;" ::: "memory")
#define CP_WAIT1()  asm volatile("cp.async.wait_group 1;" ::: "memory")
#define CP_WAIT2()  asm volatile("cp.async.wait_group 2;" ::: "memory")

// ------------- scratch -------------
__device__ __half g_x  [L * Dm];              // ln1 out, single fp16
__device__ bf16   g_qh [S * Dm]; __device__ bf16 g_ql [S * Dm];
__device__ bf16   g_kh [L * Dm]; __device__ bf16 g_kl [L * Dm];
__device__ bf16   g_vh [L * Dm]; __device__ bf16 g_vl [L * Dm];
__device__ __half g_a  [S * Dm];              // attn out, single fp16
__device__ float  g_h  [S * Dm];
__device__ __half g_h2 [S * Dm];
__device__ float  g_gr [S * FF];
__device__ __half g_g  [S * FF];
__device__ __half g_wq[Dm * Dm];
__device__ __half g_wk[Dm * Dm];
__device__ __half g_wv[Dm * Dm];
__device__ __half g_wo[Dm * Dm];
__device__ __half g_wg[FF * Dm];
__device__ __half g_wu[FF * Dm];
__device__ __half g_wd[Dm * FF];

// ------------- fp32 -> fp16 convert -------------
__global__ __launch_bounds__(256) void conv_kernel(
    const float* __restrict__ X, __half* __restrict__ H, int n4)
{
    int i = blockIdx.x * blockDim.x + threadIdx.x;
    if (i >= n4) return;
    float4 x = ((const float4*)X)[i];
    uint2 o; o.x = pack_f16(x.x, x.y); o.y = pack_f16(x.z, x.w);
    ((uint2*)H)[i] = o;
}

// ------------- LayerNorm -> single fp16 -------------
__global__ __launch_bounds__(256) void ln_conv_kernel(
    const float* __restrict__ X, const float* __restrict__ w,
    const float* __restrict__ b, __half* __restrict__ O)
{
    int row = blockIdx.x, tid = threadIdx.x;
    const float* xr = X + (size_t)row * Dm;
    float4 a = ((const float4*)xr)[tid * 2];
    float4 c = ((const float4*)xr)[tid * 2 + 1];
    float s  = a.x + a.y + a.z + a.w + c.x + c.y + c.z + c.w;
    float ss = a.x*a.x + a.y*a.y + a.z*a.z + a.w*a.w
             + c.x*c.x + c.y*c.y + c.z*c.z + c.w*c.w;
#pragma unroll
    for (int o = 16; o; o >>= 1) {
        s  += __shfl_xor_sync(0xffffffffu, s,  o);
        ss += __shfl_xor_sync(0xffffffffu, ss, o);
    }
    __shared__ float bs[8], bss[8];
    if ((tid & 31) == 0) { bs[tid >> 5] = s; bss[tid >> 5] = ss; }
    __syncthreads();
    float ts = 0.f, tss = 0.f;
#pragma unroll
    for (int i = 0; i < 8; i++) { ts += bs[i]; tss += bss[i]; }
    float mean = ts * (1.f / Dm);
    float inv  = rsqrtf(tss * (1.f / Dm) - mean * mean + 1e-5f);
    int d = tid * 8;
    float4 w0 = ((const float4*)w)[tid*2], w1 = ((const float4*)w)[tid*2+1];
    float4 b0 = ((const float4*)b)[tid*2], b1 = ((const float4*)b)[tid*2+1];
    float v8[8];
    v8[0]=(a.x-mean)*inv*w0.x+b0.x; v8[1]=(a.y-mean)*inv*w0.y+b0.y;
    v8[2]=(a.z-mean)*inv*w0.z+b0.z; v8[3]=(a.w-mean)*inv*w0.w+b0.w;
    v8[4]=(c.x-mean)*inv*w1.x+b1.x; v8[5]=(c.y-mean)*inv*w1.y+b1.y;
    v8[6]=(c.z-mean)*inv*w1.z+b1.z; v8[7]=(c.w-mean)*inv*w1.w+b1.w;
    uint4 o;
    o.x = pack_f16(v8[0], v8[1]); o.y = pack_f16(v8[2], v8[3]);
    o.z = pack_f16(v8[4], v8[5]); o.w = pack_f16(v8[6], v8[7]);
    *(uint4*)(O + (size_t)row * Dm + d) = o;
}

// ------------- GEMM: single-term fp16, 4-stage, 4 warps x 64x64 -------------
// MODE 0: fp32 (+Res) | 1: rope+scale -> bf16 hi/lo | 2: bf16 hi/lo | 3: silu(Res)*acc -> fp16
#define GBK 16
#define G_ROWB 48
#define G_TILEB (128 * G_ROWB)            // 6144
#define G_STAGEB (2 * G_TILEB)            // 12288 (A, B)
#define G_NST 4
#define G_DSMEM (G_NST * G_STAGEB)        // 49152

template<int MODE>
__global__ __launch_bounds__(128, 2)
void gemm1(const __half* __restrict__ A, const __half* __restrict__ B,
           const float* __restrict__ Res, float* __restrict__ C,
           void* __restrict__ OHv, void* __restrict__ OLv,
           float scale, int M, int N, int K)
{
    extern __shared__ char smem[];
    uint32_t sb = smem_u32(smem);
    int tid  = threadIdx.x, wid = tid >> 5, lane = tid & 31;
    int wm = wid & 1, wn = wid >> 1;
    int bm = blockIdx.y * 128, bn = blockIdx.x * 128;

    auto loadChunk = [&](int stg, int k0) {
        uint32_t base = sb + stg * G_STAGEB;
#pragma unroll
        for (int h = 0; h < 2; h++) {
            int idx = tid + h * 128;
            int r = idx >> 1, c = idx & 1;
            uint32_t doff = r * G_ROWB + c * 16;
            size_t soff = (size_t)r * K + k0 + c * 8;
            CP_ASYNC16(base + doff,           A + (size_t)bm * K + soff);
            CP_ASYNC16(base + G_TILEB + doff, B + (size_t)bn * K + soff);
        }
    };

    float acc[4][8][4];
#pragma unroll
    for (int i = 0; i < 4; i++)
#pragma unroll
        for (int j = 0; j < 8; j++)
#pragma unroll
            for (int t = 0; t < 4; t++) acc[i][j][t] = 0.f;

    int NKC = K / GBK;
    loadChunk(0, 0);        CP_COMMIT();
    loadChunk(1, GBK);      CP_COMMIT();
    loadChunk(2, 2 * GBK);  CP_COMMIT();

    int a_row = lane & 15;
    int a_kb  = (lane >> 4) * 16;
    int b_row = lane & 7;
    int b_kb  = ((lane >> 3) & 1) * 16;
    int nsel  = (lane >> 4) & 1;

    for (int k = 0; k < NKC; k++) {
        int stg = k & (G_NST - 1);
        CP_WAIT2();
        __syncthreads();
        if (k + 3 < NKC) { loadChunk((k + 3) & (G_NST - 1), (k + 3) * GBK); }
        CP_COMMIT();
        uint32_t base = sb + stg * G_STAGEB;
        uint32_t Af[4][4];
#pragma unroll
        for (int mf = 0; mf < 4; mf++) {
            uint32_t addr = base + (uint32_t)((wm*64 + mf*16 + a_row) * G_ROWB) + a_kb;
            ldm_x4(Af[mf], addr);
        }
#pragma unroll
        for (int g = 0; g < 2; g++) {
            uint32_t Bf[4][2];
#pragma unroll
            for (int p = 0; p < 2; p++) {
                uint32_t addr = base + G_TILEB
                    + (uint32_t)((wn*64 + (g*4 + p*2 + nsel)*8 + b_row) * G_ROWB) + b_kb;
                uint32_t r4[4];
                ldm_x4(r4, addr);
                Bf[p*2][0] = r4[0]; Bf[p*2][1] = r4[1];
                Bf[p*2+1][0] = r4[2]; Bf[p*2+1][1] = r4[3];
            }
#pragma unroll
            for (int mf = 0; mf < 4; mf++)
#pragma unroll
                for (int nf = 0; nf < 4; nf++)
                    mma_f16(acc[mf][g*4 + nf], Af[mf], Bf[nf][0], Bf[nf][1]);
        }
    }

    int rr = lane >> 2, cp = lane & 3;
    if (MODE == 1) {
#pragma unroll
        for (int mf = 0; mf < 4; mf++)
#pragma unroll
            for (int j = 0; j < 4; j++) {
                int d = cp * 2 + (j & 1);
                int row = bm + wm*64 + mf*16 + rr + ((j >> 1) * 8);
                int pos = row & (S - 1);
                float invf = __powf(10000.f, -(float)d * 0.125f);
                float sn, cs; sincosf(pos * invf, &sn, &cs);
                float x1 = acc[mf][0][j], x2 = acc[mf][1][j];
                acc[mf][0][j] = x1 * cs - x2 * sn;
                acc[mf][1][j] = x2 * cs + x1 * sn;
            }
    }
#pragma unroll
    for (int mf = 0; mf < 4; mf++) {
        int row0 = bm + wm*64 + mf*16 + rr;
#pragma unroll
        for (int nf = 0; nf < 8; nf++) {
            int col = bn + wn*64 + nf*8 + cp*2;
            float* c = acc[mf][nf];
            size_t o0 = (size_t)row0 * N + col;
            size_t o1 = (size_t)(row0 + 8) * N + col;
            if (MODE == 0) {
                float2 v0 = make_float2(c[0], c[1]);
                float2 v1 = make_float2(c[2], c[3]);
                if (Res) {
                    float2 e0 = *(const float2*)(Res + o0);
                    float2 e1 = *(const float2*)(Res + o1);
                    v0.x += e0.x; v0.y += e0.y; v1.x += e1.x; v1.y += e1.y;
                }
                *(float2*)(C + o0) = v0;
                *(float2*)(C + o1) = v1;
            } else if (MODE == 3) {
                float2 g0 = *(const float2*)(Res + o0);
                float2 g1 = *(const float2*)(Res + o1);
                float v0 = c[0] * g0.x / (1.f + __expf(-g0.x));
                float v1 = c[1] * g0.y / (1.f + __expf(-g0.y));
                float v2 = c[2] * g1.x / (1.f + __expf(-g1.x));
                float v3 = c[3] * g1.y / (1.f + __expf(-g1.y));
                *(uint32_t*)((uint16_t*)OHv + o0) = pack_f16(v0, v1);
                *(uint32_t*)((uint16_t*)OHv + o1) = pack_f16(v2, v3);
            } else {
                float v0 = c[0] * scale, v1 = c[1] * scale;
                float v2 = c[2] * scale, v3 = c[3] * scale;
                uint32_t h0, l0, h1, l1;
                split2b(v0, v1, h0, l0);
                split2b(v2, v3, h1, l1);
                *(uint32_t*)((uint16_t*)OHv + o0) = h0;
                *(uint32_t*)((uint16_t*)OLv + o0) = l0;
                *(uint32_t*)((uint16_t*)OHv + o1) = h1;
                *(uint32_t*)((uint16_t*)OLv + o1) = l1;
            }
        }
    }
}

// ------------- flash attention (bf16 3-term internal, fp16 out) -------------
#define A_PITCH 144
#define A_SQH 0u
#define A_SQL 9216u
#define A_SKH 18432u
#define A_SKL 36864u
#define A_SVH 55296u
#define A_SVL 73728u
#define A_SMS 92160u
#define A_SLS 92416u
#define A_DSMEM 92672

__global__ __launch_bounds__(128)
void attn_mma_kernel(const bf16* __restrict__ Qh, const bf16* __restrict__ Ql,
                     const bf16* __restrict__ Kh, const bf16* __restrict__ Kl,
                     const bf16* __restrict__ Vh, const bf16* __restrict__ Vl,
                     __half* __restrict__ O)
{
    extern __shared__ char sm[];
    uint32_t sb = smem_u32(sm);
    const int qb = blockIdx.x, h = blockIdx.y;
    const int tid = threadIdx.x, wid = tid >> 5, lane = tid & 31;
    const int m0 = wid * 16;

#pragma unroll
    for (int j = 0; j < 4; j++) {
        int idx = tid + j * 128;
        int row = idx >> 3, c = idx & 7;
        size_t g = (size_t)(qb*64 + row) * Dm + h*64 + c*8;
        *(uint4*)(sm + A_SQH + row*A_PITCH + c*16) = *(const uint4*)(Qh + g);
        *(uint4*)(sm + A_SQL + row*A_PITCH + c*16) = *(const uint4*)(Ql + g);
    }
    auto loadKV = [&](int kb, int st) {
        uint32_t o = (uint32_t)st * 9216u;
#pragma unroll
        for (int j = 0; j < 4; j++) {
            int idx = tid + j * 128;
            int row = idx >> 3, c = idx & 7;
            size_t g = (size_t)(kb*64 + row) * Dm + h*64 + c*8;
            uint32_t d = o + row*A_PITCH + c*16;
            CP_ASYNC16(sb + A_SKH + d, Kh + g);
            CP_ASYNC16(sb + A_SKL + d, Kl + g);
            CP_ASYNC16(sb + A_SVH + d, Vh + g);
            CP_ASYNC16(sb + A_SVL + d, Vl + g);
        }
    };
    loadKV(0, 0); CP_COMMIT();
    __syncthreads();

    uint32_t qfh[4][4], qfl[4][4];
    {
        int a_row = lane & 15, koff = (lane >> 4) * 16;
#pragma unroll
        for (int kk = 0; kk < 4; kk++) {
            uint32_t ad = sb + A_SQH + (uint32_t)(m0 + a_row) * A_PITCH + kk*32 + koff;
            ldm_x4(qfh[kk], ad);
            ldm_x4(qfl[kk], ad + 9216u);
        }
    }

    float oacc[8][4];
#pragma unroll
    for (int nf = 0; nf < 8; nf++)
#pragma unroll
        for (int t = 0; t < 4; t++) oacc[nf][t] = 0.f;
    float mi0 = -1e30f, mi1 = -1e30f, li0 = 0.f, li1 = 0.f;
    const int r_l = lane >> 2, cq = (lane & 3) * 2;

    for (int kb = 0; kb <= qb; kb++) {
        if (kb < qb) loadKV(kb + 1, (kb + 1) & 1);
        CP_COMMIT();
        CP_WAIT1();
        __syncthreads();
        uint32_t st = (uint32_t)(kb & 1) * 9216u;

        float sf[8][4];
#pragma unroll
        for (int nf = 0; nf < 8; nf++)
#pragma unroll
            for (int t = 0; t < 4; t++) sf[nf][t] = 0.f;
        {
            int b_row = lane & 7, b_kb = ((lane >> 3) & 1) * 16, nsel = (lane >> 4) & 1;
#pragma unroll
            for (int kk = 0; kk < 4; kk++) {
                uint32_t bh[8][2], bl[8][2];
#pragma unroll
                for (int g = 0; g < 2; g++)
#pragma unroll
                    for (int p = 0; p < 2; p++) {
                        uint32_t ad = sb + A_SKH + st
                            + (uint32_t)(((g*4 + p*2 + nsel)*8 + b_row)) * A_PITCH
                            + kk*32 + b_kb;
                        uint32_t r4[4];
                        ldm_x4(r4, ad);
                        int f = g*4 + p*2;
                        bh[f][0] = r4[0]; bh[f][1] = r4[1];
                        bh[f+1][0] = r4[2]; bh[f+1][1] = r4[3];
                        ldm_x4(r4, ad + (A_SKL - A_SKH));
                        bl[f][0] = r4[0]; bl[f][1] = r4[1];
                        bl[f+1][0] = r4[2]; bl[f+1][1] = r4[3];
                    }
#pragma unroll
                for (int nf = 0; nf < 8; nf++) mma_bf16(sf[nf], qfh[kk], bh[nf][0], bh[nf][1]);
#pragma unroll
                for (int nf = 0; nf < 8; nf++) mma_bf16(sf[nf], qfl[kk], bh[nf][0], bh[nf][1]);
#pragma unroll
                for (int nf = 0; nf < 8; nf++) mma_bf16(sf[nf], qfh[kk], bl[nf][0], bl[nf][1]);
            }
        }
        if (kb == qb) {
#pragma unroll
            for (int nf = 0; nf < 8; nf++)
#pragma unroll
                for (int hh = 0; hh < 2; hh++) {
                    int jl = nf*8 + cq + hh;
                    if (jl >= m0 + r_l)     sf[nf][hh]     = -1e30f;
                    if (jl >= m0 + r_l + 8) sf[nf][2 + hh] = -1e30f;
                }
        }
        float mx0 = -1e30f, mx1 = -1e30f;
#pragma unroll
        for (int nf = 0; nf < 8; nf++) {
            mx0 = fmaxf(mx0, fmaxf(sf[nf][0], sf[nf][1]));
            mx1 = fmaxf(mx1, fmaxf(sf[nf][2], sf[nf][3]));
        }
        mx0 = fmaxf(mx0, __shfl_xor_sync(0xffffffffu, mx0, 1));
        mx0 = fmaxf(mx0, __shfl_xor_sync(0xffffffffu, mx0, 2));
        mx1 = fmaxf(mx1, __shfl_xor_sync(0xffffffffu, mx1, 1));
        mx1 = fmaxf(mx1, __shfl_xor_sync(0xffffffffu, mx1, 2));
        float nm0 = fmaxf(mi0, mx0), nm1 = fmaxf(mi1, mx1);
        float sc0 = __expf(mi0 - nm0), sc1 = __expf(mi1 - nm1);
        float sum0 = 0.f, sum1 = 0.f;
#pragma unroll
        for (int nf = 0; nf < 8; nf++) {
            sf[nf][0] = (sf[nf][0] <= -1e29f) ? 0.f : __expf(sf[nf][0] - nm0); sum0 += sf[nf][0];
            sf[nf][1] = (sf[nf][1] <= -1e29f) ? 0.f : __expf(sf[nf][1] - nm0); sum0 += sf[nf][1];
            sf[nf][2] = (sf[nf][2] <= -1e29f) ? 0.f : __expf(sf[nf][2] - nm1); sum1 += sf[nf][2];
            sf[nf][3] = (sf[nf][3] <= -1e29f) ? 0.f : __expf(sf[nf][3] - nm1); sum1 += sf[nf][3];
        }
        sum0 += __shfl_xor_sync(0xffffffffu, sum0, 1);
        sum0 += __shfl_xor_sync(0xffffffffu, sum0, 2);
        sum1 += __shfl_xor_sync(0xffffffffu, sum1, 1);
        sum1 += __shfl_xor_sync(0xffffffffu, sum1, 2);
        li0 = li0 * sc0 + sum0; li1 = li1 * sc1 + sum1;
        mi0 = nm0; mi1 = nm1;
#pragma unroll
        for (int nf = 0; nf < 8; nf++) {
            oacc[nf][0] *= sc0; oacc[nf][1] *= sc0;
            oacc[nf][2] *= sc1; oacc[nf][3] *= sc1;
        }
        {
            int vrow = lane & 15, vcol = (lane >> 4) * 8;
#pragma unroll
            for (int ks = 0; ks < 4; ks++) {
                uint32_t ah[4], al[4];
                split2b(sf[2*ks][0],   sf[2*ks][1],   ah[0], al[0]);
                split2b(sf[2*ks][2],   sf[2*ks][3],   ah[1], al[1]);
                split2b(sf[2*ks+1][0], sf[2*ks+1][1], ah[2], al[2]);
                split2b(sf[2*ks+1][2], sf[2*ks+1][3], ah[3], al[3]);
#pragma unroll
                for (int df = 0; df < 4; df++) {
                    uint32_t vh4[4], vl4[4];
                    uint32_t ad = sb + A_SVH + st
                        + (uint32_t)(ks*16 + vrow) * A_PITCH + (df*16 + vcol) * 2;
                    ldm_x4_t(vh4, ad);
                    ldm_x4_t(vl4, ad + (A_SVL - A_SVH));
                    mma_bf16(oacc[2*df],     ah, vh4[0], vh4[1]);
                    mma_bf16(oacc[2*df + 1], ah, vh4[2], vh4[3]);
                    mma_bf16(oacc[2*df],     al, vh4[0], vh4[1]);
                    mma_bf16(oacc[2*df + 1], al, vh4[2], vh4[3]);
                    mma_bf16(oacc[2*df],     ah, vl4[0], vl4[1]);
                    mma_bf16(oacc[2*df + 1], ah, vl4[2], vl4[3]);
                }
            }
        }
        __syncthreads();
    }

    float* ost = (float*)(sm + A_SKH);
#pragma unroll
    for (int nf = 0; nf < 8; nf++) {
        int c = nf*8 + cq;
        ost[(m0 + r_l) * 72 + c]         = oacc[nf][0];
        ost[(m0 + r_l) * 72 + c + 1]     = oacc[nf][1];
        ost[(m0 + r_l + 8) * 72 + c]     = oacc[nf][2];
        ost[(m0 + r_l + 8) * 72 + c + 1] = oacc[nf][3];
    }
    if ((lane & 3) == 0) {
        ((float*)(sm + A_SMS))[m0 + r_l]     = mi0;
        ((float*)(sm + A_SMS))[m0 + r_l + 8] = mi1;
        ((float*)(sm + A_SLS))[m0 + r_l]     = li0;
        ((float*)(sm + A_SLS))[m0 + r_l + 8] = li1;
    }
    __syncthreads();

    {
        int m = tid >> 1, hf = tid & 1;
        int i = qb*64 + m;
        const __nv_bfloat162* q2h = (const __nv_bfloat162*)(Qh + (size_t)i * Dm + h*64);
        const __nv_bfloat162* q2l = (const __nv_bfloat162*)(Ql + (size_t)i * Dm + h*64);
        const __nv_bfloat162* k2h = (const __nv_bfloat162*)(Kh + (size_t)(S + i) * Dm + h*64);
        const __nv_bfloat162* k2l = (const __nv_bfloat162*)(Kl + (size_t)(S + i) * Dm + h*64);
        float dot = 0.f;
#pragma unroll
        for (int t = 0; t < 32; t++) {
            float2 qa = __bfloat1622float2(q2h[t]);
            float2 qb2 = __bfloat1622float2(q2l[t]);
            float2 ka = __bfloat1622float2(k2h[t]);
            float2 kb = __bfloat1622float2(k2l[t]);
            dot += (qa.x + qb2.x) * (ka.x + kb.x) + (qa.y + qb2.y) * (ka.y + kb.y);
        }
        float ssf = dot;
        float mi = ((float*)(sm + A_SMS))[m];
        float li = ((float*)(sm + A_SLS))[m];
        float nm = fmaxf(mi, ssf);
        float sc = __expf(mi - nm);
        float pp = __expf(ssf - nm);
        float inv = 1.f / (li * sc + pp);
        const __nv_bfloat162* v2h = (const __nv_bfloat162*)(Vh + (size_t)(S + i) * Dm + h*64 + hf*32);
        const __nv_bfloat162* v2l = (const __nv_bfloat162*)(Vl + (size_t)(S + i) * Dm + h*64 + hf*32);
        float* orow = ost + m*72 + hf*32;
        uint32_t hh[8];
#pragma unroll
        for (int t = 0; t < 16; t++) {
            float2 va = __bfloat1622float2(v2h[t]);
            float2 vb = __bfloat1622float2(v2l[t]);
            float val0 = (orow[t*2]   * sc + pp * (va.x + vb.x)) * inv;
            float val1 = (orow[t*2+1] * sc + pp * (va.y + vb.y)) * inv;
            hh[t & 7] = pack_f16(val0, val1);
            if ((t & 7) == 7) {
                int t8 = t >> 3;
                *(uint4*)(O + (size_t)i * Dm + h*64 + hf*32 + t8*16)     = *(uint4*)(hh);
                *(uint4*)(O + (size_t)i * Dm + h*64 + hf*32 + t8*16 + 8) = *(uint4*)(hh + 4);
            }
        }
    }
}

// ------------- launch -------------
extern "C" void kernel_launch(void* const* d_in, const int* in_sizes, int n_in,
                              void* d_out, int out_size)
{
    const float* hidden = (const float*)d_in[0];
    const float* memory = (const float*)d_in[1];
    const float* ln1w = (const float*)d_in[4];
    const float* ln1b = (const float*)d_in[5];
    const float* ln2w = (const float*)d_in[6];
    const float* ln2b = (const float*)d_in[7];
    const float* Wq = (const float*)d_in[8];
    const float* Wk = (const float*)d_in[9];
    const float* Wv = (const float*)d_in[10];
    const float* Wo = (const float*)d_in[11];
    const float* Wg = (const float*)d_in[12];
    const float* Wu = (const float*)d_in[13];
    const float* Wd = (const float*)d_in[14];
    float* out = (float*)d_out;

    void* p;
    cudaGetSymbolAddress(&p, g_x);   __half* x = (__half*)p;
    cudaGetSymbolAddress(&p, g_qh);  bf16* qh = (bf16*)p;
    cudaGetSymbolAddress(&p, g_ql);  bf16* ql = (bf16*)p;
    cudaGetSymbolAddress(&p, g_kh);  bf16* kh = (bf16*)p;
    cudaGetSymbolAddress(&p, g_kl);  bf16* kl = (bf16*)p;
    cudaGetSymbolAddress(&p, g_vh);  bf16* vh = (bf16*)p;
    cudaGetSymbolAddress(&p, g_vl);  bf16* vl = (bf16*)p;
    cudaGetSymbolAddress(&p, g_a);   __half* a = (__half*)p;
    cudaGetSymbolAddress(&p, g_h);   float* hbuf = (float*)p;
    cudaGetSymbolAddress(&p, g_h2);  __half* h2 = (__half*)p;
    cudaGetSymbolAddress(&p, g_gr);  float* gr = (float*)p;
    cudaGetSymbolAddress(&p, g_g);   __half* gbuf = (__half*)p;
    cudaGetSymbolAddress(&p, g_wq);  __half* wq = (__half*)p;
    cudaGetSymbolAddress(&p, g_wk);  __half* wk = (__half*)p;
    cudaGetSymbolAddress(&p, g_wv);  __half* wv = (__half*)p;
    cudaGetSymbolAddress(&p, g_wo);  __half* wo = (__half*)p;
    cudaGetSymbolAddress(&p, g_wg);  __half* wg = (__half*)p;
    cudaGetSymbolAddress(&p, g_wu);  __half* wu = (__half*)p;
    cudaGetSymbolAddress(&p, g_wd);  __half* wd = (__half*)p;

    cudaFuncSetAttribute(gemm1<0>, cudaFuncAttributeMaxDynamicSharedMemorySize, G_DSMEM);
    cudaFuncSetAttribute(gemm1<1>, cudaFuncAttributeMaxDynamicSharedMemorySize, G_DSMEM);
    cudaFuncSetAttribute(gemm1<2>, cudaFuncAttributeMaxDynamicSharedMemorySize, G_DSMEM);
    cudaFuncSetAttribute(gemm1<3>, cudaFuncAttributeMaxDynamicSharedMemorySize, G_DSMEM);
    cudaFuncSetAttribute(attn_mma_kernel, cudaFuncAttributeMaxDynamicSharedMemorySize, A_DSMEM);

    ln_conv_kernel<<<S, 256>>>(memory, ln1w, ln1b, x);
    ln_conv_kernel<<<S, 256>>>(hidden, ln1w, ln1b, x + (size_t)S * Dm);

    int nDD = Dm * Dm / 4, nFD = FF * Dm / 4;
    conv_kernel<<<nDD / 256, 256>>>(Wq, wq, nDD);
    conv_kernel<<<nDD / 256, 256>>>(Wk, wk, nDD);
    conv_kernel<<<nDD / 256, 256>>>(Wv, wv, nDD);
    conv_kernel<<<nDD / 256, 256>>>(Wo, wo, nDD);
    conv_kernel<<<nFD / 256, 256>>>(Wg, wg, nFD);
    conv_kernel<<<nFD / 256, 256>>>(Wu, wu, nFD);
    conv_kernel<<<nFD / 256, 256>>>(Wd, wd, nFD);

    {
        dim3 gKV(Dm / 128, L / 128);
        gemm1<1><<<gKV, 128, G_DSMEM>>>(x, wk, nullptr, nullptr, kh, kl, 1.0f, L, Dm, Dm);
        gemm1<2><<<gKV, 128, G_DSMEM>>>(x, wv, nullptr, nullptr, vh, vl, 1.0f, L, Dm, Dm);
        dim3 gQ(Dm / 128, S / 128);
        gemm1<1><<<gQ, 128, G_DSMEM>>>(x + (size_t)S * Dm, wq, nullptr, nullptr, qh, ql, 0.125f, S, Dm, Dm);
    }

    {
        dim3 g(S / 64, NH);
        attn_mma_kernel<<<g, 128, A_DSMEM>>>(qh, ql, kh, kl, vh, vl, a);
    }

    {
        dim3 g(Dm / 128, S / 128);
        gemm1<0><<<g, 128, G_DSMEM>>>(a, wo, hidden, hbuf, nullptr, nullptr, 1.0f, S, Dm, Dm);
    }
    ln_conv_kernel<<<S, 256>>>(hbuf, ln2w, ln2b, h2);
    {
        dim3 g(FF / 128, S / 128);
        gemm1<0><<<g, 128, G_DSMEM>>>(h2, wg, nullptr, gr, nullptr, nullptr, 1.0f, S, FF, Dm);
        gemm1<3><<<g, 128, G_DSMEM>>>(h2, wu, gr, nullptr, gbuf, nullptr, 1.0f, S, FF, Dm);
    }
    {
        dim3 g(Dm / 128, S / 128);
        gemm1<0><<<g, 128, G_DSMEM>>>(gbuf, wd, hbuf, out, nullptr, nullptr, 1.0f, S, Dm, FF);
    }
}

// round 11
// speedup vs baseline: 4.3037x; 1.1089x over previous
#include <cuda_runtime.h>
#include <cuda_bf16.h>
#include <cuda_fp16.h>
#include <cstdint>

#define S    2048
#define Dm   2048
#define FF   8192
#define NH   32
#define HD   64
#define L    4096

__device__ __forceinline__ uint32_t smem_u32(const void* p) {
    uint32_t a;
    asm("{ .reg .u64 t; cvta.to.shared.u64 t, %1; cvt.u32.u64 %0, t; }" : "=r"(a) : "l"(p));
    return a;
}
__device__ __forceinline__ void ldm_x4(uint32_t* r, uint32_t a) {
    asm volatile("ldmatrix.sync.aligned.m8n8.x4.shared.b16 {%0,%1,%2,%3}, [%4];"
        : "=r"(r[0]), "=r"(r[1]), "=r"(r[2]), "=r"(r[3]) : "r"(a));
}
__device__ __forceinline__ void ldm_x4_t(uint32_t* r, uint32_t a) {
    asm volatile("ldmatrix.sync.aligned.m8n8.x4.trans.shared.b16 {%0,%1,%2,%3}, [%4];"
        : "=r"(r[0]), "=r"(r[1]), "=r"(r[2]), "=r"(r[3]) : "r"(a));
}
__device__ __forceinline__ void mma_f16(float* c, const uint32_t* a, uint32_t b0, uint32_t b1) {
    asm volatile("mma.sync.aligned.m16n8k16.row.col.f32.f16.f16.f32 "
        "{%0,%1,%2,%3}, {%4,%5,%6,%7}, {%8,%9}, {%0,%1,%2,%3};"
        : "+f"(c[0]), "+f"(c[1]), "+f"(c[2]), "+f"(c[3])
        : "r"(a[0]), "r"(a[1]), "r"(a[2]), "r"(a[3]), "r"(b0), "r"(b1));
}
__device__ __forceinline__ uint32_t pack_f16(float a, float b) {
    __half2 t; t.x = __float2half_rn(a); t.y = __float2half_rn(b);
    return *(uint32_t*)&t;
}
__device__ __forceinline__ void split2h(float a, float b, uint32_t& h, uint32_t& l) {
    __half2 hv; hv.x = __float2half_rn(a); hv.y = __float2half_rn(b);
    h = *(uint32_t*)&hv;
    l = pack_f16(a - __half2float(hv.x), b - __half2float(hv.y));
}
#define CP_ASYNC16(dst, src) \
    asm volatile("cp.async.cg.shared.global [%0], [%1], 16;" :: "r"(dst), "l"(src))
#define CP_COMMIT() asm volatile("cp.async.commit_group;" ::: "memory")
#define CP_WAIT1()  asm volatile("cp.async.wait_group 1;" ::: "memory")
#define CP_WAIT2()  asm volatile("cp.async.wait_group 2;" ::: "memory")

// ------------- scratch -------------
__device__ __half g_x  [L * Dm];
__device__ __half g_qh [S * Dm]; __device__ __half g_ql [S * Dm];
__device__ __half g_k  [L * Dm];
__device__ __half g_v  [L * Dm];
__device__ __half g_a  [S * Dm];
__device__ float  g_h  [S * Dm];
__device__ __half g_h2 [S * Dm];
__device__ __half g_gt [S * FF];      // silu(gate) fp16
__device__ __half g_g  [S * FF];      // silu(gate)*up fp16
__device__ __half g_wq[Dm * Dm];
__device__ __half g_wk[Dm * Dm];
__device__ __half g_wv[Dm * Dm];
__device__ __half g_wo[Dm * Dm];
__device__ __half g_wg[FF * Dm];
__device__ __half g_wu[FF * Dm];
__device__ __half g_wd[Dm * FF];

// ------------- fp32 -> fp16 convert -------------
__global__ __launch_bounds__(256) void conv_kernel(
    const float* __restrict__ X, __half* __restrict__ H, int n4)
{
    int i = blockIdx.x * blockDim.x + threadIdx.x;
    if (i >= n4) return;
    float4 x = ((const float4*)X)[i];
    uint2 o; o.x = pack_f16(x.x, x.y); o.y = pack_f16(x.z, x.w);
    ((uint2*)H)[i] = o;
}

// ------------- LayerNorm -> single fp16 -------------
__global__ __launch_bounds__(256) void ln_conv_kernel(
    const float* __restrict__ X, const float* __restrict__ w,
    const float* __restrict__ b, __half* __restrict__ O)
{
    int row = blockIdx.x, tid = threadIdx.x;
    const float* xr = X + (size_t)row * Dm;
    float4 a = ((const float4*)xr)[tid * 2];
    float4 c = ((const float4*)xr)[tid * 2 + 1];
    float s  = a.x + a.y + a.z + a.w + c.x + c.y + c.z + c.w;
    float ss = a.x*a.x + a.y*a.y + a.z*a.z + a.w*a.w
             + c.x*c.x + c.y*c.y + c.z*c.z + c.w*c.w;
#pragma unroll
    for (int o = 16; o; o >>= 1) {
        s  += __shfl_xor_sync(0xffffffffu, s,  o);
        ss += __shfl_xor_sync(0xffffffffu, ss, o);
    }
    __shared__ float bs[8], bss[8];
    if ((tid & 31) == 0) { bs[tid >> 5] = s; bss[tid >> 5] = ss; }
    __syncthreads();
    float ts = 0.f, tss = 0.f;
#pragma unroll
    for (int i = 0; i < 8; i++) { ts += bs[i]; tss += bss[i]; }
    float mean = ts * (1.f / Dm);
    float inv  = rsqrtf(tss * (1.f / Dm) - mean * mean + 1e-5f);
    int d = tid * 8;
    float4 w0 = ((const float4*)w)[tid*2], w1 = ((const float4*)w)[tid*2+1];
    float4 b0 = ((const float4*)b)[tid*2], b1 = ((const float4*)b)[tid*2+1];
    float v8[8];
    v8[0]=(a.x-mean)*inv*w0.x+b0.x; v8[1]=(a.y-mean)*inv*w0.y+b0.y;
    v8[2]=(a.z-mean)*inv*w0.z+b0.z; v8[3]=(a.w-mean)*inv*w0.w+b0.w;
    v8[4]=(c.x-mean)*inv*w1.x+b1.x; v8[5]=(c.y-mean)*inv*w1.y+b1.y;
    v8[6]=(c.z-mean)*inv*w1.z+b1.z; v8[7]=(c.w-mean)*inv*w1.w+b1.w;
    uint4 o;
    o.x = pack_f16(v8[0], v8[1]); o.y = pack_f16(v8[2], v8[3]);
    o.z = pack_f16(v8[4], v8[5]); o.w = pack_f16(v8[6], v8[7]);
    *(uint4*)(O + (size_t)row * Dm + d) = o;
}

// ------------- GEMM: single-term fp16, 4-stage, 4 warps x 64x64 -------------
// MODE 0: fp32 (+Res) | 1: rope -> fp16 | 2: fp16 | 4: rope+scale -> fp16 hi/lo
// MODE 5: silu(acc) -> fp16 | 6: acc * gate16(OLv) -> fp16
#define GBK 16
#define G_ROWB 48
#define G_TILEB (128 * G_ROWB)
#define G_STAGEB (2 * G_TILEB)
#define G_NST 4
#define G_DSMEM (G_NST * G_STAGEB)        // 49152

template<int MODE>
__global__ __launch_bounds__(128, 2)
void gemm1(const __half* __restrict__ A, const __half* __restrict__ B,
           const float* __restrict__ Res, float* __restrict__ C,
           __half* __restrict__ OH, const __half* __restrict__ GIn,
           float scale, int M, int N, int K, __half* __restrict__ OL)
{
    extern __shared__ char smem[];
    uint32_t sb = smem_u32(smem);
    int tid  = threadIdx.x, wid = tid >> 5, lane = tid & 31;
    int wm = wid & 1, wn = wid >> 1;
    int bm = blockIdx.y * 128, bn = blockIdx.x * 128;

    auto loadChunk = [&](int stg, int k0) {
        uint32_t base = sb + stg * G_STAGEB;
#pragma unroll
        for (int h = 0; h < 2; h++) {
            int idx = tid + h * 128;
            int r = idx >> 1, c = idx & 1;
            uint32_t doff = r * G_ROWB + c * 16;
            size_t soff = (size_t)r * K + k0 + c * 8;
            CP_ASYNC16(base + doff,           A + (size_t)bm * K + soff);
            CP_ASYNC16(base + G_TILEB + doff, B + (size_t)bn * K + soff);
        }
    };

    float acc[4][8][4];
#pragma unroll
    for (int i = 0; i < 4; i++)
#pragma unroll
        for (int j = 0; j < 8; j++)
#pragma unroll
            for (int t = 0; t < 4; t++) acc[i][j][t] = 0.f;

    int NKC = K / GBK;
    loadChunk(0, 0);        CP_COMMIT();
    loadChunk(1, GBK);      CP_COMMIT();
    loadChunk(2, 2 * GBK);  CP_COMMIT();

    int a_row = lane & 15;
    int a_kb  = (lane >> 4) * 16;
    int b_row = lane & 7;
    int b_kb  = ((lane >> 3) & 1) * 16;
    int nsel  = (lane >> 4) & 1;

    for (int k = 0; k < NKC; k++) {
        int stg = k & (G_NST - 1);
        CP_WAIT2();
        __syncthreads();
        if (k + 3 < NKC) { loadChunk((k + 3) & (G_NST - 1), (k + 3) * GBK); }
        CP_COMMIT();
        uint32_t base = sb + stg * G_STAGEB;
        uint32_t Af[4][4];
#pragma unroll
        for (int mf = 0; mf < 4; mf++) {
            uint32_t addr = base + (uint32_t)((wm*64 + mf*16 + a_row) * G_ROWB) + a_kb;
            ldm_x4(Af[mf], addr);
        }
#pragma unroll
        for (int g = 0; g < 2; g++) {
            uint32_t Bf[4][2];
#pragma unroll
            for (int p = 0; p < 2; p++) {
                uint32_t addr = base + G_TILEB
                    + (uint32_t)((wn*64 + (g*4 + p*2 + nsel)*8 + b_row) * G_ROWB) + b_kb;
                uint32_t r4[4];
                ldm_x4(r4, addr);
                Bf[p*2][0] = r4[0]; Bf[p*2][1] = r4[1];
                Bf[p*2+1][0] = r4[2]; Bf[p*2+1][1] = r4[3];
            }
#pragma unroll
            for (int mf = 0; mf < 4; mf++)
#pragma unroll
                for (int nf = 0; nf < 4; nf++)
                    mma_f16(acc[mf][g*4 + nf], Af[mf], Bf[nf][0], Bf[nf][1]);
        }
    }

    int rr = lane >> 2, cp = lane & 3;
    if (MODE == 1 || MODE == 4) {
#pragma unroll
        for (int mf = 0; mf < 4; mf++)
#pragma unroll
            for (int j = 0; j < 4; j++) {
                int d = cp * 2 + (j & 1);
                int row = bm + wm*64 + mf*16 + rr + ((j >> 1) * 8);
                int pos = row & (S - 1);
                float invf = __powf(10000.f, -(float)d * 0.125f);
                float sn, cs; sincosf(pos * invf, &sn, &cs);
                float x1 = acc[mf][0][j], x2 = acc[mf][1][j];
                acc[mf][0][j] = x1 * cs - x2 * sn;
                acc[mf][1][j] = x2 * cs + x1 * sn;
            }
    }
#pragma unroll
    for (int mf = 0; mf < 4; mf++) {
        int row0 = bm + wm*64 + mf*16 + rr;
#pragma unroll
        for (int nf = 0; nf < 8; nf++) {
            int col = bn + wn*64 + nf*8 + cp*2;
            float* c = acc[mf][nf];
            size_t o0 = (size_t)row0 * N + col;
            size_t o1 = (size_t)(row0 + 8) * N + col;
            if (MODE == 0) {
                float2 v0 = make_float2(c[0], c[1]);
                float2 v1 = make_float2(c[2], c[3]);
                if (Res) {
                    float2 e0 = *(const float2*)(Res + o0);
                    float2 e1 = *(const float2*)(Res + o1);
                    v0.x += e0.x; v0.y += e0.y; v1.x += e1.x; v1.y += e1.y;
                }
                *(float2*)(C + o0) = v0;
                *(float2*)(C + o1) = v1;
            } else if (MODE == 4) {
                uint32_t h0, l0, h1, l1;
                split2h(c[0] * scale, c[1] * scale, h0, l0);
                split2h(c[2] * scale, c[3] * scale, h1, l1);
                *(uint32_t*)(OH + o0) = h0;
                *(uint32_t*)(OL + o0) = l0;
                *(uint32_t*)(OH + o1) = h1;
                *(uint32_t*)(OL + o1) = l1;
            } else if (MODE == 5) {
                float v0 = c[0] / (1.f + __expf(-c[0]));
                float v1 = c[1] / (1.f + __expf(-c[1]));
                float v2 = c[2] / (1.f + __expf(-c[2]));
                float v3 = c[3] / (1.f + __expf(-c[3]));
                *(uint32_t*)(OH + o0) = pack_f16(v0, v1);
                *(uint32_t*)(OH + o1) = pack_f16(v2, v3);
            } else if (MODE == 6) {
                __half2 g0 = *(const __half2*)(GIn + o0);
                __half2 g1 = *(const __half2*)(GIn + o1);
                *(uint32_t*)(OH + o0) = pack_f16(c[0] * __half2float(g0.x),
                                                 c[1] * __half2float(g0.y));
                *(uint32_t*)(OH + o1) = pack_f16(c[2] * __half2float(g1.x),
                                                 c[3] * __half2float(g1.y));
            } else {
                *(uint32_t*)(OH + o0) = pack_f16(c[0], c[1]);
                *(uint32_t*)(OH + o1) = pack_f16(c[2], c[3]);
            }
        }
    }
}

// ------------- flash attention: fp16 2-term QK and PV -------------
#define A_PITCH 144
#define A_SQH 0u
#define A_SQL 9216u
#define A_SK  18432u     // 2 stages x 9216
#define A_SV  36864u     // 2 stages x 9216
#define A_SMS 55296u
#define A_SLS 55552u
#define A_DSMEM 55808

__global__ __launch_bounds__(128, 2)
void attn_mma_kernel(const __half* __restrict__ Qh, const __half* __restrict__ Ql,
                     const __half* __restrict__ Kf, const __half* __restrict__ Vf,
                     __half* __restrict__ O)
{
    extern __shared__ char sm[];
    uint32_t sb = smem_u32(sm);
    const int qb = blockIdx.x, h = blockIdx.y;
    const int tid = threadIdx.x, wid = tid >> 5, lane = tid & 31;
    const int m0 = wid * 16;

#pragma unroll
    for (int j = 0; j < 4; j++) {
        int idx = tid + j * 128;
        int row = idx >> 3, c = idx & 7;
        size_t g = (size_t)(qb*64 + row) * Dm + h*64 + c*8;
        *(uint4*)(sm + A_SQH + row*A_PITCH + c*16) = *(const uint4*)(Qh + g);
        *(uint4*)(sm + A_SQL + row*A_PITCH + c*16) = *(const uint4*)(Ql + g);
    }
    auto loadKV = [&](int kb, int st) {
        uint32_t o = (uint32_t)st * 9216u;
#pragma unroll
        for (int j = 0; j < 4; j++) {
            int idx = tid + j * 128;
            int row = idx >> 3, c = idx & 7;
            size_t g = (size_t)(kb*64 + row) * Dm + h*64 + c*8;
            uint32_t d = o + row*A_PITCH + c*16;
            CP_ASYNC16(sb + A_SK + d, Kf + g);
            CP_ASYNC16(sb + A_SV + d, Vf + g);
        }
    };
    loadKV(0, 0); CP_COMMIT();
    __syncthreads();

    uint32_t qfh[4][4], qfl[4][4];
    {
        int a_row = lane & 15, koff = (lane >> 4) * 16;
#pragma unroll
        for (int kk = 0; kk < 4; kk++) {
            uint32_t ad = sb + A_SQH + (uint32_t)(m0 + a_row) * A_PITCH + kk*32 + koff;
            ldm_x4(qfh[kk], ad);
            ldm_x4(qfl[kk], ad + 9216u);
        }
    }

    float oacc[8][4];
#pragma unroll
    for (int nf = 0; nf < 8; nf++)
#pragma unroll
        for (int t = 0; t < 4; t++) oacc[nf][t] = 0.f;
    float mi0 = -1e30f, mi1 = -1e30f, li0 = 0.f, li1 = 0.f;
    const int r_l = lane >> 2, cq = (lane & 3) * 2;

    for (int kb = 0; kb <= qb; kb++) {
        if (kb < qb) loadKV(kb + 1, (kb + 1) & 1);
        CP_COMMIT();
        CP_WAIT1();
        __syncthreads();
        uint32_t st = (uint32_t)(kb & 1) * 9216u;

        float sf[8][4];
#pragma unroll
        for (int nf = 0; nf < 8; nf++)
#pragma unroll
            for (int t = 0; t < 4; t++) sf[nf][t] = 0.f;
        {
            int b_row = lane & 7, b_kb = ((lane >> 3) & 1) * 16, nsel = (lane >> 4) & 1;
#pragma unroll
            for (int kk = 0; kk < 4; kk++) {
                uint32_t bh[8][2];
#pragma unroll
                for (int g = 0; g < 2; g++)
#pragma unroll
                    for (int p = 0; p < 2; p++) {
                        uint32_t ad = sb + A_SK + st
                            + (uint32_t)(((g*4 + p*2 + nsel)*8 + b_row)) * A_PITCH
                            + kk*32 + b_kb;
                        uint32_t r4[4];
                        ldm_x4(r4, ad);
                        int f = g*4 + p*2;
                        bh[f][0] = r4[0]; bh[f][1] = r4[1];
                        bh[f+1][0] = r4[2]; bh[f+1][1] = r4[3];
                    }
#pragma unroll
                for (int nf = 0; nf < 8; nf++) mma_f16(sf[nf], qfh[kk], bh[nf][0], bh[nf][1]);
#pragma unroll
                for (int nf = 0; nf < 8; nf++) mma_f16(sf[nf], qfl[kk], bh[nf][0], bh[nf][1]);
            }
        }
        if (kb == qb) {
#pragma unroll
            for (int nf = 0; nf < 8; nf++)
#pragma unroll
                for (int hh = 0; hh < 2; hh++) {
                    int jl = nf*8 + cq + hh;
                    if (jl >= m0 + r_l)     sf[nf][hh]     = -1e30f;
                    if (jl >= m0 + r_l + 8) sf[nf][2 + hh] = -1e30f;
                }
        }
        float mx0 = -1e30f, mx1 = -1e30f;
#pragma unroll
        for (int nf = 0; nf < 8; nf++) {
            mx0 = fmaxf(mx0, fmaxf(sf[nf][0], sf[nf][1]));
            mx1 = fmaxf(mx1, fmaxf(sf[nf][2], sf[nf][3]));
        }
        mx0 = fmaxf(mx0, __shfl_xor_sync(0xffffffffu, mx0, 1));
        mx0 = fmaxf(mx0, __shfl_xor_sync(0xffffffffu, mx0, 2));
        mx1 = fmaxf(mx1, __shfl_xor_sync(0xffffffffu, mx1, 1));
        mx1 = fmaxf(mx1, __shfl_xor_sync(0xffffffffu, mx1, 2));
        float nm0 = fmaxf(mi0, mx0), nm1 = fmaxf(mi1, mx1);
        float sc0 = __expf(mi0 - nm0), sc1 = __expf(mi1 - nm1);
        float sum0 = 0.f, sum1 = 0.f;
#pragma unroll
        for (int nf = 0; nf < 8; nf++) {
            sf[nf][0] = (sf[nf][0] <= -1e29f) ? 0.f : __expf(sf[nf][0] - nm0); sum0 += sf[nf][0];
            sf[nf][1] = (sf[nf][1] <= -1e29f) ? 0.f : __expf(sf[nf][1] - nm0); sum0 += sf[nf][1];
            sf[nf][2] = (sf[nf][2] <= -1e29f) ? 0.f : __expf(sf[nf][2] - nm1); sum1 += sf[nf][2];
            sf[nf][3] = (sf[nf][3] <= -1e29f) ? 0.f : __expf(sf[nf][3] - nm1); sum1 += sf[nf][3];
        }
        sum0 += __shfl_xor_sync(0xffffffffu, sum0, 1);
        sum0 += __shfl_xor_sync(0xffffffffu, sum0, 2);
        sum1 += __shfl_xor_sync(0xffffffffu, sum1, 1);
        sum1 += __shfl_xor_sync(0xffffffffu, sum1, 2);
        li0 = li0 * sc0 + sum0; li1 = li1 * sc1 + sum1;
        mi0 = nm0; mi1 = nm1;
#pragma unroll
        for (int nf = 0; nf < 8; nf++) {
            oacc[nf][0] *= sc0; oacc[nf][1] *= sc0;
            oacc[nf][2] *= sc1; oacc[nf][3] *= sc1;
        }
        {
            int vrow = lane & 15, vcol = (lane >> 4) * 8;
#pragma unroll
            for (int ks = 0; ks < 4; ks++) {
                uint32_t ah[4], al[4];
                split2h(sf[2*ks][0],   sf[2*ks][1],   ah[0], al[0]);
                split2h(sf[2*ks][2],   sf[2*ks][3],   ah[1], al[1]);
                split2h(sf[2*ks+1][0], sf[2*ks+1][1], ah[2], al[2]);
                split2h(sf[2*ks+1][2], sf[2*ks+1][3], ah[3], al[3]);
#pragma unroll
                for (int df = 0; df < 4; df++) {
                    uint32_t v4[4];
                    uint32_t ad = sb + A_SV + st
                        + (uint32_t)(ks*16 + vrow) * A_PITCH + (df*16 + vcol) * 2;
                    ldm_x4_t(v4, ad);
                    mma_f16(oacc[2*df],     ah, v4[0], v4[1]);
                    mma_f16(oacc[2*df + 1], ah, v4[2], v4[3]);
                    mma_f16(oacc[2*df],     al, v4[0], v4[1]);
                    mma_f16(oacc[2*df + 1], al, v4[2], v4[3]);
                }
            }
        }
        __syncthreads();
    }

    float* ost = (float*)(sm + A_SK);
#pragma unroll
    for (int nf = 0; nf < 8; nf++) {
        int c = nf*8 + cq;
        ost[(m0 + r_l) * 72 + c]         = oacc[nf][0];
        ost[(m0 + r_l) * 72 + c + 1]     = oacc[nf][1];
        ost[(m0 + r_l + 8) * 72 + c]     = oacc[nf][2];
        ost[(m0 + r_l + 8) * 72 + c + 1] = oacc[nf][3];
    }
    if ((lane & 3) == 0) {
        ((float*)(sm + A_SMS))[m0 + r_l]     = mi0;
        ((float*)(sm + A_SMS))[m0 + r_l + 8] = mi1;
        ((float*)(sm + A_SLS))[m0 + r_l]     = li0;
        ((float*)(sm + A_SLS))[m0 + r_l + 8] = li1;
    }
    __syncthreads();

    {
        int m = tid >> 1, hf = tid & 1;
        int i = qb*64 + m;
        const __half2* q2h = (const __half2*)(Qh + (size_t)i * Dm + h*64);
        const __half2* q2l = (const __half2*)(Ql + (size_t)i * Dm + h*64);
        const __half2* k2  = (const __half2*)(Kf + (size_t)(S + i) * Dm + h*64);
        float dot = 0.f;
#pragma unroll
        for (int t = 0; t < 32; t++) {
            float2 qa = __half22float2(q2h[t]);
            float2 qb2 = __half22float2(q2l[t]);
            float2 ka = __half22float2(k2[t]);
            dot += (qa.x + qb2.x) * ka.x + (qa.y + qb2.y) * ka.y;
        }
        float ssf = dot;
        float mi = ((float*)(sm + A_SMS))[m];
        float li = ((float*)(sm + A_SLS))[m];
        float nm = fmaxf(mi, ssf);
        float sc = __expf(mi - nm);
        float pp = __expf(ssf - nm);
        float inv = 1.f / (li * sc + pp);
        const __half2* v2 = (const __half2*)(Vf + (size_t)(S + i) * Dm + h*64 + hf*32);
        float* orow = ost + m*72 + hf*32;
        uint32_t hh[8];
#pragma unroll
        for (int t = 0; t < 16; t++) {
            float2 va = __half22float2(v2[t]);
            float val0 = (orow[t*2]   * sc + pp * va.x) * inv;
            float val1 = (orow[t*2+1] * sc + pp * va.y) * inv;
            hh[t & 7] = pack_f16(val0, val1);
            if ((t & 7) == 7) {
                int t8 = t >> 3;
                *(uint4*)(O + (size_t)i * Dm + h*64 + hf*32 + t8*16)     = *(uint4*)(hh);
                *(uint4*)(O + (size_t)i * Dm + h*64 + hf*32 + t8*16 + 8) = *(uint4*)(hh + 4);
            }
        }
    }
}

// ------------- launch -------------
extern "C" void kernel_launch(void* const* d_in, const int* in_sizes, int n_in,
                              void* d_out, int out_size)
{
    const float* hidden = (const float*)d_in[0];
    const float* memory = (const float*)d_in[1];
    const float* ln1w = (const float*)d_in[4];
    const float* ln1b = (const float*)d_in[5];
    const float* ln2w = (const float*)d_in[6];
    const float* ln2b = (const float*)d_in[7];
    const float* Wq = (const float*)d_in[8];
    const float* Wk = (const float*)d_in[9];
    const float* Wv = (const float*)d_in[10];
    const float* Wo = (const float*)d_in[11];
    const float* Wg = (const float*)d_in[12];
    const float* Wu = (const float*)d_in[13];
    const float* Wd = (const float*)d_in[14];
    float* out = (float*)d_out;

    void* p;
    cudaGetSymbolAddress(&p, g_x);   __half* x = (__half*)p;
    cudaGetSymbolAddress(&p, g_qh);  __half* qh = (__half*)p;
    cudaGetSymbolAddress(&p, g_ql);  __half* ql = (__half*)p;
    cudaGetSymbolAddress(&p, g_k);   __half* k = (__half*)p;
    cudaGetSymbolAddress(&p, g_v);   __half* v = (__half*)p;
    cudaGetSymbolAddress(&p, g_a);   __half* a = (__half*)p;
    cudaGetSymbolAddress(&p, g_h);   float* hbuf = (float*)p;
    cudaGetSymbolAddress(&p, g_h2);  __half* h2 = (__half*)p;
    cudaGetSymbolAddress(&p, g_gt);  __half* gt = (__half*)p;
    cudaGetSymbolAddress(&p, g_g);   __half* gbuf = (__half*)p;
    cudaGetSymbolAddress(&p, g_wq);  __half* wq = (__half*)p;
    cudaGetSymbolAddress(&p, g_wk);  __half* wk = (__half*)p;
    cudaGetSymbolAddress(&p, g_wv);  __half* wv = (__half*)p;
    cudaGetSymbolAddress(&p, g_wo);  __half* wo = (__half*)p;
    cudaGetSymbolAddress(&p, g_wg);  __half* wg = (__half*)p;
    cudaGetSymbolAddress(&p, g_wu);  __half* wu = (__half*)p;
    cudaGetSymbolAddress(&p, g_wd);  __half* wd = (__half*)p;

    cudaFuncSetAttribute(gemm1<0>, cudaFuncAttributeMaxDynamicSharedMemorySize, G_DSMEM);
    cudaFuncSetAttribute(gemm1<1>, cudaFuncAttributeMaxDynamicSharedMemorySize, G_DSMEM);
    cudaFuncSetAttribute(gemm1<2>, cudaFuncAttributeMaxDynamicSharedMemorySize, G_DSMEM);
    cudaFuncSetAttribute(gemm1<4>, cudaFuncAttributeMaxDynamicSharedMemorySize, G_DSMEM);
    cudaFuncSetAttribute(gemm1<5>, cudaFuncAttributeMaxDynamicSharedMemorySize, G_DSMEM);
    cudaFuncSetAttribute(gemm1<6>, cudaFuncAttributeMaxDynamicSharedMemorySize, G_DSMEM);
    cudaFuncSetAttribute(attn_mma_kernel, cudaFuncAttributeMaxDynamicSharedMemorySize, A_DSMEM);

    ln_conv_kernel<<<S, 256>>>(memory, ln1w, ln1b, x);
    ln_conv_kernel<<<S, 256>>>(hidden, ln1w, ln1b, x + (size_t)S * Dm);

    int nDD = Dm * Dm / 4, nFD = FF * Dm / 4;
    conv_kernel<<<nDD / 256, 256>>>(Wq, wq, nDD);
    conv_kernel<<<nDD / 256, 256>>>(Wk, wk, nDD);
    conv_kernel<<<nDD / 256, 256>>>(Wv, wv, nDD);
    conv_kernel<<<nDD / 256, 256>>>(Wo, wo, nDD);
    conv_kernel<<<nFD / 256, 256>>>(Wg, wg, nFD);
    conv_kernel<<<nFD / 256, 256>>>(Wu, wu, nFD);
    conv_kernel<<<nFD / 256, 256>>>(Wd, wd, nFD);

    {
        dim3 gKV(Dm / 128, L / 128);
        gemm1<1><<<gKV, 128, G_DSMEM>>>(x, wk, nullptr, nullptr, k, nullptr, 1.0f, L, Dm, Dm, nullptr);
        gemm1<2><<<gKV, 128, G_DSMEM>>>(x, wv, nullptr, nullptr, v, nullptr, 1.0f, L, Dm, Dm, nullptr);
        dim3 gQ(Dm / 128, S / 128);
        gemm1<4><<<gQ, 128, G_DSMEM>>>(x + (size_t)S * Dm, wq, nullptr, nullptr, qh, nullptr, 0.125f, S, Dm, Dm, ql);
    }

    {
        dim3 g(S / 64, NH);
        attn_mma_kernel<<<g, 128, A_DSMEM>>>(qh, ql, k, v, a);
    }

    {
        dim3 g(Dm / 128, S / 128);
        gemm1<0><<<g, 128, G_DSMEM>>>(a, wo, hidden, hbuf, nullptr, nullptr, 1.0f, S, Dm, Dm, nullptr);
    }
    ln_conv_kernel<<<S, 256>>>(hbuf, ln2w, ln2b, h2);
    {
        dim3 g(FF / 128, S / 128);
        gemm1<5><<<g, 128, G_DSMEM>>>(h2, wg, nullptr, nullptr, gt, nullptr, 1.0f, S, FF, Dm, nullptr);
        gemm1<6><<<g, 128, G_DSMEM>>>(h2, wu, nullptr, nullptr, gbuf, gt, 1.0f, S, FF, Dm, nullptr);
    }
    {
        dim3 g(Dm / 128, S / 128);
        gemm1<0><<<g, 128, G_DSMEM>>>(gbuf, wd, hbuf, out, nullptr, nullptr, 1.0f, S, Dm, FF, nullptr);
    }
}

// round 12
// speedup vs baseline: 4.5171x; 1.0496x over previous
#include <cuda_runtime.h>
#include <cuda_fp16.h>
#include <cstdint>

#define S    2048
#define Dm   2048
#define FF   8192
#define NH   32
#define HD   64
#define L    4096

__device__ __forceinline__ uint32_t smem_u32(const void* p) {
    uint32_t a;
    asm("{ .reg .u64 t; cvta.to.shared.u64 t, %1; cvt.u32.u64 %0, t; }" : "=r"(a) : "l"(p));
    return a;
}
__device__ __forceinline__ void ldm_x4(uint32_t* r, uint32_t a) {
    asm volatile("ldmatrix.sync.aligned.m8n8.x4.shared.b16 {%0,%1,%2,%3}, [%4];"
        : "=r"(r[0]), "=r"(r[1]), "=r"(r[2]), "=r"(r[3]) : "r"(a));
}
__device__ __forceinline__ void ldm_x4_t(uint32_t* r, uint32_t a) {
    asm volatile("ldmatrix.sync.aligned.m8n8.x4.trans.shared.b16 {%0,%1,%2,%3}, [%4];"
        : "=r"(r[0]), "=r"(r[1]), "=r"(r[2]), "=r"(r[3]) : "r"(a));
}
__device__ __forceinline__ void mma_f16(float* c, const uint32_t* a, uint32_t b0, uint32_t b1) {
    asm volatile("mma.sync.aligned.m16n8k16.row.col.f32.f16.f16.f32 "
        "{%0,%1,%2,%3}, {%4,%5,%6,%7}, {%8,%9}, {%0,%1,%2,%3};"
        : "+f"(c[0]), "+f"(c[1]), "+f"(c[2]), "+f"(c[3])
        : "r"(a[0]), "r"(a[1]), "r"(a[2]), "r"(a[3]), "r"(b0), "r"(b1));
}
__device__ __forceinline__ uint32_t pack_f16(float a, float b) {
    __half2 t; t.x = __float2half_rn(a); t.y = __float2half_rn(b);
    return *(uint32_t*)&t;
}
__device__ __forceinline__ void split2h(float a, float b, uint32_t& h, uint32_t& l) {
    __half2 hv; hv.x = __float2half_rn(a); hv.y = __float2half_rn(b);
    h = *(uint32_t*)&hv;
    l = pack_f16(a - __half2float(hv.x), b - __half2float(hv.y));
}
#define CP_ASYNC16(dst, src) \
    asm volatile("cp.async.cg.shared.global [%0], [%1], 16;" :: "r"(dst), "l"(src))
#define CP_COMMIT() asm volatile("cp.async.commit_group;" ::: "memory")
#define CP_WAIT1()  asm volatile("cp.async.wait_group 1;" ::: "memory")
#define CP_WAIT2()  asm volatile("cp.async.wait_group 2;" ::: "memory")

// ------------- scratch -------------
__device__ __half g_x  [L * Dm];
__device__ __half g_qh [S * Dm]; __device__ __half g_ql [S * Dm];
__device__ __half g_k  [L * Dm];
__device__ __half g_v  [L * Dm];
__device__ __half g_a  [S * Dm];
__device__ float  g_h  [S * Dm];
__device__ __half g_h2 [S * Dm];
__device__ __half g_gt [S * FF];      // silu(gate)
__device__ __half g_g  [S * FF];      // up raw, then silu(gate)*up
__device__ __half g_wq[Dm * Dm];
__device__ __half g_wk[Dm * Dm];
__device__ __half g_wv[Dm * Dm];
__device__ __half g_wo[Dm * Dm];
__device__ __half g_wg[FF * Dm];
__device__ __half g_wu[FF * Dm];
__device__ __half g_wd[Dm * FF];

// ------------- fp32 -> fp16 convert, MLP=4 -------------
__global__ __launch_bounds__(256) void conv_kernel(
    const float* __restrict__ X, __half* __restrict__ H, int n4)
{
    int base = blockIdx.x * 1024 + threadIdx.x;
    float4 x0 = ((const float4*)X)[base];
    float4 x1 = ((const float4*)X)[base + 256];
    float4 x2 = ((const float4*)X)[base + 512];
    float4 x3 = ((const float4*)X)[base + 768];
    uint2 o0, o1, o2, o3;
    o0.x = pack_f16(x0.x, x0.y); o0.y = pack_f16(x0.z, x0.w);
    o1.x = pack_f16(x1.x, x1.y); o1.y = pack_f16(x1.z, x1.w);
    o2.x = pack_f16(x2.x, x2.y); o2.y = pack_f16(x2.z, x2.w);
    o3.x = pack_f16(x3.x, x3.y); o3.y = pack_f16(x3.z, x3.w);
    ((uint2*)H)[base]       = o0;
    ((uint2*)H)[base + 256] = o1;
    ((uint2*)H)[base + 512] = o2;
    ((uint2*)H)[base + 768] = o3;
}

// ------------- silu(gate) * up elementwise (fp16) -------------
__global__ __launch_bounds__(256) void mul_kernel(
    __half* __restrict__ G, const __half* __restrict__ T, int n8)
{
    int i = blockIdx.x * blockDim.x + threadIdx.x;
    if (i >= n8) return;
    uint4 a = ((const uint4*)G)[i];
    uint4 b = ((const uint4*)T)[i];
    __half2* ah = (__half2*)&a;
    __half2* bh = (__half2*)&b;
#pragma unroll
    for (int t = 0; t < 4; t++) ah[t] = __hmul2(ah[t], bh[t]);
    ((uint4*)G)[i] = a;
}

// ------------- LayerNorm -> single fp16 -------------
__global__ __launch_bounds__(256) void ln_conv_kernel(
    const float* __restrict__ X, const float* __restrict__ w,
    const float* __restrict__ b, __half* __restrict__ O)
{
    int row = blockIdx.x, tid = threadIdx.x;
    const float* xr = X + (size_t)row * Dm;
    float4 a = ((const float4*)xr)[tid * 2];
    float4 c = ((const float4*)xr)[tid * 2 + 1];
    float s  = a.x + a.y + a.z + a.w + c.x + c.y + c.z + c.w;
    float ss = a.x*a.x + a.y*a.y + a.z*a.z + a.w*a.w
             + c.x*c.x + c.y*c.y + c.z*c.z + c.w*c.w;
#pragma unroll
    for (int o = 16; o; o >>= 1) {
        s  += __shfl_xor_sync(0xffffffffu, s,  o);
        ss += __shfl_xor_sync(0xffffffffu, ss, o);
    }
    __shared__ float bs[8], bss[8];
    if ((tid & 31) == 0) { bs[tid >> 5] = s; bss[tid >> 5] = ss; }
    __syncthreads();
    float ts = 0.f, tss = 0.f;
#pragma unroll
    for (int i = 0; i < 8; i++) { ts += bs[i]; tss += bss[i]; }
    float mean = ts * (1.f / Dm);
    float inv  = rsqrtf(tss * (1.f / Dm) - mean * mean + 1e-5f);
    int d = tid * 8;
    float4 w0 = ((const float4*)w)[tid*2], w1 = ((const float4*)w)[tid*2+1];
    float4 b0 = ((const float4*)b)[tid*2], b1 = ((const float4*)b)[tid*2+1];
    float v8[8];
    v8[0]=(a.x-mean)*inv*w0.x+b0.x; v8[1]=(a.y-mean)*inv*w0.y+b0.y;
    v8[2]=(a.z-mean)*inv*w0.z+b0.z; v8[3]=(a.w-mean)*inv*w0.w+b0.w;
    v8[4]=(c.x-mean)*inv*w1.x+b1.x; v8[5]=(c.y-mean)*inv*w1.y+b1.y;
    v8[6]=(c.z-mean)*inv*w1.z+b1.z; v8[7]=(c.w-mean)*inv*w1.w+b1.w;
    uint4 o;
    o.x = pack_f16(v8[0], v8[1]); o.y = pack_f16(v8[2], v8[3]);
    o.z = pack_f16(v8[4], v8[5]); o.w = pack_f16(v8[6], v8[7]);
    *(uint4*)(O + (size_t)row * Dm + d) = o;
}

// ------------- GEMM: single-term fp16, 4-stage, 4 warps x 64x64 -------------
// MODE 0: fp32 (+Res) | 4: rope+scale -> fp16 hi/lo (Q)
// MODE 7: split launch: bx<nsplit -> rope->OH (K) ; else -> plain->O2 (V, weights B2)
// MODE 8: split launch: bx<nsplit -> silu->OH (gate) ; else -> plain->O2 (up, weights B2)
#define GBK 16
#define G_ROWB 48
#define G_TILEB (128 * G_ROWB)
#define G_STAGEB (2 * G_TILEB)
#define G_NST 4
#define G_DSMEM (G_NST * G_STAGEB)        // 49152

template<int MODE>
__global__ __launch_bounds__(128, 2)
void gemm1(const __half* __restrict__ A, const __half* __restrict__ B,
           const __half* __restrict__ B2, const float* __restrict__ Res,
           float* __restrict__ C, __half* __restrict__ OH,
           __half* __restrict__ O2, __half* __restrict__ OL,
           float scale, int M, int N, int K, int nsplit)
{
    extern __shared__ char smem[];
    uint32_t sb = smem_u32(smem);
    int tid  = threadIdx.x, wid = tid >> 5, lane = tid & 31;
    int wm = wid & 1, wn = wid >> 1;
    int bm = blockIdx.y * 128;
    int bx = blockIdx.x;
    const __half* Bp = B;
    bool first = true;
    if ((MODE == 7 || MODE == 8) && bx >= nsplit) { first = false; Bp = B2; bx -= nsplit; }
    int bn = bx * 128;

    auto loadChunk = [&](int stg, int k0) {
        uint32_t base = sb + stg * G_STAGEB;
#pragma unroll
        for (int h = 0; h < 2; h++) {
            int idx = tid + h * 128;
            int r = idx >> 1, c = idx & 1;
            uint32_t doff = r * G_ROWB + c * 16;
            size_t soff = (size_t)r * K + k0 + c * 8;
            CP_ASYNC16(base + doff,           A  + (size_t)bm * K + soff);
            CP_ASYNC16(base + G_TILEB + doff, Bp + (size_t)bn * K + soff);
        }
    };

    float acc[4][8][4];
#pragma unroll
    for (int i = 0; i < 4; i++)
#pragma unroll
        for (int j = 0; j < 8; j++)
#pragma unroll
            for (int t = 0; t < 4; t++) acc[i][j][t] = 0.f;

    int NKC = K / GBK;
    loadChunk(0, 0);        CP_COMMIT();
    loadChunk(1, GBK);      CP_COMMIT();
    loadChunk(2, 2 * GBK);  CP_COMMIT();

    int a_row = lane & 15;
    int a_kb  = (lane >> 4) * 16;
    int b_row = lane & 7;
    int b_kb  = ((lane >> 3) & 1) * 16;
    int nsel  = (lane >> 4) & 1;

    for (int k = 0; k < NKC; k++) {
        int stg = k & (G_NST - 1);
        CP_WAIT2();
        __syncthreads();
        if (k + 3 < NKC) { loadChunk((k + 3) & (G_NST - 1), (k + 3) * GBK); }
        CP_COMMIT();
        uint32_t base = sb + stg * G_STAGEB;
        uint32_t Af[4][4];
#pragma unroll
        for (int mf = 0; mf < 4; mf++) {
            uint32_t addr = base + (uint32_t)((wm*64 + mf*16 + a_row) * G_ROWB) + a_kb;
            ldm_x4(Af[mf], addr);
        }
#pragma unroll
        for (int g = 0; g < 2; g++) {
            uint32_t Bf[4][2];
#pragma unroll
            for (int p = 0; p < 2; p++) {
                uint32_t addr = base + G_TILEB
                    + (uint32_t)((wn*64 + (g*4 + p*2 + nsel)*8 + b_row) * G_ROWB) + b_kb;
                uint32_t r4[4];
                ldm_x4(r4, addr);
                Bf[p*2][0] = r4[0]; Bf[p*2][1] = r4[1];
                Bf[p*2+1][0] = r4[2]; Bf[p*2+1][1] = r4[3];
            }
#pragma unroll
            for (int mf = 0; mf < 4; mf++)
#pragma unroll
                for (int nf = 0; nf < 4; nf++)
                    mma_f16(acc[mf][g*4 + nf], Af[mf], Bf[nf][0], Bf[nf][1]);
        }
    }

    int rr = lane >> 2, cp = lane & 3;
    if (MODE == 4 || (MODE == 7 && first)) {
#pragma unroll
        for (int mf = 0; mf < 4; mf++)
#pragma unroll
            for (int j = 0; j < 4; j++) {
                int d = cp * 2 + (j & 1);
                int row = bm + wm*64 + mf*16 + rr + ((j >> 1) * 8);
                int pos = row & (S - 1);
                float invf = __powf(10000.f, -(float)d * 0.125f);
                float sn, cs; sincosf(pos * invf, &sn, &cs);
                float x1 = acc[mf][0][j], x2 = acc[mf][1][j];
                acc[mf][0][j] = x1 * cs - x2 * sn;
                acc[mf][1][j] = x2 * cs + x1 * sn;
            }
    }
#pragma unroll
    for (int mf = 0; mf < 4; mf++) {
        int row0 = bm + wm*64 + mf*16 + rr;
#pragma unroll
        for (int nf = 0; nf < 8; nf++) {
            int col = bn + wn*64 + nf*8 + cp*2;
            float* c = acc[mf][nf];
            size_t o0 = (size_t)row0 * N + col;
            size_t o1 = (size_t)(row0 + 8) * N + col;
            if (MODE == 0) {
                float2 v0 = make_float2(c[0], c[1]);
                float2 v1 = make_float2(c[2], c[3]);
                if (Res) {
                    float2 e0 = *(const float2*)(Res + o0);
                    float2 e1 = *(const float2*)(Res + o1);
                    v0.x += e0.x; v0.y += e0.y; v1.x += e1.x; v1.y += e1.y;
                }
                *(float2*)(C + o0) = v0;
                *(float2*)(C + o1) = v1;
            } else if (MODE == 4) {
                uint32_t h0, l0, h1, l1;
                split2h(c[0] * scale, c[1] * scale, h0, l0);
                split2h(c[2] * scale, c[3] * scale, h1, l1);
                *(uint32_t*)(OH + o0) = h0;
                *(uint32_t*)(OL + o0) = l0;
                *(uint32_t*)(OH + o1) = h1;
                *(uint32_t*)(OL + o1) = l1;
            } else if (MODE == 7) {
                __half* Op = first ? OH : O2;
                *(uint32_t*)(Op + o0) = pack_f16(c[0], c[1]);
                *(uint32_t*)(Op + o1) = pack_f16(c[2], c[3]);
            } else if (MODE == 8) {
                if (first) {
                    float v0 = c[0] / (1.f + __expf(-c[0]));
                    float v1 = c[1] / (1.f + __expf(-c[1]));
                    float v2 = c[2] / (1.f + __expf(-c[2]));
                    float v3 = c[3] / (1.f + __expf(-c[3]));
                    *(uint32_t*)(OH + o0) = pack_f16(v0, v1);
                    *(uint32_t*)(OH + o1) = pack_f16(v2, v3);
                } else {
                    *(uint32_t*)(O2 + o0) = pack_f16(c[0], c[1]);
                    *(uint32_t*)(O2 + o1) = pack_f16(c[2], c[3]);
                }
            }
        }
    }
}

// ------------- flash attention: fp16 2-term QK and PV, heavy-first order -------------
#define A_PITCH 144
#define A_SQH 0u
#define A_SQL 9216u
#define A_SK  18432u
#define A_SV  36864u
#define A_SMS 55296u
#define A_SLS 55552u
#define A_DSMEM 55808

__global__ __launch_bounds__(128, 2)
void attn_mma_kernel(const __half* __restrict__ Qh, const __half* __restrict__ Ql,
                     const __half* __restrict__ Kf, const __half* __restrict__ Vf,
                     __half* __restrict__ O)
{
    extern __shared__ char sm[];
    uint32_t sb = smem_u32(sm);
    const int qb = gridDim.x - 1 - blockIdx.x;   // heavy CTAs first
    const int h = blockIdx.y;
    const int tid = threadIdx.x, wid = tid >> 5, lane = tid & 31;
    const int m0 = wid * 16;

#pragma unroll
    for (int j = 0; j < 4; j++) {
        int idx = tid + j * 128;
        int row = idx >> 3, c = idx & 7;
        size_t g = (size_t)(qb*64 + row) * Dm + h*64 + c*8;
        *(uint4*)(sm + A_SQH + row*A_PITCH + c*16) = *(const uint4*)(Qh + g);
        *(uint4*)(sm + A_SQL + row*A_PITCH + c*16) = *(const uint4*)(Ql + g);
    }
    auto loadKV = [&](int kb, int st) {
        uint32_t o = (uint32_t)st * 9216u;
#pragma unroll
        for (int j = 0; j < 4; j++) {
            int idx = tid + j * 128;
            int row = idx >> 3, c = idx & 7;
            size_t g = (size_t)(kb*64 + row) * Dm + h*64 + c*8;
            uint32_t d = o + row*A_PITCH + c*16;
            CP_ASYNC16(sb + A_SK + d, Kf + g);
            CP_ASYNC16(sb + A_SV + d, Vf + g);
        }
    };
    loadKV(0, 0); CP_COMMIT();
    __syncthreads();

    uint32_t qfh[4][4], qfl[4][4];
    {
        int a_row = lane & 15, koff = (lane >> 4) * 16;
#pragma unroll
        for (int kk = 0; kk < 4; kk++) {
            uint32_t ad = sb + A_SQH + (uint32_t)(m0 + a_row) * A_PITCH + kk*32 + koff;
            ldm_x4(qfh[kk], ad);
            ldm_x4(qfl[kk], ad + 9216u);
        }
    }

    float oacc[8][4];
#pragma unroll
    for (int nf = 0; nf < 8; nf++)
#pragma unroll
        for (int t = 0; t < 4; t++) oacc[nf][t] = 0.f;
    float mi0 = -1e30f, mi1 = -1e30f, li0 = 0.f, li1 = 0.f;
    const int r_l = lane >> 2, cq = (lane & 3) * 2;

    for (int kb = 0; kb <= qb; kb++) {
        if (kb < qb) loadKV(kb + 1, (kb + 1) & 1);
        CP_COMMIT();
        CP_WAIT1();
        __syncthreads();
        uint32_t st = (uint32_t)(kb & 1) * 9216u;

        float sf[8][4];
#pragma unroll
        for (int nf = 0; nf < 8; nf++)
#pragma unroll
            for (int t = 0; t < 4; t++) sf[nf][t] = 0.f;
        {
            int b_row = lane & 7, b_kb = ((lane >> 3) & 1) * 16, nsel = (lane >> 4) & 1;
#pragma unroll
            for (int kk = 0; kk < 4; kk++) {
                uint32_t bh[8][2];
#pragma unroll
                for (int g = 0; g < 2; g++)
#pragma unroll
                    for (int p = 0; p < 2; p++) {
                        uint32_t ad = sb + A_SK + st
                            + (uint32_t)(((g*4 + p*2 + nsel)*8 + b_row)) * A_PITCH
                            + kk*32 + b_kb;
                        uint32_t r4[4];
                        ldm_x4(r4, ad);
                        int f = g*4 + p*2;
                        bh[f][0] = r4[0]; bh[f][1] = r4[1];
                        bh[f+1][0] = r4[2]; bh[f+1][1] = r4[3];
                    }
#pragma unroll
                for (int nf = 0; nf < 8; nf++) mma_f16(sf[nf], qfh[kk], bh[nf][0], bh[nf][1]);
#pragma unroll
                for (int nf = 0; nf < 8; nf++) mma_f16(sf[nf], qfl[kk], bh[nf][0], bh[nf][1]);
            }
        }
        if (kb == qb) {
#pragma unroll
            for (int nf = 0; nf < 8; nf++)
#pragma unroll
                for (int hh = 0; hh < 2; hh++) {
                    int jl = nf*8 + cq + hh;
                    if (jl >= m0 + r_l)     sf[nf][hh]     = -1e30f;
                    if (jl >= m0 + r_l + 8) sf[nf][2 + hh] = -1e30f;
                }
        }
        float mx0 = -1e30f, mx1 = -1e30f;
#pragma unroll
        for (int nf = 0; nf < 8; nf++) {
            mx0 = fmaxf(mx0, fmaxf(sf[nf][0], sf[nf][1]));
            mx1 = fmaxf(mx1, fmaxf(sf[nf][2], sf[nf][3]));
        }
        mx0 = fmaxf(mx0, __shfl_xor_sync(0xffffffffu, mx0, 1));
        mx0 = fmaxf(mx0, __shfl_xor_sync(0xffffffffu, mx0, 2));
        mx1 = fmaxf(mx1, __shfl_xor_sync(0xffffffffu, mx1, 1));
        mx1 = fmaxf(mx1, __shfl_xor_sync(0xffffffffu, mx1, 2));
        float nm0 = fmaxf(mi0, mx0), nm1 = fmaxf(mi1, mx1);
        float sc0 = __expf(mi0 - nm0), sc1 = __expf(mi1 - nm1);
        float sum0 = 0.f, sum1 = 0.f;
#pragma unroll
        for (int nf = 0; nf < 8; nf++) {
            sf[nf][0] = (sf[nf][0] <= -1e29f) ? 0.f : __expf(sf[nf][0] - nm0); sum0 += sf[nf][0];
            sf[nf][1] = (sf[nf][1] <= -1e29f) ? 0.f : __expf(sf[nf][1] - nm0); sum0 += sf[nf][1];
            sf[nf][2] = (sf[nf][2] <= -1e29f) ? 0.f : __expf(sf[nf][2] - nm1); sum1 += sf[nf][2];
            sf[nf][3] = (sf[nf][3] <= -1e29f) ? 0.f : __expf(sf[nf][3] - nm1); sum1 += sf[nf][3];
        }
        sum0 += __shfl_xor_sync(0xffffffffu, sum0, 1);
        sum0 += __shfl_xor_sync(0xffffffffu, sum0, 2);
        sum1 += __shfl_xor_sync(0xffffffffu, sum1, 1);
        sum1 += __shfl_xor_sync(0xffffffffu, sum1, 2);
        li0 = li0 * sc0 + sum0; li1 = li1 * sc1 + sum1;
        mi0 = nm0; mi1 = nm1;
#pragma unroll
        for (int nf = 0; nf < 8; nf++) {
            oacc[nf][0] *= sc0; oacc[nf][1] *= sc0;
            oacc[nf][2] *= sc1; oacc[nf][3] *= sc1;
        }
        {
            int vrow = lane & 15, vcol = (lane >> 4) * 8;
#pragma unroll
            for (int ks = 0; ks < 4; ks++) {
                uint32_t ah[4], al[4];
                split2h(sf[2*ks][0],   sf[2*ks][1],   ah[0], al[0]);
                split2h(sf[2*ks][2],   sf[2*ks][3],   ah[1], al[1]);
                split2h(sf[2*ks+1][0], sf[2*ks+1][1], ah[2], al[2]);
                split2h(sf[2*ks+1][2], sf[2*ks+1][3], ah[3], al[3]);
#pragma unroll
                for (int df = 0; df < 4; df++) {
                    uint32_t v4[4];
                    uint32_t ad = sb + A_SV + st
                        + (uint32_t)(ks*16 + vrow) * A_PITCH + (df*16 + vcol) * 2;
                    ldm_x4_t(v4, ad);
                    mma_f16(oacc[2*df],     ah, v4[0], v4[1]);
                    mma_f16(oacc[2*df + 1], ah, v4[2], v4[3]);
                    mma_f16(oacc[2*df],     al, v4[0], v4[1]);
                    mma_f16(oacc[2*df + 1], al, v4[2], v4[3]);
                }
            }
        }
        __syncthreads();
    }

    float* ost = (float*)(sm + A_SK);
#pragma unroll
    for (int nf = 0; nf < 8; nf++) {
        int c = nf*8 + cq;
        ost[(m0 + r_l) * 72 + c]         = oacc[nf][0];
        ost[(m0 + r_l) * 72 + c + 1]     = oacc[nf][1];
        ost[(m0 + r_l + 8) * 72 + c]     = oacc[nf][2];
        ost[(m0 + r_l + 8) * 72 + c + 1] = oacc[nf][3];
    }
    if ((lane & 3) == 0) {
        ((float*)(sm + A_SMS))[m0 + r_l]     = mi0;
        ((float*)(sm + A_SMS))[m0 + r_l + 8] = mi1;
        ((float*)(sm + A_SLS))[m0 + r_l]     = li0;
        ((float*)(sm + A_SLS))[m0 + r_l + 8] = li1;
    }
    __syncthreads();

    {
        int m = tid >> 1, hf = tid & 1;
        int i = qb*64 + m;
        const __half2* q2h = (const __half2*)(Qh + (size_t)i * Dm + h*64);
        const __half2* q2l = (const __half2*)(Ql + (size_t)i * Dm + h*64);
        const __half2* k2  = (const __half2*)(Kf + (size_t)(S + i) * Dm + h*64);
        float dot = 0.f;
#pragma unroll
        for (int t = 0; t < 32; t++) {
            float2 qa = __half22float2(q2h[t]);
            float2 qb2 = __half22float2(q2l[t]);
            float2 ka = __half22float2(k2[t]);
            dot += (qa.x + qb2.x) * ka.x + (qa.y + qb2.y) * ka.y;
        }
        float ssf = dot;
        float mi = ((float*)(sm + A_SMS))[m];
        float li = ((float*)(sm + A_SLS))[m];
        float nm = fmaxf(mi, ssf);
        float sc = __expf(mi - nm);
        float pp = __expf(ssf - nm);
        float inv = 1.f / (li * sc + pp);
        const __half2* v2 = (const __half2*)(Vf + (size_t)(S + i) * Dm + h*64 + hf*32);
        float* orow = ost + m*72 + hf*32;
        uint32_t hh[8];
#pragma unroll
        for (int t = 0; t < 16; t++) {
            float2 va = __half22float2(v2[t]);
            float val0 = (orow[t*2]   * sc + pp * va.x) * inv;
            float val1 = (orow[t*2+1] * sc + pp * va.y) * inv;
            hh[t & 7] = pack_f16(val0, val1);
            if ((t & 7) == 7) {
                int t8 = t >> 3;
                *(uint4*)(O + (size_t)i * Dm + h*64 + hf*32 + t8*16)     = *(uint4*)(hh);
                *(uint4*)(O + (size_t)i * Dm + h*64 + hf*32 + t8*16 + 8) = *(uint4*)(hh + 4);
            }
        }
    }
}

// ------------- launch -------------
extern "C" void kernel_launch(void* const* d_in, const int* in_sizes, int n_in,
                              void* d_out, int out_size)
{
    const float* hidden = (const float*)d_in[0];
    const float* memory = (const float*)d_in[1];
    const float* ln1w = (const float*)d_in[4];
    const float* ln1b = (const float*)d_in[5];
    const float* ln2w = (const float*)d_in[6];
    const float* ln2b = (const float*)d_in[7];
    const float* Wq = (const float*)d_in[8];
    const float* Wk = (const float*)d_in[9];
    const float* Wv = (const float*)d_in[10];
    const float* Wo = (const float*)d_in[11];
    const float* Wg = (const float*)d_in[12];
    const float* Wu = (const float*)d_in[13];
    const float* Wd = (const float*)d_in[14];
    float* out = (float*)d_out;

    void* p;
    cudaGetSymbolAddress(&p, g_x);   __half* x = (__half*)p;
    cudaGetSymbolAddress(&p, g_qh);  __half* qh = (__half*)p;
    cudaGetSymbolAddress(&p, g_ql);  __half* ql = (__half*)p;
    cudaGetSymbolAddress(&p, g_k);   __half* k = (__half*)p;
    cudaGetSymbolAddress(&p, g_v);   __half* v = (__half*)p;
    cudaGetSymbolAddress(&p, g_a);   __half* a = (__half*)p;
    cudaGetSymbolAddress(&p, g_h);   float* hbuf = (float*)p;
    cudaGetSymbolAddress(&p, g_h2);  __half* h2 = (__half*)p;
    cudaGetSymbolAddress(&p, g_gt);  __half* gt = (__half*)p;
    cudaGetSymbolAddress(&p, g_g);   __half* gbuf = (__half*)p;
    cudaGetSymbolAddress(&p, g_wq);  __half* wq = (__half*)p;
    cudaGetSymbolAddress(&p, g_wk);  __half* wk = (__half*)p;
    cudaGetSymbolAddress(&p, g_wv);  __half* wv = (__half*)p;
    cudaGetSymbolAddress(&p, g_wo);  __half* wo = (__half*)p;
    cudaGetSymbolAddress(&p, g_wg);  __half* wg = (__half*)p;
    cudaGetSymbolAddress(&p, g_wu);  __half* wu = (__half*)p;
    cudaGetSymbolAddress(&p, g_wd);  __half* wd = (__half*)p;

    cudaFuncSetAttribute(gemm1<0>, cudaFuncAttributeMaxDynamicSharedMemorySize, G_DSMEM);
    cudaFuncSetAttribute(gemm1<4>, cudaFuncAttributeMaxDynamicSharedMemorySize, G_DSMEM);
    cudaFuncSetAttribute(gemm1<7>, cudaFuncAttributeMaxDynamicSharedMemorySize, G_DSMEM);
    cudaFuncSetAttribute(gemm1<8>, cudaFuncAttributeMaxDynamicSharedMemorySize, G_DSMEM);
    cudaFuncSetAttribute(attn_mma_kernel, cudaFuncAttributeMaxDynamicSharedMemorySize, A_DSMEM);

    ln_conv_kernel<<<S, 256>>>(memory, ln1w, ln1b, x);
    ln_conv_kernel<<<S, 256>>>(hidden, ln1w, ln1b, x + (size_t)S * Dm);

    int nDD = Dm * Dm / 4, nFD = FF * Dm / 4;
    conv_kernel<<<nDD / 1024, 256>>>(Wq, wq, nDD);
    conv_kernel<<<nDD / 1024, 256>>>(Wk, wk, nDD);
    conv_kernel<<<nDD / 1024, 256>>>(Wv, wv, nDD);
    conv_kernel<<<nDD / 1024, 256>>>(Wo, wo, nDD);
    conv_kernel<<<nFD / 1024, 256>>>(Wg, wg, nFD);
    conv_kernel<<<nFD / 1024, 256>>>(Wu, wu, nFD);
    conv_kernel<<<nFD / 1024, 256>>>(Wd, wd, nFD);

    {
        // K + V merged (32 x 32 grid), Q separate (with hi/lo + scale)
        dim3 gKV(32, L / 128);
        gemm1<7><<<gKV, 128, G_DSMEM>>>(x, wk, wv, nullptr, nullptr, k, v, nullptr,
                                        1.0f, L, Dm, Dm, 16);
        dim3 gQ(16, S / 128);
        gemm1<4><<<gQ, 128, G_DSMEM>>>(x + (size_t)S * Dm, wq, nullptr, nullptr, nullptr,
                                       qh, nullptr, ql, 0.125f, S, Dm, Dm, 0);
    }

    {
        dim3 g(S / 64, NH);
        attn_mma_kernel<<<g, 128, A_DSMEM>>>(qh, ql, k, v, a);
    }

    {
        dim3 g(Dm / 128, S / 128);
        gemm1<0><<<g, 128, G_DSMEM>>>(a, wo, nullptr, hidden, hbuf, nullptr, nullptr, nullptr,
                                      1.0f, S, Dm, Dm, 0);
    }
    ln_conv_kernel<<<S, 256>>>(hbuf, ln2w, ln2b, h2);
    {
        // gate + up merged (128 x 16 grid)
        dim3 g(128, S / 128);
        gemm1<8><<<g, 128, G_DSMEM>>>(h2, wg, wu, nullptr, nullptr, gt, gbuf, nullptr,
                                      1.0f, S, FF, Dm, 64);
        mul_kernel<<<S * FF / 2048, 256>>>(gbuf, gt, S * FF / 8);
    }
    {
        dim3 g(Dm / 128, S / 128);
        gemm1<0><<<g, 128, G_DSMEM>>>(gbuf, wd, nullptr, hbuf, out, nullptr, nullptr, nullptr,
                                      1.0f, S, Dm, FF, 0);
    }
}

// round 13
// speedup vs baseline: 4.7758x; 1.0573x over previous
#include <cuda_runtime.h>
#include <cuda_fp16.h>
#include <cstdint>

#define S    2048
#define Dm   2048
#define FF   8192
#define NH   32
#define HD   64
#define L    4096

__device__ __forceinline__ uint32_t smem_u32(const void* p) {
    uint32_t a;
    asm("{ .reg .u64 t; cvta.to.shared.u64 t, %1; cvt.u32.u64 %0, t; }" : "=r"(a) : "l"(p));
    return a;
}
__device__ __forceinline__ void ldm_x4(uint32_t* r, uint32_t a) {
    asm volatile("ldmatrix.sync.aligned.m8n8.x4.shared.b16 {%0,%1,%2,%3}, [%4];"
        : "=r"(r[0]), "=r"(r[1]), "=r"(r[2]), "=r"(r[3]) : "r"(a));
}
__device__ __forceinline__ void ldm_x4_t(uint32_t* r, uint32_t a) {
    asm volatile("ldmatrix.sync.aligned.m8n8.x4.trans.shared.b16 {%0,%1,%2,%3}, [%4];"
        : "=r"(r[0]), "=r"(r[1]), "=r"(r[2]), "=r"(r[3]) : "r"(a));
}
__device__ __forceinline__ void mma_f16(float* c, const uint32_t* a, uint32_t b0, uint32_t b1) {
    asm volatile("mma.sync.aligned.m16n8k16.row.col.f32.f16.f16.f32 "
        "{%0,%1,%2,%3}, {%4,%5,%6,%7}, {%8,%9}, {%0,%1,%2,%3};"
        : "+f"(c[0]), "+f"(c[1]), "+f"(c[2]), "+f"(c[3])
        : "r"(a[0]), "r"(a[1]), "r"(a[2]), "r"(a[3]), "r"(b0), "r"(b1));
}
__device__ __forceinline__ uint32_t pack_f16(float a, float b) {
    __half2 t; t.x = __float2half_rn(a); t.y = __float2half_rn(b);
    return *(uint32_t*)&t;
}
#define CP_ASYNC16(dst, src) \
    asm volatile("cp.async.cg.shared.global [%0], [%1], 16;" :: "r"(dst), "l"(src))
#define CP_COMMIT() asm volatile("cp.async.commit_group;" ::: "memory")
#define CP_WAIT1()  asm volatile("cp.async.wait_group 1;" ::: "memory")
#define CP_WAIT2()  asm volatile("cp.async.wait_group 2;" ::: "memory")

// ------------- scratch -------------
__device__ __half g_x  [L * Dm];
__device__ __half g_q  [S * Dm];
__device__ __half g_k  [L * Dm];
__device__ __half g_v  [L * Dm];
__device__ __half g_a  [S * Dm];
__device__ float  g_h  [S * Dm];
__device__ __half g_h2 [S * Dm];
__device__ __half g_gt [S * FF];
__device__ __half g_g  [S * FF];
__device__ __half g_wq[Dm * Dm];
__device__ __half g_wk[Dm * Dm];
__device__ __half g_wv[Dm * Dm];
__device__ __half g_wo[Dm * Dm];
__device__ __half g_wg[FF * Dm];
__device__ __half g_wu[FF * Dm];
__device__ __half g_wd[Dm * FF];

// ------------- merged fp32 -> fp16 convert of all 7 weights -------------
// DD weights: 1024 blocks each; FD weights: 4096 blocks each. 16384 blocks total.
__global__ __launch_bounds__(256) void conv_all_kernel(
    const float* __restrict__ Wq, const float* __restrict__ Wk,
    const float* __restrict__ Wv, const float* __restrict__ Wo,
    const float* __restrict__ Wg, const float* __restrict__ Wu,
    const float* __restrict__ Wd,
    __half* __restrict__ wq, __half* __restrict__ wk, __half* __restrict__ wv,
    __half* __restrict__ wo, __half* __restrict__ wg, __half* __restrict__ wu,
    __half* __restrict__ wd)
{
    int b = blockIdx.x;
    const float* src; __half* dst; int rel;
    if      (b < 1024)  { src = Wq; dst = wq; rel = b; }
    else if (b < 2048)  { src = Wk; dst = wk; rel = b - 1024; }
    else if (b < 3072)  { src = Wv; dst = wv; rel = b - 2048; }
    else if (b < 4096)  { src = Wo; dst = wo; rel = b - 3072; }
    else if (b < 8192)  { src = Wg; dst = wg; rel = b - 4096; }
    else if (b < 12288) { src = Wu; dst = wu; rel = b - 8192; }
    else                { src = Wd; dst = wd; rel = b - 12288; }
    int base = rel * 1024 + threadIdx.x;
#pragma unroll
    for (int t = 0; t < 4; t++) {
        float4 x = ((const float4*)src)[base + t * 256];
        uint2 o; o.x = pack_f16(x.x, x.y); o.y = pack_f16(x.z, x.w);
        ((uint2*)dst)[base + t * 256] = o;
    }
}

// ------------- silu(gate) * up elementwise (fp16) -------------
__global__ __launch_bounds__(256) void mul_kernel(
    __half* __restrict__ G, const __half* __restrict__ T, int n8)
{
    int i = blockIdx.x * blockDim.x + threadIdx.x;
    if (i >= n8) return;
    uint4 a = ((const uint4*)G)[i];
    uint4 b = ((const uint4*)T)[i];
    __half2* ah = (__half2*)&a;
    __half2* bh = (__half2*)&b;
#pragma unroll
    for (int t = 0; t < 4; t++) ah[t] = __hmul2(ah[t], bh[t]);
    ((uint4*)G)[i] = a;
}

// ------------- LayerNorm -> single fp16 -------------
__global__ __launch_bounds__(256) void ln_conv_kernel(
    const float* __restrict__ X, const float* __restrict__ w,
    const float* __restrict__ b, __half* __restrict__ O)
{
    int row = blockIdx.x, tid = threadIdx.x;
    const float* xr = X + (size_t)row * Dm;
    float4 a = ((const float4*)xr)[tid * 2];
    float4 c = ((const float4*)xr)[tid * 2 + 1];
    float s  = a.x + a.y + a.z + a.w + c.x + c.y + c.z + c.w;
    float ss = a.x*a.x + a.y*a.y + a.z*a.z + a.w*a.w
             + c.x*c.x + c.y*c.y + c.z*c.z + c.w*c.w;
#pragma unroll
    for (int o = 16; o; o >>= 1) {
        s  += __shfl_xor_sync(0xffffffffu, s,  o);
        ss += __shfl_xor_sync(0xffffffffu, ss, o);
    }
    __shared__ float bs[8], bss[8];
    if ((tid & 31) == 0) { bs[tid >> 5] = s; bss[tid >> 5] = ss; }
    __syncthreads();
    float ts = 0.f, tss = 0.f;
#pragma unroll
    for (int i = 0; i < 8; i++) { ts += bs[i]; tss += bss[i]; }
    float mean = ts * (1.f / Dm);
    float inv  = rsqrtf(tss * (1.f / Dm) - mean * mean + 1e-5f);
    int d = tid * 8;
    float4 w0 = ((const float4*)w)[tid*2], w1 = ((const float4*)w)[tid*2+1];
    float4 b0 = ((const float4*)b)[tid*2], b1 = ((const float4*)b)[tid*2+1];
    float v8[8];
    v8[0]=(a.x-mean)*inv*w0.x+b0.x; v8[1]=(a.y-mean)*inv*w0.y+b0.y;
    v8[2]=(a.z-mean)*inv*w0.z+b0.z; v8[3]=(a.w-mean)*inv*w0.w+b0.w;
    v8[4]=(c.x-mean)*inv*w1.x+b1.x; v8[5]=(c.y-mean)*inv*w1.y+b1.y;
    v8[6]=(c.z-mean)*inv*w1.z+b1.z; v8[7]=(c.w-mean)*inv*w1.w+b1.w;
    uint4 o;
    o.x = pack_f16(v8[0], v8[1]); o.y = pack_f16(v8[2], v8[3]);
    o.z = pack_f16(v8[4], v8[5]); o.w = pack_f16(v8[6], v8[7]);
    *(uint4*)(O + (size_t)row * Dm + d) = o;
}

// ------------- GEMM: single-term fp16, 4-stage, 4 warps x 64x64 -------------
// MODE 0: fp32 (+Res) | 4: rope+scale -> fp16 (Q)
// MODE 7: bx<nsplit -> rope->OH (K) ; else plain->O2 (V, weights B2)
// MODE 8: bx<nsplit -> silu->OH (gate) ; else plain->O2 (up, weights B2)
#define GBK 16
#define G_ROWB 48
#define G_TILEB (128 * G_ROWB)
#define G_STAGEB (2 * G_TILEB)
#define G_NST 4
#define G_DSMEM (G_NST * G_STAGEB)        // 49152

template<int MODE>
__global__ __launch_bounds__(128, 2)
void gemm1(const __half* __restrict__ A, const __half* __restrict__ B,
           const __half* __restrict__ B2, const float* __restrict__ Res,
           float* __restrict__ C, __half* __restrict__ OH,
           __half* __restrict__ O2, float scale, int M, int N, int K, int nsplit)
{
    extern __shared__ char smem[];
    uint32_t sb = smem_u32(smem);
    int tid  = threadIdx.x, wid = tid >> 5, lane = tid & 31;
    int wm = wid & 1, wn = wid >> 1;
    int bm = blockIdx.y * 128;
    int bx = blockIdx.x;
    const __half* Bp = B;
    bool first = true;
    if ((MODE == 7 || MODE == 8) && bx >= nsplit) { first = false; Bp = B2; bx -= nsplit; }
    int bn = bx * 128;

    auto loadChunk = [&](int stg, int k0) {
        uint32_t base = sb + stg * G_STAGEB;
#pragma unroll
        for (int h = 0; h < 2; h++) {
            int idx = tid + h * 128;
            int r = idx >> 1, c = idx & 1;
            uint32_t doff = r * G_ROWB + c * 16;
            size_t soff = (size_t)r * K + k0 + c * 8;
            CP_ASYNC16(base + doff,           A  + (size_t)bm * K + soff);
            CP_ASYNC16(base + G_TILEB + doff, Bp + (size_t)bn * K + soff);
        }
    };

    float acc[4][8][4];
#pragma unroll
    for (int i = 0; i < 4; i++)
#pragma unroll
        for (int j = 0; j < 8; j++)
#pragma unroll
            for (int t = 0; t < 4; t++) acc[i][j][t] = 0.f;

    int NKC = K / GBK;
    loadChunk(0, 0);        CP_COMMIT();
    loadChunk(1, GBK);      CP_COMMIT();
    loadChunk(2, 2 * GBK);  CP_COMMIT();

    int a_row = lane & 15;
    int a_kb  = (lane >> 4) * 16;
    int b_row = lane & 7;
    int b_kb  = ((lane >> 3) & 1) * 16;
    int nsel  = (lane >> 4) & 1;

    for (int k = 0; k < NKC; k++) {
        int stg = k & (G_NST - 1);
        CP_WAIT2();
        __syncthreads();
        if (k + 3 < NKC) { loadChunk((k + 3) & (G_NST - 1), (k + 3) * GBK); }
        CP_COMMIT();
        uint32_t base = sb + stg * G_STAGEB;
        uint32_t Af[4][4];
#pragma unroll
        for (int mf = 0; mf < 4; mf++) {
            uint32_t addr = base + (uint32_t)((wm*64 + mf*16 + a_row) * G_ROWB) + a_kb;
            ldm_x4(Af[mf], addr);
        }
#pragma unroll
        for (int g = 0; g < 2; g++) {
            uint32_t Bf[4][2];
#pragma unroll
            for (int p = 0; p < 2; p++) {
                uint32_t addr = base + G_TILEB
                    + (uint32_t)((wn*64 + (g*4 + p*2 + nsel)*8 + b_row) * G_ROWB) + b_kb;
                uint32_t r4[4];
                ldm_x4(r4, addr);
                Bf[p*2][0] = r4[0]; Bf[p*2][1] = r4[1];
                Bf[p*2+1][0] = r4[2]; Bf[p*2+1][1] = r4[3];
            }
#pragma unroll
            for (int mf = 0; mf < 4; mf++)
#pragma unroll
                for (int nf = 0; nf < 4; nf++)
                    mma_f16(acc[mf][g*4 + nf], Af[mf], Bf[nf][0], Bf[nf][1]);
        }
    }

    int rr = lane >> 2, cp = lane & 3;
    if (MODE == 4 || (MODE == 7 && first)) {
#pragma unroll
        for (int mf = 0; mf < 4; mf++)
#pragma unroll
            for (int j = 0; j < 4; j++) {
                int d = cp * 2 + (j & 1);
                int row = bm + wm*64 + mf*16 + rr + ((j >> 1) * 8);
                int pos = row & (S - 1);
                float invf = __powf(10000.f, -(float)d * 0.125f);
                float sn, cs; sincosf(pos * invf, &sn, &cs);
                float x1 = acc[mf][0][j], x2 = acc[mf][1][j];
                acc[mf][0][j] = x1 * cs - x2 * sn;
                acc[mf][1][j] = x2 * cs + x1 * sn;
            }
    }
#pragma unroll
    for (int mf = 0; mf < 4; mf++) {
        int row0 = bm + wm*64 + mf*16 + rr;
#pragma unroll
        for (int nf = 0; nf < 8; nf++) {
            int col = bn + wn*64 + nf*8 + cp*2;
            float* c = acc[mf][nf];
            size_t o0 = (size_t)row0 * N + col;
            size_t o1 = (size_t)(row0 + 8) * N + col;
            if (MODE == 0) {
                float2 v0 = make_float2(c[0], c[1]);
                float2 v1 = make_float2(c[2], c[3]);
                if (Res) {
                    float2 e0 = *(const float2*)(Res + o0);
                    float2 e1 = *(const float2*)(Res + o1);
                    v0.x += e0.x; v0.y += e0.y; v1.x += e1.x; v1.y += e1.y;
                }
                *(float2*)(C + o0) = v0;
                *(float2*)(C + o1) = v1;
            } else if (MODE == 4) {
                *(uint32_t*)(OH + o0) = pack_f16(c[0] * scale, c[1] * scale);
                *(uint32_t*)(OH + o1) = pack_f16(c[2] * scale, c[3] * scale);
            } else if (MODE == 7) {
                __half* Op = first ? OH : O2;
                *(uint32_t*)(Op + o0) = pack_f16(c[0], c[1]);
                *(uint32_t*)(Op + o1) = pack_f16(c[2], c[3]);
            } else if (MODE == 8) {
                if (first) {
                    float v0 = c[0] / (1.f + __expf(-c[0]));
                    float v1 = c[1] / (1.f + __expf(-c[1]));
                    float v2 = c[2] / (1.f + __expf(-c[2]));
                    float v3 = c[3] / (1.f + __expf(-c[3]));
                    *(uint32_t*)(OH + o0) = pack_f16(v0, v1);
                    *(uint32_t*)(OH + o1) = pack_f16(v2, v3);
                } else {
                    *(uint32_t*)(O2 + o0) = pack_f16(c[0], c[1]);
                    *(uint32_t*)(O2 + o1) = pack_f16(c[2], c[3]);
                }
            }
        }
    }
}

// ------------- flash attention: fully 1-term fp16, heavy-first -------------
#define A_PITCH 144
#define A_SQ  0u
#define A_SK  9216u      // 2 stages x 9216
#define A_SV  27648u     // 2 stages x 9216
#define A_SMS 46080u
#define A_SLS 46336u
#define A_DSMEM 46592

__global__ __launch_bounds__(128, 2)
void attn_mma_kernel(const __half* __restrict__ Qf, const __half* __restrict__ Kf,
                     const __half* __restrict__ Vf, __half* __restrict__ O)
{
    extern __shared__ char sm[];
    uint32_t sb = smem_u32(sm);
    const int qb = gridDim.x - 1 - blockIdx.x;
    const int h = blockIdx.y;
    const int tid = threadIdx.x, wid = tid >> 5, lane = tid & 31;
    const int m0 = wid * 16;

#pragma unroll
    for (int j = 0; j < 4; j++) {
        int idx = tid + j * 128;
        int row = idx >> 3, c = idx & 7;
        size_t g = (size_t)(qb*64 + row) * Dm + h*64 + c*8;
        *(uint4*)(sm + A_SQ + row*A_PITCH + c*16) = *(const uint4*)(Qf + g);
    }
    auto loadKV = [&](int kb, int st) {
        uint32_t o = (uint32_t)st * 9216u;
#pragma unroll
        for (int j = 0; j < 4; j++) {
            int idx = tid + j * 128;
            int row = idx >> 3, c = idx & 7;
            size_t g = (size_t)(kb*64 + row) * Dm + h*64 + c*8;
            uint32_t d = o + row*A_PITCH + c*16;
            CP_ASYNC16(sb + A_SK + d, Kf + g);
            CP_ASYNC16(sb + A_SV + d, Vf + g);
        }
    };
    loadKV(0, 0); CP_COMMIT();
    __syncthreads();

    uint32_t qf[4][4];
    {
        int a_row = lane & 15, koff = (lane >> 4) * 16;
#pragma unroll
        for (int kk = 0; kk < 4; kk++) {
            uint32_t ad = sb + A_SQ + (uint32_t)(m0 + a_row) * A_PITCH + kk*32 + koff;
            ldm_x4(qf[kk], ad);
        }
    }

    float oacc[8][4];
#pragma unroll
    for (int nf = 0; nf < 8; nf++)
#pragma unroll
        for (int t = 0; t < 4; t++) oacc[nf][t] = 0.f;
    float mi0 = -1e30f, mi1 = -1e30f, li0 = 0.f, li1 = 0.f;
    const int r_l = lane >> 2, cq = (lane & 3) * 2;

    for (int kb = 0; kb <= qb; kb++) {
        if (kb < qb) loadKV(kb + 1, (kb + 1) & 1);
        CP_COMMIT();
        CP_WAIT1();
        __syncthreads();
        uint32_t st = (uint32_t)(kb & 1) * 9216u;

        float sf[8][4];
#pragma unroll
        for (int nf = 0; nf < 8; nf++)
#pragma unroll
            for (int t = 0; t < 4; t++) sf[nf][t] = 0.f;
        {
            int b_row = lane & 7, b_kb = ((lane >> 3) & 1) * 16, nsel = (lane >> 4) & 1;
#pragma unroll
            for (int kk = 0; kk < 4; kk++) {
                uint32_t bh[8][2];
#pragma unroll
                for (int g = 0; g < 2; g++)
#pragma unroll
                    for (int p = 0; p < 2; p++) {
                        uint32_t ad = sb + A_SK + st
                            + (uint32_t)(((g*4 + p*2 + nsel)*8 + b_row)) * A_PITCH
                            + kk*32 + b_kb;
                        uint32_t r4[4];
                        ldm_x4(r4, ad);
                        int f = g*4 + p*2;
                        bh[f][0] = r4[0]; bh[f][1] = r4[1];
                        bh[f+1][0] = r4[2]; bh[f+1][1] = r4[3];
                    }
#pragma unroll
                for (int nf = 0; nf < 8; nf++) mma_f16(sf[nf], qf[kk], bh[nf][0], bh[nf][1]);
            }
        }
        if (kb == qb) {
#pragma unroll
            for (int nf = 0; nf < 8; nf++)
#pragma unroll
                for (int hh = 0; hh < 2; hh++) {
                    int jl = nf*8 + cq + hh;
                    if (jl >= m0 + r_l)     sf[nf][hh]     = -1e30f;
                    if (jl >= m0 + r_l + 8) sf[nf][2 + hh] = -1e30f;
                }
        }
        float mx0 = -1e30f, mx1 = -1e30f;
#pragma unroll
        for (int nf = 0; nf < 8; nf++) {
            mx0 = fmaxf(mx0, fmaxf(sf[nf][0], sf[nf][1]));
            mx1 = fmaxf(mx1, fmaxf(sf[nf][2], sf[nf][3]));
        }
        mx0 = fmaxf(mx0, __shfl_xor_sync(0xffffffffu, mx0, 1));
        mx0 = fmaxf(mx0, __shfl_xor_sync(0xffffffffu, mx0, 2));
        mx1 = fmaxf(mx1, __shfl_xor_sync(0xffffffffu, mx1, 1));
        mx1 = fmaxf(mx1, __shfl_xor_sync(0xffffffffu, mx1, 2));
        float nm0 = fmaxf(mi0, mx0), nm1 = fmaxf(mi1, mx1);
        float sc0 = __expf(mi0 - nm0), sc1 = __expf(mi1 - nm1);
        float sum0 = 0.f, sum1 = 0.f;
#pragma unroll
        for (int nf = 0; nf < 8; nf++) {
            sf[nf][0] = (sf[nf][0] <= -1e29f) ? 0.f : __expf(sf[nf][0] - nm0); sum0 += sf[nf][0];
            sf[nf][1] = (sf[nf][1] <= -1e29f) ? 0.f : __expf(sf[nf][1] - nm0); sum0 += sf[nf][1];
            sf[nf][2] = (sf[nf][2] <= -1e29f) ? 0.f : __expf(sf[nf][2] - nm1); sum1 += sf[nf][2];
            sf[nf][3] = (sf[nf][3] <= -1e29f) ? 0.f : __expf(sf[nf][3] - nm1); sum1 += sf[nf][3];
        }
        sum0 += __shfl_xor_sync(0xffffffffu, sum0, 1);
        sum0 += __shfl_xor_sync(0xffffffffu, sum0, 2);
        sum1 += __shfl_xor_sync(0xffffffffu, sum1, 1);
        sum1 += __shfl_xor_sync(0xffffffffu, sum1, 2);
        li0 = li0 * sc0 + sum0; li1 = li1 * sc1 + sum1;
        mi0 = nm0; mi1 = nm1;
#pragma unroll
        for (int nf = 0; nf < 8; nf++) {
            oacc[nf][0] *= sc0; oacc[nf][1] *= sc0;
            oacc[nf][2] *= sc1; oacc[nf][3] *= sc1;
        }
        {
            int vrow = lane & 15, vcol = (lane >> 4) * 8;
#pragma unroll
            for (int ks = 0; ks < 4; ks++) {
                uint32_t ah[4];
                ah[0] = pack_f16(sf[2*ks][0],   sf[2*ks][1]);
                ah[1] = pack_f16(sf[2*ks][2],   sf[2*ks][3]);
                ah[2] = pack_f16(sf[2*ks+1][0], sf[2*ks+1][1]);
                ah[3] = pack_f16(sf[2*ks+1][2], sf[2*ks+1][3]);
#pragma unroll
                for (int df = 0; df < 4; df++) {
                    uint32_t v4[4];
                    uint32_t ad = sb + A_SV + st
                        + (uint32_t)(ks*16 + vrow) * A_PITCH + (df*16 + vcol) * 2;
                    ldm_x4_t(v4, ad);
                    mma_f16(oacc[2*df],     ah, v4[0], v4[1]);
                    mma_f16(oacc[2*df + 1], ah, v4[2], v4[3]);
                }
            }
        }
        __syncthreads();
    }

    float* ost = (float*)(sm + A_SK);
#pragma unroll
    for (int nf = 0; nf < 8; nf++) {
        int c = nf*8 + cq;
        ost[(m0 + r_l) * 72 + c]         = oacc[nf][0];
        ost[(m0 + r_l) * 72 + c + 1]     = oacc[nf][1];
        ost[(m0 + r_l + 8) * 72 + c]     = oacc[nf][2];
        ost[(m0 + r_l + 8) * 72 + c + 1] = oacc[nf][3];
    }
    if ((lane & 3) == 0) {
        ((float*)(sm + A_SMS))[m0 + r_l]     = mi0;
        ((float*)(sm + A_SMS))[m0 + r_l + 8] = mi1;
        ((float*)(sm + A_SLS))[m0 + r_l]     = li0;
        ((float*)(sm + A_SLS))[m0 + r_l + 8] = li1;
    }
    __syncthreads();

    {
        int m = tid >> 1, hf = tid & 1;
        int i = qb*64 + m;
        const __half2* q2 = (const __half2*)(Qf + (size_t)i * Dm + h*64);
        const __half2* k2 = (const __half2*)(Kf + (size_t)(S + i) * Dm + h*64);
        float dot = 0.f;
#pragma unroll
        for (int t = 0; t < 32; t++) {
            float2 qa = __half22float2(q2[t]);
            float2 ka = __half22float2(k2[t]);
            dot += qa.x * ka.x + qa.y * ka.y;
        }
        float ssf = dot;
        float mi = ((float*)(sm + A_SMS))[m];
        float li = ((float*)(sm + A_SLS))[m];
        float nm = fmaxf(mi, ssf);
        float sc = __expf(mi - nm);
        float pp = __expf(ssf - nm);
        float inv = 1.f / (li * sc + pp);
        const __half2* v2 = (const __half2*)(Vf + (size_t)(S + i) * Dm + h*64 + hf*32);
        float* orow = ost + m*72 + hf*32;
        uint32_t hh[8];
#pragma unroll
        for (int t = 0; t < 16; t++) {
            float2 va = __half22float2(v2[t]);
            float val0 = (orow[t*2]   * sc + pp * va.x) * inv;
            float val1 = (orow[t*2+1] * sc + pp * va.y) * inv;
            hh[t & 7] = pack_f16(val0, val1);
            if ((t & 7) == 7) {
                int t8 = t >> 3;
                *(uint4*)(O + (size_t)i * Dm + h*64 + hf*32 + t8*16)     = *(uint4*)(hh);
                *(uint4*)(O + (size_t)i * Dm + h*64 + hf*32 + t8*16 + 8) = *(uint4*)(hh + 4);
            }
        }
    }
}

// ------------- launch -------------
extern "C" void kernel_launch(void* const* d_in, const int* in_sizes, int n_in,
                              void* d_out, int out_size)
{
    const float* hidden = (const float*)d_in[0];
    const float* memory = (const float*)d_in[1];
    const float* ln1w = (const float*)d_in[4];
    const float* ln1b = (const float*)d_in[5];
    const float* ln2w = (const float*)d_in[6];
    const float* ln2b = (const float*)d_in[7];
    const float* Wq = (const float*)d_in[8];
    const float* Wk = (const float*)d_in[9];
    const float* Wv = (const float*)d_in[10];
    const float* Wo = (const float*)d_in[11];
    const float* Wg = (const float*)d_in[12];
    const float* Wu = (const float*)d_in[13];
    const float* Wd = (const float*)d_in[14];
    float* out = (float*)d_out;

    void* p;
    cudaGetSymbolAddress(&p, g_x);   __half* x = (__half*)p;
    cudaGetSymbolAddress(&p, g_q);   __half* q = (__half*)p;
    cudaGetSymbolAddress(&p, g_k);   __half* k = (__half*)p;
    cudaGetSymbolAddress(&p, g_v);   __half* v = (__half*)p;
    cudaGetSymbolAddress(&p, g_a);   __half* a = (__half*)p;
    cudaGetSymbolAddress(&p, g_h);   float* hbuf = (float*)p;
    cudaGetSymbolAddress(&p, g_h2);  __half* h2 = (__half*)p;
    cudaGetSymbolAddress(&p, g_gt);  __half* gt = (__half*)p;
    cudaGetSymbolAddress(&p, g_g);   __half* gbuf = (__half*)p;
    cudaGetSymbolAddress(&p, g_wq);  __half* wq = (__half*)p;
    cudaGetSymbolAddress(&p, g_wk);  __half* wk = (__half*)p;
    cudaGetSymbolAddress(&p, g_wv);  __half* wv = (__half*)p;
    cudaGetSymbolAddress(&p, g_wo);  __half* wo = (__half*)p;
    cudaGetSymbolAddress(&p, g_wg);  __half* wg = (__half*)p;
    cudaGetSymbolAddress(&p, g_wu);  __half* wu = (__half*)p;
    cudaGetSymbolAddress(&p, g_wd);  __half* wd = (__half*)p;

    cudaFuncSetAttribute(gemm1<0>, cudaFuncAttributeMaxDynamicSharedMemorySize, G_DSMEM);
    cudaFuncSetAttribute(gemm1<4>, cudaFuncAttributeMaxDynamicSharedMemorySize, G_DSMEM);
    cudaFuncSetAttribute(gemm1<7>, cudaFuncAttributeMaxDynamicSharedMemorySize, G_DSMEM);
    cudaFuncSetAttribute(gemm1<8>, cudaFuncAttributeMaxDynamicSharedMemorySize, G_DSMEM);
    cudaFuncSetAttribute(attn_mma_kernel, cudaFuncAttributeMaxDynamicSharedMemorySize, A_DSMEM);

    ln_conv_kernel<<<S, 256>>>(memory, ln1w, ln1b, x);
    ln_conv_kernel<<<S, 256>>>(hidden, ln1w, ln1b, x + (size_t)S * Dm);

    conv_all_kernel<<<16384, 256>>>(Wq, Wk, Wv, Wo, Wg, Wu, Wd,
                                    wq, wk, wv, wo, wg, wu, wd);

    {
        dim3 gKV(32, L / 128);
        gemm1<7><<<gKV, 128, G_DSMEM>>>(x, wk, wv, nullptr, nullptr, k, v,
                                        1.0f, L, Dm, Dm, 16);
        dim3 gQ(16, S / 128);
        gemm1<4><<<gQ, 128, G_DSMEM>>>(x + (size_t)S * Dm, wq, nullptr, nullptr, nullptr,
                                       q, nullptr, 0.125f, S, Dm, Dm, 0);
    }

    {
        dim3 g(S / 64, NH);
        attn_mma_kernel<<<g, 128, A_DSMEM>>>(q, k, v, a);
    }

    {
        dim3 g(Dm / 128, S / 128);
        gemm1<0><<<g, 128, G_DSMEM>>>(a, wo, nullptr, hidden, hbuf, nullptr, nullptr,
                                      1.0f, S, Dm, Dm, 0);
    }
    ln_conv_kernel<<<S, 256>>>(hbuf, ln2w, ln2b, h2);
    {
        dim3 g(128, S / 128);
        gemm1<8><<<g, 128, G_DSMEM>>>(h2, wg, wu, nullptr, nullptr, gt, gbuf,
                                      1.0f, S, FF, Dm, 64);
        mul_kernel<<<S * FF / 2048, 256>>>(gbuf, gt, S * FF / 8);
    }
    {
        dim3 g(Dm / 128, S / 128);
        gemm1<0><<<g, 128, G_DSMEM>>>(gbuf, wd, nullptr, hbuf, out, nullptr, nullptr,
                                      1.0f, S, Dm, FF, 0);
    }
}